// round 1
// baseline (speedup 1.0000x reference)
#include <cuda_runtime.h>
#include <math.h>

#define Bsz 16
#define L   512
#define NH  12
#define HD  64
#define D   768
#define D3  2304
#define NC  20
#define BL  (Bsz*L)      // 8192
#define BH  (Bsz*NH)     // 192
#define LL  (L*L)        // 262144

// ---------------- scratch (allocation-free) ----------------
__device__ float g_x[(size_t)BL*D];        // token emb activations
__device__ float g_hid[(size_t)BL*D3];     // post-linear hiddens
__device__ float g_att[(size_t)BH*LL];     // attention matrix
__device__ float g_qn[(size_t)BH*L*HD];
__device__ float g_kn[(size_t)BH*L*HD];
__device__ float g_v [(size_t)BH*L*HD];
__device__ float g_out[(size_t)BL*D];      // att @ V, re-laid out [B,L,D]
__device__ float g_probs[(size_t)BL*NC];
__device__ float g_col[BL];
__device__ float g_wgt[BL];

__device__ __forceinline__ float lrelu(float x) { return x >= 0.f ? x : 0.01f * x; }

// ---------------- 1. embedding + leaky ----------------
__global__ void embed_leaky_k(const int* __restrict__ ids, const float* __restrict__ emb,
                              float* __restrict__ x) {
    int bl = blockIdx.x;
    long long id = ids[bl];
    const float* src = emb + id * D;
    float* dst = x + (long long)bl * D;
    for (int k = threadIdx.x; k < D; k += blockDim.x)
        dst[k] = lrelu(src[k]);
}

// ---------------- 2. C = leaky(A[M,K] @ W[N,K]^T + bias) ----------------
// BM=BN=64, BK=16, 16x16 threads, 4x4 per thread. M,N multiples of 64; K guarded.
__global__ void gemm_nt_k(const float* __restrict__ A, const float* __restrict__ W,
                          const float* __restrict__ bias, float* __restrict__ Cm,
                          int M, int N, int K) {
    __shared__ float As[16][65];
    __shared__ float Bs[16][65];
    int tx = threadIdx.x, ty = threadIdx.y;
    int t  = ty * 16 + tx;
    int lr = t >> 4, lc = t & 15;
    int bm = blockIdx.y * 64, bn = blockIdx.x * 64;
    float acc[4][4] = {};
    for (int k0 = 0; k0 < K; k0 += 16) {
        int kk = k0 + lc;
        bool ok = kk < K;
#pragma unroll
        for (int p = 0; p < 4; p++) {
            int row = lr + p * 16;
            As[lc][row] = ok ? A[(long long)(bm + row) * K + kk] : 0.f;
            Bs[lc][row] = ok ? W[(long long)(bn + row) * K + kk] : 0.f;
        }
        __syncthreads();
#pragma unroll
        for (int q = 0; q < 16; q++) {
            float a[4], b[4];
#pragma unroll
            for (int i = 0; i < 4; i++) a[i] = As[q][ty * 4 + i];
#pragma unroll
            for (int j = 0; j < 4; j++) b[j] = Bs[q][tx * 4 + j];
#pragma unroll
            for (int i = 0; i < 4; i++)
#pragma unroll
                for (int j = 0; j < 4; j++) acc[i][j] += a[i] * b[j];
        }
        __syncthreads();
    }
#pragma unroll
    for (int i = 0; i < 4; i++)
#pragma unroll
        for (int j = 0; j < 4; j++) {
            int n = bn + tx * 4 + j;
            Cm[(long long)(bm + ty * 4 + i) * N + n] = lrelu(acc[i][j] + bias[n]);
        }
}

// ---------------- 3. split QKV + cosine-normalize Q,K ----------------
__global__ void splitnorm_k(const float* __restrict__ hid, float* __restrict__ qn,
                            float* __restrict__ kn, float* __restrict__ v) {
    int bhl = blockIdx.x;                 // (b,h,l)
    int dd  = threadIdx.x;                // 0..63
    int b   = bhl / (NH * L);
    int rem = bhl % (NH * L);
    int h   = rem / L;
    int l   = rem % L;
    const float* base = hid + (long long)(b * L + l) * D3 + h * HD;
    float q  = base[dd];
    float k  = base[D + dd];
    float vv = base[2 * D + dd];
    __shared__ float sq[64], sk[64];
    sq[dd] = q * q; sk[dd] = k * k;
    __syncthreads();
    for (int o = 32; o; o >>= 1) {
        if (dd < o) { sq[dd] += sq[dd + o]; sk[dd] += sk[dd + o]; }
        __syncthreads();
    }
    float qno = fmaxf(sqrtf(sq[0]), 1e-8f);
    float kno = fmaxf(sqrtf(sk[0]), 1e-8f);
    long long o = ((long long)(b * NH + h) * L + l) * HD + dd;
    qn[o] = q / qno; kn[o] = k / kno; v[o] = vv;
}

// ---------------- 4. att[z,i,j] = Kn[z,i,:] . Qn[z,j,:]  (batched NT, K=64) ----------------
__global__ void attscore_k(const float* __restrict__ Kn, const float* __restrict__ Qn,
                           float* __restrict__ att) {
    int z = blockIdx.z;
    const float* A = Kn + (long long)z * L * HD;
    const float* Bq = Qn + (long long)z * L * HD;
    float* Cp = att + (long long)z * LL;
    int tx = threadIdx.x, ty = threadIdx.y;
    int t = ty * 16 + tx, lr = t >> 4, lc = t & 15;
    int bm = blockIdx.y * 64, bn = blockIdx.x * 64;
    __shared__ float As[16][65];
    __shared__ float Bs[16][65];
    float acc[4][4] = {};
#pragma unroll
    for (int k0 = 0; k0 < HD; k0 += 16) {
#pragma unroll
        for (int p = 0; p < 4; p++) {
            int row = lr + p * 16;
            As[lc][row] = A[(bm + row) * HD + k0 + lc];
            Bs[lc][row] = Bq[(bn + row) * HD + k0 + lc];
        }
        __syncthreads();
#pragma unroll
        for (int q = 0; q < 16; q++) {
            float a[4], b[4];
#pragma unroll
            for (int i = 0; i < 4; i++) a[i] = As[q][ty * 4 + i];
#pragma unroll
            for (int j = 0; j < 4; j++) b[j] = Bs[q][tx * 4 + j];
#pragma unroll
            for (int i = 0; i < 4; i++)
#pragma unroll
                for (int j = 0; j < 4; j++) acc[i][j] += a[i] * b[j];
        }
        __syncthreads();
    }
#pragma unroll
    for (int i = 0; i < 4; i++)
#pragma unroll
        for (int j = 0; j < 4; j++)
            Cp[(long long)(bm + ty * 4 + i) * L + bn + tx * 4 + j] = acc[i][j];
}

// ---------------- 5. LayerNorm across the 12 heads at each (b,i,j) ----------------
__global__ void ln_heads_k(float* __restrict__ att, const float* __restrict__ gamma,
                           const float* __restrict__ beta) {
    int idx = blockIdx.x * blockDim.x + threadIdx.x;   // 0 .. B*L*L
    int b  = idx / LL;
    int ij = idx % LL;
    long long base = (long long)b * NH * LL + ij;
    float v[NH];
    float mu = 0.f;
#pragma unroll
    for (int h = 0; h < NH; h++) { v[h] = att[base + (long long)h * LL]; mu += v[h]; }
    mu *= (1.f / NH);
    float var = 0.f;
#pragma unroll
    for (int h = 0; h < NH; h++) { float d0 = v[h] - mu; var += d0 * d0; }
    var *= (1.f / NH);
    float rstd = rsqrtf(var + 1e-5f);
#pragma unroll
    for (int h = 0; h < NH; h++)
        att[base + (long long)h * LL] = (v[h] - mu) * rstd * gamma[h] + beta[h];
}

// ---------------- 6. softmax over j for each (b,h,i) row ----------------
__global__ void softmax_row_k(float* __restrict__ att) {
    long long row = blockIdx.x;
    float* p = att + row * L;
    int tid = threadIdx.x;                 // 256 threads, 2 elems each
    float v0 = p[tid], v1 = p[tid + 256];
    __shared__ float red[256];
    red[tid] = fmaxf(v0, v1);
    __syncthreads();
    for (int o = 128; o; o >>= 1) { if (tid < o) red[tid] = fmaxf(red[tid], red[tid + o]); __syncthreads(); }
    float mx = red[0];
    __syncthreads();
    float e0 = __expf(v0 - mx), e1 = __expf(v1 - mx);
    red[tid] = e0 + e1;
    __syncthreads();
    for (int o = 128; o; o >>= 1) { if (tid < o) red[tid] += red[tid + o]; __syncthreads(); }
    float inv = 1.f / red[0];
    p[tid] = e0 * inv; p[tid + 256] = e1 * inv;
}

// ---------------- 7. colsum[b,j] = mean_h sum_i att[b,h,i,j] ----------------
__global__ void zero_col_k(float* __restrict__ col) {
    int idx = blockIdx.x * blockDim.x + threadIdx.x;
    if (idx < BL) col[idx] = 0.f;
}
__global__ void colsum_k(const float* __restrict__ att, float* __restrict__ col) {
    int idx = blockIdx.x * blockDim.x + threadIdx.x;   // (b,h,j)
    int b = idx / (NH * L);
    int rem = idx % (NH * L);
    int h = rem / L;
    int j = rem % L;
    const float* base = att + (long long)(b * NH + h) * LL + j;
    float s = 0.f;
#pragma unroll 8
    for (int i = 0; i < L; i++) s += base[(long long)i * L];
    atomicAdd(&col[b * L + j], s * (1.f / NH));
}

// ---------------- 8. out[b,i,h*64+dd] = sum_j att[z,i,j] * V[z,j,dd]  (batched NN) ----------------
__global__ void attv_k(const float* __restrict__ att, const float* __restrict__ V,
                       float* __restrict__ out) {
    int z = blockIdx.z;
    int b = z / NH, h = z % NH;
    const float* A  = att + (long long)z * LL;
    const float* Bv = V + (long long)z * L * HD;
    float* Cp = out + (long long)b * L * D + h * HD;
    int tx = threadIdx.x, ty = threadIdx.y;
    int t = ty * 16 + tx;
    int bm = blockIdx.y * 64;
    __shared__ float As[16][65];
    __shared__ float Bs[16][64];
    float acc[4][4] = {};
    for (int k0 = 0; k0 < L; k0 += 16) {
#pragma unroll
        for (int p = 0; p < 4; p++) {
            int idx = t + p * 256;
            int r = idx >> 4, c = idx & 15;
            As[c][r] = A[(long long)(bm + r) * L + k0 + c];
            int kk = idx >> 6, n = idx & 63;
            Bs[kk][n] = Bv[(k0 + kk) * HD + n];
        }
        __syncthreads();
#pragma unroll
        for (int q = 0; q < 16; q++) {
            float a[4], bb[4];
#pragma unroll
            for (int i = 0; i < 4; i++) a[i] = As[q][ty * 4 + i];
#pragma unroll
            for (int j = 0; j < 4; j++) bb[j] = Bs[q][tx * 4 + j];
#pragma unroll
            for (int i = 0; i < 4; i++)
#pragma unroll
                for (int j = 0; j < 4; j++) acc[i][j] += a[i] * bb[j];
        }
        __syncthreads();
    }
#pragma unroll
    for (int i = 0; i < 4; i++)
#pragma unroll
        for (int j = 0; j < 4; j++)
            Cp[(long long)(bm + ty * 4 + i) * D + tx * 4 + j] = acc[i][j];
}

// ---------------- 9. per-token class probs: softmax(out @ Wout^T + bout) ----------------
__global__ void probs_k(const float* __restrict__ out, const float* __restrict__ Wout,
                        const float* __restrict__ bout, float* __restrict__ probs) {
    int bl = blockIdx.x;
    int warp = threadIdx.x >> 5, lane = threadIdx.x & 31;  // 5 warps
    __shared__ float s[NC];
    __shared__ float mx, sum;
    const float* row = out + (long long)bl * D;
#pragma unroll
    for (int cc = 0; cc < 4; cc++) {
        int c = warp * 4 + cc;
        const float* w = Wout + c * D;
        float acc = 0.f;
        for (int k = lane; k < D; k += 32) acc += row[k] * w[k];
#pragma unroll
        for (int o = 16; o; o >>= 1) acc += __shfl_down_sync(0xffffffffu, acc, o);
        if (lane == 0) s[c] = acc + bout[c];
    }
    __syncthreads();
    if (threadIdx.x == 0) {
        float m = -1e30f;
        for (int c = 0; c < NC; c++) m = fmaxf(m, s[c]);
        float ss = 0.f;
        for (int c = 0; c < NC; c++) ss += __expf(s[c] - m);
        mx = m; sum = ss;
    }
    __syncthreads();
    if (threadIdx.x < NC)
        probs[(long long)bl * NC + threadIdx.x] = __expf(s[threadIdx.x] - mx) / sum;
}

// ---------------- 10. per-batch token weights: softmax_l(mask * colsum) ----------------
__global__ void weights_k(const int* __restrict__ ids, const float* __restrict__ col,
                          float* __restrict__ wgt) {
    int b = blockIdx.x, l = threadIdx.x;   // 512 threads
    float w = (ids[b * L + l] != 0 ? 1.f : 0.f) * col[b * L + l];
    __shared__ float red[512];
    red[l] = w;
    __syncthreads();
    for (int o = 256; o; o >>= 1) { if (l < o) red[l] = fmaxf(red[l], red[l + o]); __syncthreads(); }
    float mxv = red[0];
    __syncthreads();
    float e = __expf(w - mxv);
    red[l] = e;
    __syncthreads();
    for (int o = 256; o; o >>= 1) { if (l < o) red[l] += red[l + o]; __syncthreads(); }
    wgt[b * L + l] = e / red[0];
}

// ---------------- 11. final: dout[b,c] (+)= 0.5 * sum_l wgt[b,l]*probs[b,l,c] ----------------
__global__ void final_k(const float* __restrict__ wgt, const float* __restrict__ probs,
                        float* __restrict__ dout, int first) {
    int b = blockIdx.x;
    __shared__ float red[256];
    int tid = threadIdx.x;
    for (int c = 0; c < NC; c++) {
        float s = 0.f;
        for (int l = tid; l < L; l += 256)
            s += wgt[b * L + l] * probs[(long long)(b * L + l) * NC + c];
        red[tid] = s;
        __syncthreads();
        for (int o = 128; o; o >>= 1) { if (tid < o) red[tid] += red[tid + o]; __syncthreads(); }
        if (tid == 0) {
            float v = 0.5f * red[0];
            dout[b * NC + c] = first ? v : dout[b * NC + c] + v;
        }
        __syncthreads();
    }
}

// ---------------- launch ----------------
extern "C" void kernel_launch(void* const* d_in, const int* in_sizes, int n_in,
                              void* d_out, int out_size) {
    (void)in_sizes; (void)n_in; (void)out_size;
    const int*   ids   = (const int*)d_in[0];
    const float* wv    = (const float*)d_in[1];
    const float* emb   = (const float*)d_in[2];
    const float* W_t   = (const float*)d_in[3];
    const float* b_t   = (const float*)d_in[4];
    const float* gam_t = (const float*)d_in[5];
    const float* bet_t = (const float*)d_in[6];
    const float* Wo_t  = (const float*)d_in[7];
    const float* bo_t  = (const float*)d_in[8];
    const float* W_h   = (const float*)d_in[9];
    const float* b_h   = (const float*)d_in[10];
    const float* gam_h = (const float*)d_in[11];
    const float* bet_h = (const float*)d_in[12];
    const float* Wo_h  = (const float*)d_in[13];
    const float* bo_h  = (const float*)d_in[14];
    float* out = (float*)d_out;

    float *px, *phid, *patt, *pqn, *pkn, *pv, *pout, *pprobs, *pcol, *pwgt;
    cudaGetSymbolAddress((void**)&px, g_x);
    cudaGetSymbolAddress((void**)&phid, g_hid);
    cudaGetSymbolAddress((void**)&patt, g_att);
    cudaGetSymbolAddress((void**)&pqn, g_qn);
    cudaGetSymbolAddress((void**)&pkn, g_kn);
    cudaGetSymbolAddress((void**)&pv, g_v);
    cudaGetSymbolAddress((void**)&pout, g_out);
    cudaGetSymbolAddress((void**)&pprobs, g_probs);
    cudaGetSymbolAddress((void**)&pcol, g_col);
    cudaGetSymbolAddress((void**)&pwgt, g_wgt);

    dim3 tb(16, 16);
    dim3 gemm_grid(D3 / 64, BL / 64);

    // ===== token branch =====
    embed_leaky_k<<<BL, 256>>>(ids, emb, px);
    gemm_nt_k<<<gemm_grid, tb>>>(px, W_t, b_t, phid, BL, D3, D);
    splitnorm_k<<<Bsz * NH * L, 64>>>(phid, pqn, pkn, pv);
    attscore_k<<<dim3(8, 8, BH), tb>>>(pkn, pqn, patt);
    ln_heads_k<<<(Bsz * LL) / 256, 256>>>(patt, gam_t, bet_t);
    softmax_row_k<<<BH * L, 256>>>(patt);
    zero_col_k<<<BL / 256, 256>>>(pcol);
    colsum_k<<<(BH * L) / 256, 256>>>(patt, pcol);
    attv_k<<<dim3(1, 8, BH), tb>>>(patt, pv, pout);
    probs_k<<<BL, 160>>>(pout, Wo_t, bo_t, pprobs);
    weights_k<<<Bsz, 512>>>(ids, pcol, pwgt);
    final_k<<<Bsz, 256>>>(pwgt, pprobs, out, 1);

    // ===== hidden / word-vector branch =====
    gemm_nt_k<<<gemm_grid, tb>>>(wv, W_h, b_h, phid, BL, D3, 300);
    splitnorm_k<<<Bsz * NH * L, 64>>>(phid, pqn, pkn, pv);
    attscore_k<<<dim3(8, 8, BH), tb>>>(pkn, pqn, patt);
    ln_heads_k<<<(Bsz * LL) / 256, 256>>>(patt, gam_h, bet_h);
    softmax_row_k<<<BH * L, 256>>>(patt);
    zero_col_k<<<BL / 256, 256>>>(pcol);
    colsum_k<<<(BH * L) / 256, 256>>>(patt, pcol);
    attv_k<<<dim3(1, 8, BH), tb>>>(patt, pv, pout);
    probs_k<<<BL, 160>>>(pout, Wo_h, bo_h, pprobs);
    weights_k<<<Bsz, 512>>>(ids, pcol, pwgt);
    final_k<<<Bsz, 256>>>(pwgt, pprobs, out, 0);
}

// round 2
// speedup vs baseline: 1.4903x; 1.4903x over previous
#include <cuda_runtime.h>
#include <math.h>

#define Bsz 16
#define L   512
#define NH  12
#define HD  64
#define D   768
#define D3  2304
#define NC  20
#define BL  (Bsz*L)      // 8192
#define BH  (Bsz*NH)     // 192
#define LL  (L*L)        // 262144

// ---------------- scratch (allocation-free) ----------------
__device__ float g_x[(size_t)BL*D];
__device__ float g_hid[(size_t)BL*D3];
__device__ float g_att[(size_t)BH*LL];
__device__ float g_qn[(size_t)BH*L*HD];
__device__ float g_kn[(size_t)BH*L*HD];
__device__ float g_v [(size_t)BH*L*HD];
__device__ float g_out[(size_t)BL*D];
__device__ float g_probs[(size_t)BL*NC];
__device__ float g_col[BL];
__device__ float g_wgt[BL];

__device__ __forceinline__ float lrelu(float x) { return x >= 0.f ? x : 0.01f * x; }

// ---------------- 1. embedding + leaky ----------------
__global__ void embed_leaky_k(const int* __restrict__ ids, const float* __restrict__ emb,
                              float* __restrict__ x) {
    int bl = blockIdx.x;
    long long id = ids[bl];
    const float* src = emb + id * D;
    float* dst = x + (long long)bl * D;
    for (int k = threadIdx.x; k < D; k += blockDim.x)
        dst[k] = lrelu(src[k]);
}

// ---------------- 2. 128x128x16 double-buffered NT GEMM ----------------
// C[m,n] = op( sum_k A[m,k]*B[n,k] + bias[n] )    MODE 1: lrelu+bias, 0: plain
// M,N multiples of 128; K arbitrary multiple of 4. Batched via blockIdx.z strides.
template<int MODE>
__global__ void __launch_bounds__(256, 2)
gemm128(const float* __restrict__ A, long long sA,
        const float* __restrict__ B, long long sB,
        const float* __restrict__ bias,
        float* __restrict__ C, int ldc, long long sC, int K) {
    __shared__ float As[2][16][128];
    __shared__ float Bs[2][16][128];
    const int tid = threadIdx.x;
    const int lr  = tid >> 2;       // 0..63
    const int lc4 = tid & 3;        // float4 col index within k-tile
    const int tx  = tid & 15, ty = tid >> 4;
    const float* Ab = A + (long long)blockIdx.z * sA + (long long)blockIdx.y * 128 * K;
    const float* Bb = B + (long long)blockIdx.z * sB + (long long)blockIdx.x * 128 * K;
    const int ktiles = (K + 15) >> 4;
    float4 ra[2], rb[2];
    float acc[8][8] = {};

#define LDG_TILE(k0)                                                          \
    {                                                                         \
        int col = (k0) + lc4 * 4;                                             \
        bool ok = (col + 4) <= K;                                             \
        _Pragma("unroll")                                                     \
        for (int p = 0; p < 2; p++) {                                         \
            int row = lr + p * 64;                                            \
            if (ok) {                                                         \
                ra[p] = *(const float4*)(Ab + (long long)row * K + col);      \
                rb[p] = *(const float4*)(Bb + (long long)row * K + col);      \
            } else {                                                          \
                ra[p] = make_float4(0.f,0.f,0.f,0.f);                         \
                rb[p] = make_float4(0.f,0.f,0.f,0.f);                         \
            }                                                                 \
        }                                                                     \
    }
#define STS_TILE(bf)                                                          \
    {                                                                         \
        _Pragma("unroll")                                                     \
        for (int p = 0; p < 2; p++) {                                         \
            int row = lr + p * 64;                                            \
            As[bf][lc4*4+0][row] = ra[p].x; As[bf][lc4*4+1][row] = ra[p].y;   \
            As[bf][lc4*4+2][row] = ra[p].z; As[bf][lc4*4+3][row] = ra[p].w;   \
            Bs[bf][lc4*4+0][row] = rb[p].x; Bs[bf][lc4*4+1][row] = rb[p].y;   \
            Bs[bf][lc4*4+2][row] = rb[p].z; Bs[bf][lc4*4+3][row] = rb[p].w;   \
        }                                                                     \
    }

    LDG_TILE(0);
    STS_TILE(0);
    __syncthreads();
    int buf = 0;
    for (int t = 0; t < ktiles; t++) {
        if (t + 1 < ktiles) LDG_TILE((t + 1) << 4);
#pragma unroll
        for (int kk = 0; kk < 16; kk++) {
            float4 a0 = *(const float4*)&As[buf][kk][ty * 8];
            float4 a1 = *(const float4*)&As[buf][kk][ty * 8 + 4];
            float4 b0 = *(const float4*)&Bs[buf][kk][tx * 8];
            float4 b1 = *(const float4*)&Bs[buf][kk][tx * 8 + 4];
            float av[8] = {a0.x,a0.y,a0.z,a0.w,a1.x,a1.y,a1.z,a1.w};
            float bv[8] = {b0.x,b0.y,b0.z,b0.w,b1.x,b1.y,b1.z,b1.w};
#pragma unroll
            for (int i = 0; i < 8; i++)
#pragma unroll
                for (int j = 0; j < 8; j++) acc[i][j] += av[i] * bv[j];
        }
        if (t + 1 < ktiles) { STS_TILE(buf ^ 1); __syncthreads(); buf ^= 1; }
    }
#undef LDG_TILE
#undef STS_TILE

    float bj[8];
    if (MODE == 1) {
#pragma unroll
        for (int j = 0; j < 8; j++) bj[j] = bias[blockIdx.x * 128 + tx * 8 + j];
    }
    float* Cb = C + (long long)blockIdx.z * sC
                  + ((long long)blockIdx.y * 128 + ty * 8) * ldc
                  + blockIdx.x * 128 + tx * 8;
#pragma unroll
    for (int i = 0; i < 8; i++) {
        float v[8];
#pragma unroll
        for (int j = 0; j < 8; j++)
            v[j] = (MODE == 1) ? lrelu(acc[i][j] + bj[j]) : acc[i][j];
        *(float4*)(Cb + (long long)i * ldc)     = make_float4(v[0],v[1],v[2],v[3]);
        *(float4*)(Cb + (long long)i * ldc + 4) = make_float4(v[4],v[5],v[6],v[7]);
    }
}

// ---------------- 3. split QKV + cosine-normalize Q,K ----------------
__global__ void splitnorm_k(const float* __restrict__ hid, float* __restrict__ qn,
                            float* __restrict__ kn, float* __restrict__ v) {
    int bhl = blockIdx.x;
    int dd  = threadIdx.x;
    int b   = bhl / (NH * L);
    int rem = bhl % (NH * L);
    int h   = rem / L;
    int l   = rem % L;
    const float* base = hid + (long long)(b * L + l) * D3 + h * HD;
    float q  = base[dd];
    float k  = base[D + dd];
    float vv = base[2 * D + dd];
    __shared__ float sq[64], sk[64];
    sq[dd] = q * q; sk[dd] = k * k;
    __syncthreads();
    for (int o = 32; o; o >>= 1) {
        if (dd < o) { sq[dd] += sq[dd + o]; sk[dd] += sk[dd + o]; }
        __syncthreads();
    }
    float qno = fmaxf(sqrtf(sq[0]), 1e-8f);
    float kno = fmaxf(sqrtf(sk[0]), 1e-8f);
    long long o = ((long long)(b * NH + h) * L + l) * HD + dd;
    qn[o] = q / qno; kn[o] = k / kno; v[o] = vv;
}

// ---------------- 4. fused LayerNorm(heads) + softmax(j) + colsum ----------------
// one block per (b,i); att[b,h,i,j] = base + h*LL + j
__global__ void __launch_bounds__(256)
lnsm_k(float* __restrict__ att, const float* __restrict__ gamma,
       const float* __restrict__ beta, float* __restrict__ col) {
    __shared__ float s[NH][L];      // 24 KB
    __shared__ float rinv[NH];
    int b = blockIdx.x / L, i = blockIdx.x % L;
    float* base = att + (long long)b * NH * LL + (long long)i * L;
    int tid = threadIdx.x;
    float g[NH], be[NH];
#pragma unroll
    for (int h = 0; h < NH; h++) { g[h] = gamma[h]; be[h] = beta[h]; }

#pragma unroll
    for (int rep = 0; rep < 2; rep++) {
        int j = tid + rep * 256;
        float v[NH]; float mu = 0.f;
#pragma unroll
        for (int h = 0; h < NH; h++) { v[h] = base[(long long)h * LL + j]; mu += v[h]; }
        mu *= (1.f / NH);
        float var = 0.f;
#pragma unroll
        for (int h = 0; h < NH; h++) { float d0 = v[h] - mu; var += d0 * d0; }
        float rstd = rsqrtf(var * (1.f / NH) + 1e-5f);
#pragma unroll
        for (int h = 0; h < NH; h++)
            s[h][j] = (v[h] - mu) * rstd * g[h] + be[h];
    }
    __syncthreads();

    int w = tid >> 5, lane = tid & 31;
    for (int h = w; h < NH; h += 8) {
        float m = -1e30f;
#pragma unroll
        for (int q = 0; q < 16; q++) m = fmaxf(m, s[h][q * 32 + lane]);
#pragma unroll
        for (int o = 16; o; o >>= 1) m = fmaxf(m, __shfl_xor_sync(0xffffffffu, m, o));
        float sum = 0.f;
#pragma unroll
        for (int q = 0; q < 16; q++) {
            float e = __expf(s[h][q * 32 + lane] - m);
            s[h][q * 32 + lane] = e;
            sum += e;
        }
#pragma unroll
        for (int o = 16; o; o >>= 1) sum += __shfl_xor_sync(0xffffffffu, sum, o);
        if (lane == 0) rinv[h] = 1.f / sum;
    }
    __syncthreads();

    float inv[NH];
#pragma unroll
    for (int h = 0; h < NH; h++) inv[h] = rinv[h];
#pragma unroll
    for (int rep = 0; rep < 2; rep++) {
        int j = tid + rep * 256;
        float cs = 0.f;
#pragma unroll
        for (int h = 0; h < NH; h++) {
            float e = s[h][j] * inv[h];
            base[(long long)h * LL + j] = e;
            cs += e;
        }
        atomicAdd(&col[b * L + j], cs * (1.f / NH));
    }
}

// ---------------- 5. colsum zero ----------------
__global__ void zero_col_k(float* __restrict__ col) {
    int idx = blockIdx.x * blockDim.x + threadIdx.x;
    if (idx < BL) col[idx] = 0.f;
}

// ---------------- 6. out = att @ V  (128x64x32 double-buffered NN) ----------------
__global__ void __launch_bounds__(256, 2)
attv128(const float* __restrict__ att, const float* __restrict__ V,
        float* __restrict__ out) {
    __shared__ float As[2][32][128];
    __shared__ float Bs[2][32][64];
    int z = blockIdx.z;
    int b = z / NH, h = z % NH;
    const float* Ab = att + (long long)z * LL + (long long)blockIdx.y * 128 * L;
    const float* Bb = V + (long long)z * L * HD;
    int tid = threadIdx.x;
    int tx = tid & 15, ty = tid >> 4;
    int arow = tid >> 3, ac4 = tid & 7;
    int brow = tid >> 4, bc4 = tid & 15;
    float4 ra[4], rb[2];
    float acc[8][4] = {};

#define ALDG(k0)                                                              \
    {                                                                         \
        _Pragma("unroll")                                                     \
        for (int p = 0; p < 4; p++)                                           \
            ra[p] = *(const float4*)(Ab + (long long)(arow + p*32) * L + (k0) + ac4*4); \
        _Pragma("unroll")                                                     \
        for (int p = 0; p < 2; p++)                                           \
            rb[p] = *(const float4*)(Bb + (long long)((k0) + brow + p*16) * HD + bc4*4); \
    }
#define ASTS(bf)                                                              \
    {                                                                         \
        _Pragma("unroll")                                                     \
        for (int p = 0; p < 4; p++) {                                         \
            int row = arow + p * 32;                                          \
            As[bf][ac4*4+0][row] = ra[p].x; As[bf][ac4*4+1][row] = ra[p].y;   \
            As[bf][ac4*4+2][row] = ra[p].z; As[bf][ac4*4+3][row] = ra[p].w;   \
        }                                                                     \
        _Pragma("unroll")                                                     \
        for (int p = 0; p < 2; p++)                                           \
            *(float4*)&Bs[bf][brow + p*16][bc4*4] = rb[p];                    \
    }

    ALDG(0);
    ASTS(0);
    __syncthreads();
    int buf = 0;
    const int ktiles = L / 32;
    for (int t = 0; t < ktiles; t++) {
        if (t + 1 < ktiles) ALDG((t + 1) * 32);
#pragma unroll
        for (int kk = 0; kk < 32; kk++) {
            float4 a0 = *(const float4*)&As[buf][kk][ty * 8];
            float4 a1 = *(const float4*)&As[buf][kk][ty * 8 + 4];
            float4 b0 = *(const float4*)&Bs[buf][kk][tx * 4];
            float av[8] = {a0.x,a0.y,a0.z,a0.w,a1.x,a1.y,a1.z,a1.w};
            float bv[4] = {b0.x,b0.y,b0.z,b0.w};
#pragma unroll
            for (int i = 0; i < 8; i++)
#pragma unroll
                for (int j = 0; j < 4; j++) acc[i][j] += av[i] * bv[j];
        }
        if (t + 1 < ktiles) { ASTS(buf ^ 1); __syncthreads(); buf ^= 1; }
    }
#undef ALDG
#undef ASTS

    float* Cb = out + ((long long)b * L + blockIdx.y * 128 + ty * 8) * D + h * HD + tx * 4;
#pragma unroll
    for (int i = 0; i < 8; i++)
        *(float4*)(Cb + (long long)i * D) = make_float4(acc[i][0], acc[i][1], acc[i][2], acc[i][3]);
}

// ---------------- 7. per-token class probs ----------------
__global__ void probs_k(const float* __restrict__ out, const float* __restrict__ Wout,
                        const float* __restrict__ bout, float* __restrict__ probs) {
    int bl = blockIdx.x;
    int warp = threadIdx.x >> 5, lane = threadIdx.x & 31;
    __shared__ float s[NC];
    __shared__ float mx, sum;
    const float* row = out + (long long)bl * D;
#pragma unroll
    for (int cc = 0; cc < 4; cc++) {
        int c = warp * 4 + cc;
        const float* w = Wout + c * D;
        float acc = 0.f;
        for (int k = lane; k < D; k += 32) acc += row[k] * w[k];
#pragma unroll
        for (int o = 16; o; o >>= 1) acc += __shfl_down_sync(0xffffffffu, acc, o);
        if (lane == 0) s[c] = acc + bout[c];
    }
    __syncthreads();
    if (threadIdx.x == 0) {
        float m = -1e30f;
        for (int c = 0; c < NC; c++) m = fmaxf(m, s[c]);
        float ss = 0.f;
        for (int c = 0; c < NC; c++) ss += __expf(s[c] - m);
        mx = m; sum = ss;
    }
    __syncthreads();
    if (threadIdx.x < NC)
        probs[(long long)bl * NC + threadIdx.x] = __expf(s[threadIdx.x] - mx) / sum;
}

// ---------------- 8. per-batch token weights ----------------
__global__ void weights_k(const int* __restrict__ ids, const float* __restrict__ col,
                          float* __restrict__ wgt) {
    int b = blockIdx.x, l = threadIdx.x;
    float w = (ids[b * L + l] != 0 ? 1.f : 0.f) * col[b * L + l];
    __shared__ float red[512];
    red[l] = w;
    __syncthreads();
    for (int o = 256; o; o >>= 1) { if (l < o) red[l] = fmaxf(red[l], red[l + o]); __syncthreads(); }
    float mxv = red[0];
    __syncthreads();
    float e = __expf(w - mxv);
    red[l] = e;
    __syncthreads();
    for (int o = 256; o; o >>= 1) { if (l < o) red[l] += red[l + o]; __syncthreads(); }
    wgt[b * L + l] = e / red[0];
}

// ---------------- 9. final reduce ----------------
__global__ void final_k(const float* __restrict__ wgt, const float* __restrict__ probs,
                        float* __restrict__ dout, int first) {
    int b = blockIdx.x;
    __shared__ float red[256];
    int tid = threadIdx.x;
    for (int c = 0; c < NC; c++) {
        float s = 0.f;
        for (int l = tid; l < L; l += 256)
            s += wgt[b * L + l] * probs[(long long)(b * L + l) * NC + c];
        red[tid] = s;
        __syncthreads();
        for (int o = 128; o; o >>= 1) { if (tid < o) red[tid] += red[tid + o]; __syncthreads(); }
        if (tid == 0) {
            float v = 0.5f * red[0];
            dout[b * NC + c] = first ? v : dout[b * NC + c] + v;
        }
        __syncthreads();
    }
}

// ---------------- launch ----------------
extern "C" void kernel_launch(void* const* d_in, const int* in_sizes, int n_in,
                              void* d_out, int out_size) {
    (void)in_sizes; (void)n_in; (void)out_size;
    const int*   ids   = (const int*)d_in[0];
    const float* wv    = (const float*)d_in[1];
    const float* emb   = (const float*)d_in[2];
    const float* W_t   = (const float*)d_in[3];
    const float* b_t   = (const float*)d_in[4];
    const float* gam_t = (const float*)d_in[5];
    const float* bet_t = (const float*)d_in[6];
    const float* Wo_t  = (const float*)d_in[7];
    const float* bo_t  = (const float*)d_in[8];
    const float* W_h   = (const float*)d_in[9];
    const float* b_h   = (const float*)d_in[10];
    const float* gam_h = (const float*)d_in[11];
    const float* bet_h = (const float*)d_in[12];
    const float* Wo_h  = (const float*)d_in[13];
    const float* bo_h  = (const float*)d_in[14];
    float* out = (float*)d_out;

    float *px, *phid, *patt, *pqn, *pkn, *pv, *pout, *pprobs, *pcol, *pwgt;
    cudaGetSymbolAddress((void**)&px, g_x);
    cudaGetSymbolAddress((void**)&phid, g_hid);
    cudaGetSymbolAddress((void**)&patt, g_att);
    cudaGetSymbolAddress((void**)&pqn, g_qn);
    cudaGetSymbolAddress((void**)&pkn, g_kn);
    cudaGetSymbolAddress((void**)&pv, g_v);
    cudaGetSymbolAddress((void**)&pout, g_out);
    cudaGetSymbolAddress((void**)&pprobs, g_probs);
    cudaGetSymbolAddress((void**)&pcol, g_col);
    cudaGetSymbolAddress((void**)&pwgt, g_wgt);

    dim3 proj_grid(D3 / 128, BL / 128, 1);      // 18 x 64
    dim3 att_grid(L / 128, L / 128, BH);        // 4 x 4 x 192
    dim3 av_grid(1, L / 128, BH);               // 1 x 4 x 192

    // ===== token branch =====
    embed_leaky_k<<<BL, 256>>>(ids, emb, px);
    gemm128<1><<<proj_grid, 256>>>(px, 0, W_t, 0, b_t, phid, D3, 0, D);
    splitnorm_k<<<Bsz * NH * L, 64>>>(phid, pqn, pkn, pv);
    gemm128<0><<<att_grid, 256>>>(pkn, (long long)L * HD, pqn, (long long)L * HD,
                                  nullptr, patt, L, (long long)LL, HD);
    zero_col_k<<<BL / 256, 256>>>(pcol);
    lnsm_k<<<BL, 256>>>(patt, gam_t, bet_t, pcol);
    attv128<<<av_grid, 256>>>(patt, pv, pout);
    probs_k<<<BL, 160>>>(pout, Wo_t, bo_t, pprobs);
    weights_k<<<Bsz, 512>>>(ids, pcol, pwgt);
    final_k<<<Bsz, 256>>>(pwgt, pprobs, out, 1);

    // ===== hidden / word-vector branch =====
    gemm128<1><<<proj_grid, 256>>>(wv, 0, W_h, 0, b_h, phid, D3, 0, 300);
    splitnorm_k<<<Bsz * NH * L, 64>>>(phid, pqn, pkn, pv);
    gemm128<0><<<att_grid, 256>>>(pkn, (long long)L * HD, pqn, (long long)L * HD,
                                  nullptr, patt, L, (long long)LL, HD);
    zero_col_k<<<BL / 256, 256>>>(pcol);
    lnsm_k<<<BL, 256>>>(patt, gam_h, bet_h, pcol);
    attv128<<<av_grid, 256>>>(patt, pv, pout);
    probs_k<<<BL, 160>>>(pout, Wo_h, bo_h, pprobs);
    weights_k<<<Bsz, 512>>>(ids, pcol, pwgt);
    final_k<<<Bsz, 256>>>(pwgt, pprobs, out, 0);
}

// round 3
// speedup vs baseline: 2.8819x; 1.9338x over previous
#include <cuda_runtime.h>
#include <math.h>

#define Bsz 16
#define L   512
#define NH  12
#define HD  64
#define D   768
#define D3  2304
#define NC  20
#define BL  (Bsz*L)      // 8192
#define BH  (Bsz*NH)     // 192
#define LL  (L*L)        // 262144

// ---------------- scratch (allocation-free) ----------------
__device__ float g_x[(size_t)BL*D];
__device__ float g_hid[(size_t)BL*D3];
__device__ float g_att[(size_t)BH*LL];
__device__ float g_qn[(size_t)BH*L*HD];
__device__ float g_kn[(size_t)BH*L*HD];
__device__ float g_vt[(size_t)BH*HD*L];    // V transposed: [z][d][l]
__device__ float g_out[(size_t)BL*D];
__device__ float g_probs[(size_t)BL*NC];
__device__ float g_col[BL];
__device__ float g_wgt[BL];

__device__ __forceinline__ float lrelu(float x) { return x >= 0.f ? x : 0.01f * x; }

__device__ __forceinline__ unsigned f2tf(float f) {
    unsigned u; asm("cvt.rna.tf32.f32 %0, %1;" : "=r"(u) : "f"(f)); return u;
}

__device__ __forceinline__ void mma8(float c[4], const unsigned a[4], const unsigned b[2]) {
    asm volatile(
        "mma.sync.aligned.m16n8k8.row.col.f32.tf32.tf32.f32 "
        "{%0,%1,%2,%3},{%4,%5,%6,%7},{%8,%9},{%0,%1,%2,%3};"
        : "+f"(c[0]), "+f"(c[1]), "+f"(c[2]), "+f"(c[3])
        : "r"(a[0]), "r"(a[1]), "r"(a[2]), "r"(a[3]), "r"(b[0]), "r"(b[1]));
}

// ---------------- 1. embedding + leaky ----------------
__global__ void embed_leaky_k(const int* __restrict__ ids, const float* __restrict__ emb,
                              float* __restrict__ x) {
    int bl = blockIdx.x;
    long long id = ids[bl];
    const float* src = emb + id * D;
    float* dst = x + (long long)bl * D;
    for (int k = threadIdx.x; k < D; k += blockDim.x)
        dst[k] = lrelu(src[k]);
}

// ---------------- 2. unified tf32 tensor-core GEMM ----------------
// C = A[m,k] @ B[n,k]^T   (both A and B k-contiguous row-major)
// MODE 0: C[m][n] = lrelu(acc + bias[n])           (proj, z=1)
// MODE 1: C = acc, batched via sA/sB/sC            (attscore)
// MODE 2: C = acc into out[b, i, h*64+n], z=(b,h)  (attv)
template<int BM, int BN, int WM, int WN, int MODE>
__global__ void __launch_bounds__(256)
mma_gemm(const float* __restrict__ A, long long sA, int lda,
         const float* __restrict__ B, long long sB, int ldb,
         const float* __restrict__ bias,
         float* __restrict__ C, long long sC, int ldc, int K) {
    constexpr int BK = 16;
    constexpr int IM = WM / 16;          // mma tiles per warp, m
    constexpr int IN = WN / 8;           // mma tiles per warp, n
    constexpr int WCOLS = BN / WN;       // warps along n
    constexpr int AV = BM * 4 / 256;     // uint4 loads per thread (A)
    constexpr int BV = BN * 4 / 256;     // uint4 loads per thread (B)

    __shared__ __align__(16) unsigned As[2][BM][BK + 4];
    __shared__ __align__(16) unsigned Bs[2][BN][BK + 4];

    const int tid = threadIdx.x;
    const int wid = tid >> 5, lane = tid & 31;
    const int g = lane >> 2, tg = lane & 3;
    const int wm = (wid / WCOLS) * WM, wn = (wid % WCOLS) * WN;

    const float* Ab = A + blockIdx.z * sA + (long long)blockIdx.y * BM * lda;
    const float* Bb = B + blockIdx.z * sB + (long long)blockIdx.x * BN * ldb;

    const int ktiles = (K + BK - 1) / BK;
    float4 fa[AV], fb[BV];
    float acc[IM][IN][4] = {};

#define LDG(k0)                                                                  \
    {                                                                            \
        _Pragma("unroll")                                                        \
        for (int c = 0; c < AV; c++) {                                           \
            int idx = tid + c * 256;                                             \
            int row = idx >> 2, col = (k0) + (idx & 3) * 4;                      \
            fa[c] = (col + 4 <= K) ? *(const float4*)(Ab + (long long)row * lda + col) \
                                   : make_float4(0.f, 0.f, 0.f, 0.f);            \
        }                                                                        \
        _Pragma("unroll")                                                        \
        for (int c = 0; c < BV; c++) {                                           \
            int idx = tid + c * 256;                                             \
            int row = idx >> 2, col = (k0) + (idx & 3) * 4;                      \
            fb[c] = (col + 4 <= K) ? *(const float4*)(Bb + (long long)row * ldb + col) \
                                   : make_float4(0.f, 0.f, 0.f, 0.f);            \
        }                                                                        \
    }
#define STS(bf)                                                                  \
    {                                                                            \
        _Pragma("unroll")                                                        \
        for (int c = 0; c < AV; c++) {                                           \
            int idx = tid + c * 256;                                             \
            int row = idx >> 2, kc = (idx & 3) * 4;                              \
            *(uint4*)&As[bf][row][kc] =                                          \
                make_uint4(f2tf(fa[c].x), f2tf(fa[c].y), f2tf(fa[c].z), f2tf(fa[c].w)); \
        }                                                                        \
        _Pragma("unroll")                                                        \
        for (int c = 0; c < BV; c++) {                                           \
            int idx = tid + c * 256;                                             \
            int row = idx >> 2, kc = (idx & 3) * 4;                              \
            *(uint4*)&Bs[bf][row][kc] =                                          \
                make_uint4(f2tf(fb[c].x), f2tf(fb[c].y), f2tf(fb[c].z), f2tf(fb[c].w)); \
        }                                                                        \
    }

    LDG(0);
    STS(0);
    __syncthreads();
    int buf = 0;
    for (int t = 0; t < ktiles; t++) {
        if (t + 1 < ktiles) LDG((t + 1) * BK);
#pragma unroll
        for (int kk = 0; kk < BK; kk += 8) {
            unsigned a[IM][4], b[IN][2];
#pragma unroll
            for (int im = 0; im < IM; im++) {
                int r = wm + im * 16 + g;
                a[im][0] = As[buf][r][kk + tg];
                a[im][1] = As[buf][r + 8][kk + tg];
                a[im][2] = As[buf][r][kk + tg + 4];
                a[im][3] = As[buf][r + 8][kk + tg + 4];
            }
#pragma unroll
            for (int in_ = 0; in_ < IN; in_++) {
                int r = wn + in_ * 8 + g;
                b[in_][0] = Bs[buf][r][kk + tg];
                b[in_][1] = Bs[buf][r][kk + tg + 4];
            }
#pragma unroll
            for (int im = 0; im < IM; im++)
#pragma unroll
                for (int in_ = 0; in_ < IN; in_++)
                    mma8(acc[im][in_], a[im], b[in_]);
        }
        if (t + 1 < ktiles) { STS(buf ^ 1); __syncthreads(); buf ^= 1; }
    }
#undef LDG
#undef STS

    float* Cb;
    if (MODE == 2) {
        int z = blockIdx.z;
        Cb = C + (long long)(z / NH) * L * D + (z % NH) * HD;
    } else {
        Cb = C + blockIdx.z * sC;
    }
    const int rbase = blockIdx.y * BM + wm + g;
    const int cbase = blockIdx.x * BN + wn + tg * 2;
#pragma unroll
    for (int im = 0; im < IM; im++) {
        int r = rbase + im * 16;
#pragma unroll
        for (int in_ = 0; in_ < IN; in_++) {
            int cc = cbase + in_ * 8;
            float2 v0 = make_float2(acc[im][in_][0], acc[im][in_][1]);
            float2 v1 = make_float2(acc[im][in_][2], acc[im][in_][3]);
            if (MODE == 0) {
                float b0 = bias[cc], b1 = bias[cc + 1];
                v0.x = lrelu(v0.x + b0); v0.y = lrelu(v0.y + b1);
                v1.x = lrelu(v1.x + b0); v1.y = lrelu(v1.y + b1);
            }
            *(float2*)&Cb[(long long)r * ldc + cc] = v0;
            *(float2*)&Cb[(long long)(r + 8) * ldc + cc] = v1;
        }
    }
}

// ---------------- 3. split QKV + cosine-normalize Q,K (+ V transpose) ----------------
__global__ void splitnorm_k(const float* __restrict__ hid, float* __restrict__ qn,
                            float* __restrict__ kn, float* __restrict__ vt) {
    int bhl = blockIdx.x;
    int dd  = threadIdx.x;
    int b   = bhl / (NH * L);
    int rem = bhl % (NH * L);
    int h   = rem / L;
    int l   = rem % L;
    const float* base = hid + (long long)(b * L + l) * D3 + h * HD;
    float q  = base[dd];
    float k  = base[D + dd];
    float vv = base[2 * D + dd];
    __shared__ float sq[64], sk[64];
    sq[dd] = q * q; sk[dd] = k * k;
    __syncthreads();
    for (int o = 32; o; o >>= 1) {
        if (dd < o) { sq[dd] += sq[dd + o]; sk[dd] += sk[dd + o]; }
        __syncthreads();
    }
    float qno = fmaxf(sqrtf(sq[0]), 1e-8f);
    float kno = fmaxf(sqrtf(sk[0]), 1e-8f);
    int z = b * NH + h;
    long long o = ((long long)z * L + l) * HD + dd;
    qn[o] = q / qno; kn[o] = k / kno;
    vt[((long long)z * HD + dd) * L + l] = vv;
}

// ---------------- 4. fused LayerNorm(heads) + softmax(j) + colsum ----------------
__global__ void __launch_bounds__(256)
lnsm_k(float* __restrict__ att, const float* __restrict__ gamma,
       const float* __restrict__ beta, float* __restrict__ col) {
    __shared__ float s[NH][L];
    __shared__ float rinv[NH];
    int b = blockIdx.x / L, i = blockIdx.x % L;
    float* base = att + (long long)b * NH * LL + (long long)i * L;
    int tid = threadIdx.x;
    float g[NH], be[NH];
#pragma unroll
    for (int h = 0; h < NH; h++) { g[h] = gamma[h]; be[h] = beta[h]; }

#pragma unroll
    for (int rep = 0; rep < 2; rep++) {
        int j = tid + rep * 256;
        float v[NH]; float mu = 0.f;
#pragma unroll
        for (int h = 0; h < NH; h++) { v[h] = base[(long long)h * LL + j]; mu += v[h]; }
        mu *= (1.f / NH);
        float var = 0.f;
#pragma unroll
        for (int h = 0; h < NH; h++) { float d0 = v[h] - mu; var += d0 * d0; }
        float rstd = rsqrtf(var * (1.f / NH) + 1e-5f);
#pragma unroll
        for (int h = 0; h < NH; h++)
            s[h][j] = (v[h] - mu) * rstd * g[h] + be[h];
    }
    __syncthreads();

    int w = tid >> 5, lane = tid & 31;
    for (int h = w; h < NH; h += 8) {
        float m = -1e30f;
#pragma unroll
        for (int q = 0; q < 16; q++) m = fmaxf(m, s[h][q * 32 + lane]);
#pragma unroll
        for (int o = 16; o; o >>= 1) m = fmaxf(m, __shfl_xor_sync(0xffffffffu, m, o));
        float sum = 0.f;
#pragma unroll
        for (int q = 0; q < 16; q++) {
            float e = __expf(s[h][q * 32 + lane] - m);
            s[h][q * 32 + lane] = e;
            sum += e;
        }
#pragma unroll
        for (int o = 16; o; o >>= 1) sum += __shfl_xor_sync(0xffffffffu, sum, o);
        if (lane == 0) rinv[h] = 1.f / sum;
    }
    __syncthreads();

    float inv[NH];
#pragma unroll
    for (int h = 0; h < NH; h++) inv[h] = rinv[h];
#pragma unroll
    for (int rep = 0; rep < 2; rep++) {
        int j = tid + rep * 256;
        float cs = 0.f;
#pragma unroll
        for (int h = 0; h < NH; h++) {
            float e = s[h][j] * inv[h];
            base[(long long)h * LL + j] = e;
            cs += e;
        }
        atomicAdd(&col[b * L + j], cs * (1.f / NH));
    }
}

// ---------------- 5. colsum zero ----------------
__global__ void zero_col_k(float* __restrict__ col) {
    int idx = blockIdx.x * blockDim.x + threadIdx.x;
    if (idx < BL) col[idx] = 0.f;
}

// ---------------- 6. per-token class probs ----------------
__global__ void probs_k(const float* __restrict__ out, const float* __restrict__ Wout,
                        const float* __restrict__ bout, float* __restrict__ probs) {
    int bl = blockIdx.x;
    int warp = threadIdx.x >> 5, lane = threadIdx.x & 31;
    __shared__ float s[NC];
    __shared__ float mx, sum;
    const float* row = out + (long long)bl * D;
#pragma unroll
    for (int cc = 0; cc < 4; cc++) {
        int c = warp * 4 + cc;
        const float* w = Wout + c * D;
        float acc = 0.f;
        for (int k = lane; k < D; k += 32) acc += row[k] * w[k];
#pragma unroll
        for (int o = 16; o; o >>= 1) acc += __shfl_down_sync(0xffffffffu, acc, o);
        if (lane == 0) s[c] = acc + bout[c];
    }
    __syncthreads();
    if (threadIdx.x == 0) {
        float m = -1e30f;
        for (int c = 0; c < NC; c++) m = fmaxf(m, s[c]);
        float ss = 0.f;
        for (int c = 0; c < NC; c++) ss += __expf(s[c] - m);
        mx = m; sum = ss;
    }
    __syncthreads();
    if (threadIdx.x < NC)
        probs[(long long)bl * NC + threadIdx.x] = __expf(s[threadIdx.x] - mx) / sum;
}

// ---------------- 7. per-batch token weights ----------------
__global__ void weights_k(const int* __restrict__ ids, const float* __restrict__ col,
                          float* __restrict__ wgt) {
    int b = blockIdx.x, l = threadIdx.x;
    float w = (ids[b * L + l] != 0 ? 1.f : 0.f) * col[b * L + l];
    __shared__ float red[512];
    red[l] = w;
    __syncthreads();
    for (int o = 256; o; o >>= 1) { if (l < o) red[l] = fmaxf(red[l], red[l + o]); __syncthreads(); }
    float mxv = red[0];
    __syncthreads();
    float e = __expf(w - mxv);
    red[l] = e;
    __syncthreads();
    for (int o = 256; o; o >>= 1) { if (l < o) red[l] += red[l + o]; __syncthreads(); }
    wgt[b * L + l] = e / red[0];
}

// ---------------- 8. final reduce ----------------
__global__ void final_k(const float* __restrict__ wgt, const float* __restrict__ probs,
                        float* __restrict__ dout, int first) {
    int b = blockIdx.x;
    __shared__ float red[256];
    int tid = threadIdx.x;
    for (int c = 0; c < NC; c++) {
        float s = 0.f;
        for (int l = tid; l < L; l += 256)
            s += wgt[b * L + l] * probs[(long long)(b * L + l) * NC + c];
        red[tid] = s;
        __syncthreads();
        for (int o = 128; o; o >>= 1) { if (tid < o) red[tid] += red[tid + o]; __syncthreads(); }
        if (tid == 0) {
            float v = 0.5f * red[0];
            dout[b * NC + c] = first ? v : dout[b * NC + c] + v;
        }
        __syncthreads();
    }
}

// ---------------- launch ----------------
extern "C" void kernel_launch(void* const* d_in, const int* in_sizes, int n_in,
                              void* d_out, int out_size) {
    (void)in_sizes; (void)n_in; (void)out_size;
    const int*   ids   = (const int*)d_in[0];
    const float* wv    = (const float*)d_in[1];
    const float* emb   = (const float*)d_in[2];
    const float* W_t   = (const float*)d_in[3];
    const float* b_t   = (const float*)d_in[4];
    const float* gam_t = (const float*)d_in[5];
    const float* bet_t = (const float*)d_in[6];
    const float* Wo_t  = (const float*)d_in[7];
    const float* bo_t  = (const float*)d_in[8];
    const float* W_h   = (const float*)d_in[9];
    const float* b_h   = (const float*)d_in[10];
    const float* gam_h = (const float*)d_in[11];
    const float* bet_h = (const float*)d_in[12];
    const float* Wo_h  = (const float*)d_in[13];
    const float* bo_h  = (const float*)d_in[14];
    float* out = (float*)d_out;

    float *px, *phid, *patt, *pqn, *pkn, *pvt, *pout, *pprobs, *pcol, *pwgt;
    cudaGetSymbolAddress((void**)&px, g_x);
    cudaGetSymbolAddress((void**)&phid, g_hid);
    cudaGetSymbolAddress((void**)&patt, g_att);
    cudaGetSymbolAddress((void**)&pqn, g_qn);
    cudaGetSymbolAddress((void**)&pkn, g_kn);
    cudaGetSymbolAddress((void**)&pvt, g_vt);
    cudaGetSymbolAddress((void**)&pout, g_out);
    cudaGetSymbolAddress((void**)&pprobs, g_probs);
    cudaGetSymbolAddress((void**)&pcol, g_col);
    cudaGetSymbolAddress((void**)&pwgt, g_wgt);

    dim3 proj_grid(D3 / 128, BL / 128, 1);      // 18 x 64
    dim3 att_grid(L / 128, L / 128, BH);        // 4 x 4 x 192
    dim3 av_grid(1, L / 128, BH);               // 1 x 4 x 192
    const long long sQK = (long long)L * HD;

    // ===== token branch =====
    embed_leaky_k<<<BL, 256>>>(ids, emb, px);
    mma_gemm<128,128,32,64,0><<<proj_grid, 256>>>(px, 0, D, W_t, 0, D, b_t, phid, 0, D3, D);
    splitnorm_k<<<Bsz * NH * L, 64>>>(phid, pqn, pkn, pvt);
    mma_gemm<128,128,32,64,1><<<att_grid, 256>>>(pkn, sQK, HD, pqn, sQK, HD, nullptr,
                                                 patt, (long long)LL, L, HD);
    zero_col_k<<<BL / 256, 256>>>(pcol);
    lnsm_k<<<BL, 256>>>(patt, gam_t, bet_t, pcol);
    mma_gemm<128,64,32,32,2><<<av_grid, 256>>>(patt, (long long)LL, L, pvt, sQK, L, nullptr,
                                               pout, 0, D, L);
    probs_k<<<BL, 160>>>(pout, Wo_t, bo_t, pprobs);
    weights_k<<<Bsz, 512>>>(ids, pcol, pwgt);
    final_k<<<Bsz, 256>>>(pwgt, pprobs, out, 1);

    // ===== hidden / word-vector branch =====
    mma_gemm<128,128,32,64,0><<<proj_grid, 256>>>(wv, 0, 300, W_h, 0, 300, b_h, phid, 0, D3, 300);
    splitnorm_k<<<Bsz * NH * L, 64>>>(phid, pqn, pkn, pvt);
    mma_gemm<128,128,32,64,1><<<att_grid, 256>>>(pkn, sQK, HD, pqn, sQK, HD, nullptr,
                                                 patt, (long long)LL, L, HD);
    zero_col_k<<<BL / 256, 256>>>(pcol);
    lnsm_k<<<BL, 256>>>(patt, gam_h, bet_h, pcol);
    mma_gemm<128,64,32,32,2><<<av_grid, 256>>>(patt, (long long)LL, L, pvt, sQK, L, nullptr,
                                               pout, 0, D, L);
    probs_k<<<BL, 160>>>(pout, Wo_h, bo_h, pprobs);
    weights_k<<<Bsz, 512>>>(ids, pcol, pwgt);
    final_k<<<Bsz, 256>>>(pwgt, pprobs, out, 0);
}

// round 4
// speedup vs baseline: 3.9420x; 1.3678x over previous
#include <cuda_runtime.h>
#include <cuda_fp16.h>
#include <math.h>

#define Bsz 16
#define L   512
#define NH  12
#define HD  64
#define D   768
#define D3  2304
#define NC  20
#define BL  (Bsz*L)      // 8192
#define BH  (Bsz*NH)     // 192
#define LL  (L*L)        // 262144
#define KH  320          // padded K for hidden branch (300 -> 320)

// ---------------- scratch (allocation-free) ----------------
__device__ __half g_x[(size_t)BL*D];          // token activations fp16
__device__ __half g_wt16[(size_t)D3*D];       // W_t fp16
__device__ __half g_wh16[(size_t)D3*KH];      // W_h fp16 (padded)
__device__ __half g_wv16[(size_t)BL*KH];      // wv fp16 (padded)
__device__ __half g_hid[(size_t)BL*D3];       // post-linear hiddens fp16
__device__ float  g_att[(size_t)BH*LL];       // raw scores fp32
__device__ __half g_att16[(size_t)BH*LL];     // post-softmax att fp16
__device__ __half g_qn[(size_t)BH*L*HD];
__device__ __half g_kn[(size_t)BH*L*HD];
__device__ __half g_vt[(size_t)BH*HD*L];      // V transposed [z][d][l]
__device__ float  g_out[(size_t)BL*D];
__device__ float  g_probs[(size_t)BL*NC];
__device__ float  g_col[BL];
__device__ float  g_wgt[BL];

__device__ __forceinline__ float lrelu(float x) { return x >= 0.f ? x : 0.01f * x; }

__device__ __forceinline__ void mma16(float c[4], const unsigned a[4], const unsigned b[2]) {
    asm volatile(
        "mma.sync.aligned.m16n8k16.row.col.f32.f16.f16.f32 "
        "{%0,%1,%2,%3},{%4,%5,%6,%7},{%8,%9},{%0,%1,%2,%3};"
        : "+f"(c[0]), "+f"(c[1]), "+f"(c[2]), "+f"(c[3])
        : "r"(a[0]), "r"(a[1]), "r"(a[2]), "r"(a[3]), "r"(b[0]), "r"(b[1]));
}
__device__ __forceinline__ unsigned lds_u32(const __half* p) { return *(const unsigned*)p; }

// ---------------- 0. fp32 -> fp16 (optionally K-padded rows) ----------------
__global__ void convpad_k(const float* __restrict__ src, __half* __restrict__ dst,
                          int K, int KP) {
    long long row = blockIdx.x;
    for (int k = threadIdx.x; k < KP; k += blockDim.x)
        dst[row * KP + k] = (k < K) ? __float2half_rn(src[row * K + k]) : __half(0.f);
}

// ---------------- 1. embedding + leaky -> fp16 ----------------
__global__ void embed_leaky_k(const int* __restrict__ ids, const float* __restrict__ emb,
                              __half* __restrict__ x) {
    int bl = blockIdx.x;
    long long id = ids[bl];
    const float* src = emb + id * D;
    __half* dst = x + (long long)bl * D;
    for (int k = threadIdx.x; k < D; k += blockDim.x)
        dst[k] = __float2half_rn(lrelu(src[k]));
}

// ---------------- 2. unified fp16 tensor-core GEMM (fp32 acc) ----------------
// C = A[m,k] @ B[n,k]^T, A/B fp16 k-contiguous. K multiple of 32.
// MODE 0: hid fp16 = lrelu(acc+bias)  MODE 1: att fp32 = acc (batched)
// MODE 2: out fp32, z=(b,h), col offset h*64
template<int BM, int BN, int WM, int WN, int MODE>
__global__ void __launch_bounds__(256)
h_gemm(const __half* __restrict__ A, long long sA, int lda,
       const __half* __restrict__ B, long long sB, int ldb,
       const float* __restrict__ bias,
       void* __restrict__ Cv, long long sC, int ldc, int K) {
    constexpr int BK = 32;               // halves per k-tile
    constexpr int PAD = 8;
    constexpr int IM = WM / 16;
    constexpr int IN = WN / 8;
    constexpr int WCOLS = BN / WN;
    constexpr int AV = BM * BK / (256 * 8);
    constexpr int BV = BN * BK / (256 * 8);

    __shared__ __align__(16) __half As[2][BM][BK + PAD];
    __shared__ __align__(16) __half Bs[2][BN][BK + PAD];

    const int tid = threadIdx.x;
    const int wid = tid >> 5, lane = tid & 31;
    const int g = lane >> 2, tg = lane & 3;
    const int wm = (wid / WCOLS) * WM, wn = (wid % WCOLS) * WN;

    const __half* Ab = A + blockIdx.z * sA + (long long)blockIdx.y * BM * lda;
    const __half* Bb = B + blockIdx.z * sB + (long long)blockIdx.x * BN * ldb;

    const int ktiles = K / BK;
    uint4 fa[AV], fb[BV];
    float acc[IM][IN][4] = {};

#define LDG(k0)                                                                  \
    {                                                                            \
        _Pragma("unroll")                                                        \
        for (int c = 0; c < AV; c++) {                                           \
            int idx = tid + c * 256;                                             \
            int row = idx >> 2, cq = idx & 3;                                    \
            fa[c] = *(const uint4*)(Ab + (long long)row * lda + (k0) + cq * 8);  \
        }                                                                        \
        _Pragma("unroll")                                                        \
        for (int c = 0; c < BV; c++) {                                           \
            int idx = tid + c * 256;                                             \
            int row = idx >> 2, cq = idx & 3;                                    \
            fb[c] = *(const uint4*)(Bb + (long long)row * ldb + (k0) + cq * 8);  \
        }                                                                        \
    }
#define STS(bf)                                                                  \
    {                                                                            \
        _Pragma("unroll")                                                        \
        for (int c = 0; c < AV; c++) {                                           \
            int idx = tid + c * 256;                                             \
            int row = idx >> 2, cq = idx & 3;                                    \
            *(uint4*)&As[bf][row][cq * 8] = fa[c];                               \
        }                                                                        \
        _Pragma("unroll")                                                        \
        for (int c = 0; c < BV; c++) {                                           \
            int idx = tid + c * 256;                                             \
            int row = idx >> 2, cq = idx & 3;                                    \
            *(uint4*)&Bs[bf][row][cq * 8] = fb[c];                               \
        }                                                                        \
    }

    LDG(0);
    STS(0);
    __syncthreads();
    int buf = 0;
    for (int t = 0; t < ktiles; t++) {
        if (t + 1 < ktiles) LDG((t + 1) * BK);
#pragma unroll
        for (int kk = 0; kk < BK; kk += 16) {
            unsigned a[IM][4], b[IN][2];
#pragma unroll
            for (int im = 0; im < IM; im++) {
                int r = wm + im * 16 + g;
                a[im][0] = lds_u32(&As[buf][r][kk + tg * 2]);
                a[im][1] = lds_u32(&As[buf][r + 8][kk + tg * 2]);
                a[im][2] = lds_u32(&As[buf][r][kk + tg * 2 + 8]);
                a[im][3] = lds_u32(&As[buf][r + 8][kk + tg * 2 + 8]);
            }
#pragma unroll
            for (int in_ = 0; in_ < IN; in_++) {
                int r = wn + in_ * 8 + g;
                b[in_][0] = lds_u32(&Bs[buf][r][kk + tg * 2]);
                b[in_][1] = lds_u32(&Bs[buf][r][kk + tg * 2 + 8]);
            }
#pragma unroll
            for (int im = 0; im < IM; im++)
#pragma unroll
                for (int in_ = 0; in_ < IN; in_++)
                    mma16(acc[im][in_], a[im], b[in_]);
        }
        if (t + 1 < ktiles) { STS(buf ^ 1); __syncthreads(); buf ^= 1; }
    }
#undef LDG
#undef STS

    const int rbase = blockIdx.y * BM + wm + g;
    const int cbase = blockIdx.x * BN + wn + tg * 2;

    if (MODE == 0) {
        __half* Cb = (__half*)Cv + blockIdx.z * sC;
#pragma unroll
        for (int im = 0; im < IM; im++) {
            int r = rbase + im * 16;
#pragma unroll
            for (int in_ = 0; in_ < IN; in_++) {
                int cc = cbase + in_ * 8;
                float b0 = bias[cc], b1 = bias[cc + 1];
                __half2 v0 = __floats2half2_rn(lrelu(acc[im][in_][0] + b0),
                                               lrelu(acc[im][in_][1] + b1));
                __half2 v1 = __floats2half2_rn(lrelu(acc[im][in_][2] + b0),
                                               lrelu(acc[im][in_][3] + b1));
                *(__half2*)&Cb[(long long)r * ldc + cc] = v0;
                *(__half2*)&Cb[(long long)(r + 8) * ldc + cc] = v1;
            }
        }
    } else {
        float* Cb;
        if (MODE == 2) {
            int z = blockIdx.z;
            Cb = (float*)Cv + (long long)(z / NH) * L * D + (z % NH) * HD;
        } else {
            Cb = (float*)Cv + blockIdx.z * sC;
        }
#pragma unroll
        for (int im = 0; im < IM; im++) {
            int r = rbase + im * 16;
#pragma unroll
            for (int in_ = 0; in_ < IN; in_++) {
                int cc = cbase + in_ * 8;
                *(float2*)&Cb[(long long)r * ldc + cc] =
                    make_float2(acc[im][in_][0], acc[im][in_][1]);
                *(float2*)&Cb[(long long)(r + 8) * ldc + cc] =
                    make_float2(acc[im][in_][2], acc[im][in_][3]);
            }
        }
    }
}

// ---------------- 3. split QKV + cosine-normalize + V transpose (+ col zero) ----------------
__global__ void splitnorm_k(const __half* __restrict__ hid, __half* __restrict__ qn,
                            __half* __restrict__ kn, __half* __restrict__ vt,
                            float* __restrict__ col) {
    int bhl = blockIdx.x;
    int dd  = threadIdx.x;
    if (dd == 0 && bhl < BL) col[bhl] = 0.f;
    int b   = bhl / (NH * L);
    int rem = bhl % (NH * L);
    int h   = rem / L;
    int l   = rem % L;
    const __half* base = hid + (long long)(b * L + l) * D3 + h * HD;
    float q  = __half2float(base[dd]);
    float k  = __half2float(base[D + dd]);
    __half vv = base[2 * D + dd];
    __shared__ float sq[64], sk[64];
    sq[dd] = q * q; sk[dd] = k * k;
    __syncthreads();
    for (int o = 32; o; o >>= 1) {
        if (dd < o) { sq[dd] += sq[dd + o]; sk[dd] += sk[dd + o]; }
        __syncthreads();
    }
    float qno = fmaxf(sqrtf(sq[0]), 1e-8f);
    float kno = fmaxf(sqrtf(sk[0]), 1e-8f);
    int z = b * NH + h;
    long long o = ((long long)z * L + l) * HD + dd;
    qn[o] = __float2half_rn(q / qno);
    kn[o] = __float2half_rn(k / kno);
    vt[((long long)z * HD + dd) * L + l] = vv;
}

// ---------------- 4. fused LN(heads) + softmax(j) + colsum, writes fp16 ----------------
__global__ void __launch_bounds__(256)
lnsm_k(const float* __restrict__ att, __half* __restrict__ att16,
       const float* __restrict__ gamma, const float* __restrict__ beta,
       float* __restrict__ col) {
    __shared__ float s[NH][L];
    __shared__ float rinv[NH];
    int b = blockIdx.x / L, i = blockIdx.x % L;
    const float* base = att + (long long)b * NH * LL + (long long)i * L;
    __half* base16 = att16 + (long long)b * NH * LL + (long long)i * L;
    int tid = threadIdx.x;
    float g[NH], be[NH];
#pragma unroll
    for (int h = 0; h < NH; h++) { g[h] = gamma[h]; be[h] = beta[h]; }

#pragma unroll
    for (int rep = 0; rep < 2; rep++) {
        int j = tid + rep * 256;
        float v[NH]; float mu = 0.f;
#pragma unroll
        for (int h = 0; h < NH; h++) { v[h] = base[(long long)h * LL + j]; mu += v[h]; }
        mu *= (1.f / NH);
        float var = 0.f;
#pragma unroll
        for (int h = 0; h < NH; h++) { float d0 = v[h] - mu; var += d0 * d0; }
        float rstd = rsqrtf(var * (1.f / NH) + 1e-5f);
#pragma unroll
        for (int h = 0; h < NH; h++)
            s[h][j] = (v[h] - mu) * rstd * g[h] + be[h];
    }
    __syncthreads();

    int w = tid >> 5, lane = tid & 31;
    for (int h = w; h < NH; h += 8) {
        float m = -1e30f;
#pragma unroll
        for (int q = 0; q < 16; q++) m = fmaxf(m, s[h][q * 32 + lane]);
#pragma unroll
        for (int o = 16; o; o >>= 1) m = fmaxf(m, __shfl_xor_sync(0xffffffffu, m, o));
        float sum = 0.f;
#pragma unroll
        for (int q = 0; q < 16; q++) {
            float e = __expf(s[h][q * 32 + lane] - m);
            s[h][q * 32 + lane] = e;
            sum += e;
        }
#pragma unroll
        for (int o = 16; o; o >>= 1) sum += __shfl_xor_sync(0xffffffffu, sum, o);
        if (lane == 0) rinv[h] = 1.f / sum;
    }
    __syncthreads();

    float inv[NH];
#pragma unroll
    for (int h = 0; h < NH; h++) inv[h] = rinv[h];
#pragma unroll
    for (int rep = 0; rep < 2; rep++) {
        int j = tid + rep * 256;
        float cs = 0.f;
#pragma unroll
        for (int h = 0; h < NH; h++) {
            float e = s[h][j] * inv[h];
            base16[(long long)h * LL + j] = __float2half_rn(e);
            cs += e;
        }
        atomicAdd(&col[b * L + j], cs * (1.f / NH));
    }
}

// ---------------- 5. per-token class probs ----------------
__global__ void probs_k(const float* __restrict__ out, const float* __restrict__ Wout,
                        const float* __restrict__ bout, float* __restrict__ probs) {
    int bl = blockIdx.x;
    int warp = threadIdx.x >> 5, lane = threadIdx.x & 31;
    __shared__ float s[NC];
    __shared__ float mx, sum;
    const float* row = out + (long long)bl * D;
#pragma unroll
    for (int cc = 0; cc < 4; cc++) {
        int c = warp * 4 + cc;
        const float* w = Wout + c * D;
        float acc = 0.f;
        for (int k = lane; k < D; k += 32) acc += row[k] * w[k];
#pragma unroll
        for (int o = 16; o; o >>= 1) acc += __shfl_down_sync(0xffffffffu, acc, o);
        if (lane == 0) s[c] = acc + bout[c];
    }
    __syncthreads();
    if (threadIdx.x == 0) {
        float m = -1e30f;
        for (int c = 0; c < NC; c++) m = fmaxf(m, s[c]);
        float ss = 0.f;
        for (int c = 0; c < NC; c++) ss += __expf(s[c] - m);
        mx = m; sum = ss;
    }
    __syncthreads();
    if (threadIdx.x < NC)
        probs[(long long)bl * NC + threadIdx.x] = __expf(s[threadIdx.x] - mx) / sum;
}

// ---------------- 6. per-batch token weights ----------------
__global__ void weights_k(const int* __restrict__ ids, const float* __restrict__ col,
                          float* __restrict__ wgt) {
    int b = blockIdx.x, l = threadIdx.x;
    float w = (ids[b * L + l] != 0 ? 1.f : 0.f) * col[b * L + l];
    __shared__ float red[512];
    red[l] = w;
    __syncthreads();
    for (int o = 256; o; o >>= 1) { if (l < o) red[l] = fmaxf(red[l], red[l + o]); __syncthreads(); }
    float mxv = red[0];
    __syncthreads();
    float e = __expf(w - mxv);
    red[l] = e;
    __syncthreads();
    for (int o = 256; o; o >>= 1) { if (l < o) red[l] += red[l + o]; __syncthreads(); }
    wgt[b * L + l] = e / red[0];
}

// ---------------- 7. final reduce ----------------
__global__ void final_k(const float* __restrict__ wgt, const float* __restrict__ probs,
                        float* __restrict__ dout, int first) {
    int b = blockIdx.x;
    __shared__ float red[256];
    int tid = threadIdx.x;
    for (int c = 0; c < NC; c++) {
        float s = 0.f;
        for (int l = tid; l < L; l += 256)
            s += wgt[b * L + l] * probs[(long long)(b * L + l) * NC + c];
        red[tid] = s;
        __syncthreads();
        for (int o = 128; o; o >>= 1) { if (tid < o) red[tid] += red[tid + o]; __syncthreads(); }
        if (tid == 0) {
            float v = 0.5f * red[0];
            dout[b * NC + c] = first ? v : dout[b * NC + c] + v;
        }
        __syncthreads();
    }
}

// ---------------- launch ----------------
extern "C" void kernel_launch(void* const* d_in, const int* in_sizes, int n_in,
                              void* d_out, int out_size) {
    (void)in_sizes; (void)n_in; (void)out_size;
    const int*   ids   = (const int*)d_in[0];
    const float* wv    = (const float*)d_in[1];
    const float* emb   = (const float*)d_in[2];
    const float* W_t   = (const float*)d_in[3];
    const float* b_t   = (const float*)d_in[4];
    const float* gam_t = (const float*)d_in[5];
    const float* bet_t = (const float*)d_in[6];
    const float* Wo_t  = (const float*)d_in[7];
    const float* bo_t  = (const float*)d_in[8];
    const float* W_h   = (const float*)d_in[9];
    const float* b_h   = (const float*)d_in[10];
    const float* gam_h = (const float*)d_in[11];
    const float* bet_h = (const float*)d_in[12];
    const float* Wo_h  = (const float*)d_in[13];
    const float* bo_h  = (const float*)d_in[14];
    float* out = (float*)d_out;

    __half *px, *pwt, *pwh, *pwv, *phid, *patt16, *pqn, *pkn, *pvt;
    float *patt, *pout, *pprobs, *pcol, *pwgt;
    cudaGetSymbolAddress((void**)&px, g_x);
    cudaGetSymbolAddress((void**)&pwt, g_wt16);
    cudaGetSymbolAddress((void**)&pwh, g_wh16);
    cudaGetSymbolAddress((void**)&pwv, g_wv16);
    cudaGetSymbolAddress((void**)&phid, g_hid);
    cudaGetSymbolAddress((void**)&patt, g_att);
    cudaGetSymbolAddress((void**)&patt16, g_att16);
    cudaGetSymbolAddress((void**)&pqn, g_qn);
    cudaGetSymbolAddress((void**)&pkn, g_kn);
    cudaGetSymbolAddress((void**)&pvt, g_vt);
    cudaGetSymbolAddress((void**)&pout, g_out);
    cudaGetSymbolAddress((void**)&pprobs, g_probs);
    cudaGetSymbolAddress((void**)&pcol, g_col);
    cudaGetSymbolAddress((void**)&pwgt, g_wgt);

    dim3 proj_grid(D3 / 128, BL / 128, 1);
    dim3 att_grid(L / 128, L / 128, BH);
    dim3 av_grid(1, L / 128, BH);
    const long long sQK = (long long)L * HD;

    // weight / input conversions
    convpad_k<<<D3, 256>>>(W_t, pwt, D, D);
    convpad_k<<<D3, 256>>>(W_h, pwh, 300, KH);
    convpad_k<<<BL, 256>>>(wv, pwv, 300, KH);

    // ===== token branch =====
    embed_leaky_k<<<BL, 256>>>(ids, emb, px);
    h_gemm<128,128,32,64,0><<<proj_grid, 256>>>(px, 0, D, pwt, 0, D, b_t, phid, 0, D3, D);
    splitnorm_k<<<Bsz * NH * L, 64>>>(phid, pqn, pkn, pvt, pcol);
    h_gemm<128,128,32,64,1><<<att_grid, 256>>>(pkn, sQK, HD, pqn, sQK, HD, nullptr,
                                               patt, (long long)LL, L, HD);
    lnsm_k<<<BL, 256>>>(patt, patt16, gam_t, bet_t, pcol);
    h_gemm<128,64,32,32,2><<<av_grid, 256>>>(patt16, (long long)LL, L, pvt, sQK, L, nullptr,
                                             pout, 0, D, L);
    probs_k<<<BL, 160>>>(pout, Wo_t, bo_t, pprobs);
    weights_k<<<Bsz, 512>>>(ids, pcol, pwgt);
    final_k<<<Bsz, 256>>>(pwgt, pprobs, out, 1);

    // ===== hidden / word-vector branch =====
    h_gemm<128,128,32,64,0><<<proj_grid, 256>>>(pwv, 0, KH, pwh, 0, KH, b_h, phid, 0, D3, KH);
    splitnorm_k<<<Bsz * NH * L, 64>>>(phid, pqn, pkn, pvt, pcol);
    h_gemm<128,128,32,64,1><<<att_grid, 256>>>(pkn, sQK, HD, pqn, sQK, HD, nullptr,
                                               patt, (long long)LL, L, HD);
    lnsm_k<<<BL, 256>>>(patt, patt16, gam_h, bet_h, pcol);
    h_gemm<128,64,32,32,2><<<av_grid, 256>>>(patt16, (long long)LL, L, pvt, sQK, L, nullptr,
                                             pout, 0, D, L);
    probs_k<<<BL, 160>>>(pout, Wo_h, bo_h, pprobs);
    weights_k<<<Bsz, 512>>>(ids, pcol, pwgt);
    final_k<<<Bsz, 256>>>(pwgt, pprobs, out, 0);
}

// round 5
// speedup vs baseline: 4.3915x; 1.1140x over previous
#include <cuda_runtime.h>
#include <cuda_fp16.h>
#include <math.h>

#define Bsz 16
#define L   512
#define NH  12
#define HD  64
#define D   768
#define D3  2304
#define NC  20
#define BL  (Bsz*L)      // 8192
#define BH  (Bsz*NH)     // 192
#define LL  (L*L)        // 262144
#define KH  320          // padded K for hidden branch (300 -> 320)

// ---------------- scratch (allocation-free) ----------------
__device__ __half g_x[(size_t)BL*D];          // token activations fp16
__device__ __half g_wt16[(size_t)D3*D];       // W_t fp16
__device__ __half g_wh16[(size_t)D3*KH];      // W_h fp16 (padded)
__device__ __half g_wv16[(size_t)BL*KH];      // wv fp16 (padded)
__device__ __half g_hid[(size_t)BL*D3];       // post-linear hiddens fp16
__device__ __half g_att16[(size_t)BH*LL];     // scores, then softmaxed (in-place)
__device__ __half g_qn[(size_t)BH*L*HD];
__device__ __half g_kn[(size_t)BH*L*HD];
__device__ __half g_vt[(size_t)BH*HD*L];      // V transposed [z][d][l]
__device__ float  g_out[(size_t)BL*D];
__device__ float  g_probs[(size_t)BL*NC];
__device__ float  g_col[BL];
__device__ float  g_wgt[BL];

__device__ __forceinline__ float lrelu(float x) { return x >= 0.f ? x : 0.01f * x; }

__device__ __forceinline__ void mma16(float c[4], const unsigned a[4], const unsigned b[2]) {
    asm volatile(
        "mma.sync.aligned.m16n8k16.row.col.f32.f16.f16.f32 "
        "{%0,%1,%2,%3},{%4,%5,%6,%7},{%8,%9},{%0,%1,%2,%3};"
        : "+f"(c[0]), "+f"(c[1]), "+f"(c[2]), "+f"(c[3])
        : "r"(a[0]), "r"(a[1]), "r"(a[2]), "r"(a[3]), "r"(b[0]), "r"(b[1]));
}
__device__ __forceinline__ unsigned lds_u32(const __half* p) { return *(const unsigned*)p; }
__device__ __forceinline__ void cpasync16(void* smem, const void* gmem) {
    unsigned s = (unsigned)__cvta_generic_to_shared(smem);
    asm volatile("cp.async.cg.shared.global [%0], [%1], 16;\n" :: "r"(s), "l"(gmem));
}
__device__ __forceinline__ void cpcommit() { asm volatile("cp.async.commit_group;\n"); }
__device__ __forceinline__ void cpwait1()  { asm volatile("cp.async.wait_group 1;\n"); }

// ---------------- 0. fp32 -> fp16 (optionally K-padded rows) ----------------
__global__ void convpad_k(const float* __restrict__ src, __half* __restrict__ dst,
                          int K, int KP) {
    long long row = blockIdx.x;
    for (int k4 = threadIdx.x * 4; k4 < KP; k4 += blockDim.x * 4) {
        float4 v = (k4 + 4 <= K) ? *(const float4*)(src + row * K + k4)
                                 : make_float4(k4 < K ? src[row * K + k4] : 0.f,
                                               k4 + 1 < K ? src[row * K + k4 + 1] : 0.f,
                                               k4 + 2 < K ? src[row * K + k4 + 2] : 0.f,
                                               k4 + 3 < K ? src[row * K + k4 + 3] : 0.f);
        __half2 h0 = __floats2half2_rn(v.x, v.y);
        __half2 h1 = __floats2half2_rn(v.z, v.w);
        *(__half2*)(dst + row * KP + k4) = h0;
        *(__half2*)(dst + row * KP + k4 + 2) = h1;
    }
}

// ---------------- 1. embedding + leaky -> fp16 ----------------
__global__ void embed_leaky_k(const int* __restrict__ ids, const float* __restrict__ emb,
                              __half* __restrict__ x) {
    int bl = blockIdx.x;
    long long id = ids[bl];
    const float* src = emb + id * D;
    __half* dst = x + (long long)bl * D;
    for (int k4 = threadIdx.x * 4; k4 < D; k4 += blockDim.x * 4) {
        float4 v = *(const float4*)(src + k4);
        __half2 h0 = __floats2half2_rn(lrelu(v.x), lrelu(v.y));
        __half2 h1 = __floats2half2_rn(lrelu(v.z), lrelu(v.w));
        *(__half2*)(dst + k4) = h0;
        *(__half2*)(dst + k4 + 2) = h1;
    }
}

// ---------------- 2. unified fp16 tensor-core GEMM, cp.async 3-stage ----------------
// C = A[m,k] @ B[n,k]^T, fp16 in, fp32 acc. K multiple of 32.
// MODE 0: hid fp16 = lrelu(acc+bias)   MODE 1: att fp16 = acc (batched)
// MODE 2: out fp32, z=(b,h), col offset h*64
template<int BM, int BN, int WM, int WN, int MODE>
__global__ void __launch_bounds__(256)
h_gemm(const __half* __restrict__ A, long long sA, int lda,
       const __half* __restrict__ B, long long sB, int ldb,
       const float* __restrict__ bias,
       void* __restrict__ Cv, long long sC, int ldc, int K) {
    constexpr int BK = 32;
    constexpr int PAD = 8;
    constexpr int STG = 3;
    constexpr int IM = WM / 16;
    constexpr int IN = WN / 8;
    constexpr int WCOLS = BN / WN;
    constexpr int AV = BM * BK / (256 * 8);
    constexpr int BV = BN * BK / (256 * 8);

    __shared__ __align__(16) __half As[STG][BM][BK + PAD];
    __shared__ __align__(16) __half Bs[STG][BN][BK + PAD];

    const int tid = threadIdx.x;
    const int wid = tid >> 5, lane = tid & 31;
    const int g = lane >> 2, tg = lane & 3;
    const int wm = (wid / WCOLS) * WM, wn = (wid % WCOLS) * WN;

    const __half* Ab = A + blockIdx.z * sA + (long long)blockIdx.y * BM * lda;
    const __half* Bb = B + blockIdx.z * sB + (long long)blockIdx.x * BN * ldb;

    const int ktiles = K / BK;
    float acc[IM][IN][4] = {};

    auto issue = [&](int t, int s) {
        int k0 = t * BK;
#pragma unroll
        for (int c = 0; c < AV; c++) {
            int idx = tid + c * 256;
            int row = idx >> 2, cq = idx & 3;
            cpasync16(&As[s][row][cq * 8], Ab + (long long)row * lda + k0 + cq * 8);
        }
#pragma unroll
        for (int c = 0; c < BV; c++) {
            int idx = tid + c * 256;
            int row = idx >> 2, cq = idx & 3;
            cpasync16(&Bs[s][row][cq * 8], Bb + (long long)row * ldb + k0 + cq * 8);
        }
    };

    issue(0, 0); cpcommit();
    if (ktiles > 1) issue(1, 1);
    cpcommit();
    cpwait1();
    __syncthreads();

    int rs = 0;
    for (int t = 0; t < ktiles; t++) {
#pragma unroll
        for (int kk = 0; kk < BK; kk += 16) {
            unsigned a[IM][4], b[IN][2];
#pragma unroll
            for (int im = 0; im < IM; im++) {
                int r = wm + im * 16 + g;
                a[im][0] = lds_u32(&As[rs][r][kk + tg * 2]);
                a[im][1] = lds_u32(&As[rs][r + 8][kk + tg * 2]);
                a[im][2] = lds_u32(&As[rs][r][kk + tg * 2 + 8]);
                a[im][3] = lds_u32(&As[rs][r + 8][kk + tg * 2 + 8]);
            }
#pragma unroll
            for (int in_ = 0; in_ < IN; in_++) {
                int r = wn + in_ * 8 + g;
                b[in_][0] = lds_u32(&Bs[rs][r][kk + tg * 2]);
                b[in_][1] = lds_u32(&Bs[rs][r][kk + tg * 2 + 8]);
            }
#pragma unroll
            for (int im = 0; im < IM; im++)
#pragma unroll
                for (int in_ = 0; in_ < IN; in_++)
                    mma16(acc[im][in_], a[im], b[in_]);
        }
        if (t + 2 < ktiles) issue(t + 2, (rs + 2) % STG);
        cpcommit();
        cpwait1();
        __syncthreads();
        rs = (rs + 1) % STG;
    }

    const int rbase = blockIdx.y * BM + wm + g;
    const int cbase = blockIdx.x * BN + wn + tg * 2;

    if (MODE == 0) {
        __half* Cb = (__half*)Cv + blockIdx.z * sC;
#pragma unroll
        for (int im = 0; im < IM; im++) {
            int r = rbase + im * 16;
#pragma unroll
            for (int in_ = 0; in_ < IN; in_++) {
                int cc = cbase + in_ * 8;
                float b0 = bias[cc], b1 = bias[cc + 1];
                *(__half2*)&Cb[(long long)r * ldc + cc] =
                    __floats2half2_rn(lrelu(acc[im][in_][0] + b0), lrelu(acc[im][in_][1] + b1));
                *(__half2*)&Cb[(long long)(r + 8) * ldc + cc] =
                    __floats2half2_rn(lrelu(acc[im][in_][2] + b0), lrelu(acc[im][in_][3] + b1));
            }
        }
    } else if (MODE == 1) {
        __half* Cb = (__half*)Cv + blockIdx.z * sC;
#pragma unroll
        for (int im = 0; im < IM; im++) {
            int r = rbase + im * 16;
#pragma unroll
            for (int in_ = 0; in_ < IN; in_++) {
                int cc = cbase + in_ * 8;
                *(__half2*)&Cb[(long long)r * ldc + cc] =
                    __floats2half2_rn(acc[im][in_][0], acc[im][in_][1]);
                *(__half2*)&Cb[(long long)(r + 8) * ldc + cc] =
                    __floats2half2_rn(acc[im][in_][2], acc[im][in_][3]);
            }
        }
    } else {
        int z = blockIdx.z;
        float* Cb = (float*)Cv + (long long)(z / NH) * L * D + (z % NH) * HD;
#pragma unroll
        for (int im = 0; im < IM; im++) {
            int r = rbase + im * 16;
#pragma unroll
            for (int in_ = 0; in_ < IN; in_++) {
                int cc = cbase + in_ * 8;
                *(float2*)&Cb[(long long)r * ldc + cc] =
                    make_float2(acc[im][in_][0], acc[im][in_][1]);
                *(float2*)&Cb[(long long)(r + 8) * ldc + cc] =
                    make_float2(acc[im][in_][2], acc[im][in_][3]);
            }
        }
    }
}

// ---------------- 3. split QKV + cosine-normalize + V transpose (+ col zero) ----------------
__global__ void splitnorm_k(const __half* __restrict__ hid, __half* __restrict__ qn,
                            __half* __restrict__ kn, __half* __restrict__ vt,
                            float* __restrict__ col) {
    int bhl = blockIdx.x;
    int dd  = threadIdx.x;
    if (dd == 0 && bhl < BL) col[bhl] = 0.f;
    int b   = bhl / (NH * L);
    int rem = bhl % (NH * L);
    int h   = rem / L;
    int l   = rem % L;
    const __half* base = hid + (long long)(b * L + l) * D3 + h * HD;
    float q  = __half2float(base[dd]);
    float k  = __half2float(base[D + dd]);
    __half vv = base[2 * D + dd];
    __shared__ float sq[64], sk[64];
    sq[dd] = q * q; sk[dd] = k * k;
    __syncthreads();
    for (int o = 32; o; o >>= 1) {
        if (dd < o) { sq[dd] += sq[dd + o]; sk[dd] += sk[dd + o]; }
        __syncthreads();
    }
    float qno = fmaxf(sqrtf(sq[0]), 1e-8f);
    float kno = fmaxf(sqrtf(sk[0]), 1e-8f);
    int z = b * NH + h;
    long long o = ((long long)z * L + l) * HD + dd;
    qn[o] = __float2half_rn(q / qno);
    kn[o] = __float2half_rn(k / kno);
    vt[((long long)z * HD + dd) * L + l] = vv;
}

// ---------------- 4. fused LN(heads) + softmax(j) + colsum, in-place fp16 ----------------
__global__ void __launch_bounds__(256)
lnsm_k(__half* __restrict__ att16, const float* __restrict__ gamma,
       const float* __restrict__ beta, float* __restrict__ col) {
    __shared__ float s[NH][L];
    __shared__ float rinv[NH];
    int b = blockIdx.x / L, i = blockIdx.x % L;
    __half* base16 = att16 + (long long)b * NH * LL + (long long)i * L;
    int tid = threadIdx.x;
    float g[NH], be[NH];
#pragma unroll
    for (int h = 0; h < NH; h++) { g[h] = gamma[h]; be[h] = beta[h]; }

#pragma unroll
    for (int rep = 0; rep < 2; rep++) {
        int j = tid + rep * 256;
        float v[NH]; float mu = 0.f;
#pragma unroll
        for (int h = 0; h < NH; h++) {
            v[h] = __half2float(base16[(long long)h * LL + j]);
            mu += v[h];
        }
        mu *= (1.f / NH);
        float var = 0.f;
#pragma unroll
        for (int h = 0; h < NH; h++) { float d0 = v[h] - mu; var += d0 * d0; }
        float rstd = rsqrtf(var * (1.f / NH) + 1e-5f);
#pragma unroll
        for (int h = 0; h < NH; h++)
            s[h][j] = (v[h] - mu) * rstd * g[h] + be[h];
    }
    __syncthreads();

    int w = tid >> 5, lane = tid & 31;
    for (int h = w; h < NH; h += 8) {
        float m = -1e30f;
#pragma unroll
        for (int q = 0; q < 16; q++) m = fmaxf(m, s[h][q * 32 + lane]);
#pragma unroll
        for (int o = 16; o; o >>= 1) m = fmaxf(m, __shfl_xor_sync(0xffffffffu, m, o));
        float sum = 0.f;
#pragma unroll
        for (int q = 0; q < 16; q++) {
            float e = __expf(s[h][q * 32 + lane] - m);
            s[h][q * 32 + lane] = e;
            sum += e;
        }
#pragma unroll
        for (int o = 16; o; o >>= 1) sum += __shfl_xor_sync(0xffffffffu, sum, o);
        if (lane == 0) rinv[h] = 1.f / sum;
    }
    __syncthreads();

    float inv[NH];
#pragma unroll
    for (int h = 0; h < NH; h++) inv[h] = rinv[h];
#pragma unroll
    for (int rep = 0; rep < 2; rep++) {
        int j = tid + rep * 256;
        float cs = 0.f;
#pragma unroll
        for (int h = 0; h < NH; h++) {
            float e = s[h][j] * inv[h];
            base16[(long long)h * LL + j] = __float2half_rn(e);
            cs += e;
        }
        atomicAdd(&col[b * L + j], cs * (1.f / NH));
    }
}

// ---------------- 5. per-token class probs ----------------
__global__ void probs_k(const float* __restrict__ out, const float* __restrict__ Wout,
                        const float* __restrict__ bout, float* __restrict__ probs) {
    int bl = blockIdx.x;
    int warp = threadIdx.x >> 5, lane = threadIdx.x & 31;
    __shared__ float s[NC];
    __shared__ float mx, sum;
    const float* row = out + (long long)bl * D;
#pragma unroll
    for (int cc = 0; cc < 4; cc++) {
        int c = warp * 4 + cc;
        const float* w = Wout + c * D;
        float acc = 0.f;
        for (int k = lane; k < D; k += 32) acc += row[k] * w[k];
#pragma unroll
        for (int o = 16; o; o >>= 1) acc += __shfl_down_sync(0xffffffffu, acc, o);
        if (lane == 0) s[c] = acc + bout[c];
    }
    __syncthreads();
    if (threadIdx.x == 0) {
        float m = -1e30f;
        for (int c = 0; c < NC; c++) m = fmaxf(m, s[c]);
        float ss = 0.f;
        for (int c = 0; c < NC; c++) ss += __expf(s[c] - m);
        mx = m; sum = ss;
    }
    __syncthreads();
    if (threadIdx.x < NC)
        probs[(long long)bl * NC + threadIdx.x] = __expf(s[threadIdx.x] - mx) / sum;
}

// ---------------- 6. per-batch token weights ----------------
__global__ void weights_k(const int* __restrict__ ids, const float* __restrict__ col,
                          float* __restrict__ wgt) {
    int b = blockIdx.x, l = threadIdx.x;
    float w = (ids[b * L + l] != 0 ? 1.f : 0.f) * col[b * L + l];
    __shared__ float red[512];
    red[l] = w;
    __syncthreads();
    for (int o = 256; o; o >>= 1) { if (l < o) red[l] = fmaxf(red[l], red[l + o]); __syncthreads(); }
    float mxv = red[0];
    __syncthreads();
    float e = __expf(w - mxv);
    red[l] = e;
    __syncthreads();
    for (int o = 256; o; o >>= 1) { if (l < o) red[l] += red[l + o]; __syncthreads(); }
    wgt[b * L + l] = e / red[0];
}

// ---------------- 7. final reduce ----------------
__global__ void final_k(const float* __restrict__ wgt, const float* __restrict__ probs,
                        float* __restrict__ dout, int first) {
    int b = blockIdx.x;
    __shared__ float red[256];
    int tid = threadIdx.x;
    for (int c = 0; c < NC; c++) {
        float s = 0.f;
        for (int l = tid; l < L; l += 256)
            s += wgt[b * L + l] * probs[(long long)(b * L + l) * NC + c];
        red[tid] = s;
        __syncthreads();
        for (int o = 128; o; o >>= 1) { if (tid < o) red[tid] += red[tid + o]; __syncthreads(); }
        if (tid == 0) {
            float v = 0.5f * red[0];
            dout[b * NC + c] = first ? v : dout[b * NC + c] + v;
        }
        __syncthreads();
    }
}

// ---------------- launch ----------------
extern "C" void kernel_launch(void* const* d_in, const int* in_sizes, int n_in,
                              void* d_out, int out_size) {
    (void)in_sizes; (void)n_in; (void)out_size;
    const int*   ids   = (const int*)d_in[0];
    const float* wv    = (const float*)d_in[1];
    const float* emb   = (const float*)d_in[2];
    const float* W_t   = (const float*)d_in[3];
    const float* b_t   = (const float*)d_in[4];
    const float* gam_t = (const float*)d_in[5];
    const float* bet_t = (const float*)d_in[6];
    const float* Wo_t  = (const float*)d_in[7];
    const float* bo_t  = (const float*)d_in[8];
    const float* W_h   = (const float*)d_in[9];
    const float* b_h   = (const float*)d_in[10];
    const float* gam_h = (const float*)d_in[11];
    const float* bet_h = (const float*)d_in[12];
    const float* Wo_h  = (const float*)d_in[13];
    const float* bo_h  = (const float*)d_in[14];
    float* out = (float*)d_out;

    __half *px, *pwt, *pwh, *pwv, *phid, *patt16, *pqn, *pkn, *pvt;
    float *pout, *pprobs, *pcol, *pwgt;
    cudaGetSymbolAddress((void**)&px, g_x);
    cudaGetSymbolAddress((void**)&pwt, g_wt16);
    cudaGetSymbolAddress((void**)&pwh, g_wh16);
    cudaGetSymbolAddress((void**)&pwv, g_wv16);
    cudaGetSymbolAddress((void**)&phid, g_hid);
    cudaGetSymbolAddress((void**)&patt16, g_att16);
    cudaGetSymbolAddress((void**)&pqn, g_qn);
    cudaGetSymbolAddress((void**)&pkn, g_kn);
    cudaGetSymbolAddress((void**)&pvt, g_vt);
    cudaGetSymbolAddress((void**)&pout, g_out);
    cudaGetSymbolAddress((void**)&pprobs, g_probs);
    cudaGetSymbolAddress((void**)&pcol, g_col);
    cudaGetSymbolAddress((void**)&pwgt, g_wgt);

    dim3 proj_grid(D3 / 128, BL / 128, 1);
    dim3 att_grid(L / 128, L / 128, BH);
    dim3 av_grid(1, L / 128, BH);
    const long long sQK = (long long)L * HD;

    // weight / input conversions
    convpad_k<<<D3, 192>>>(W_t, pwt, D, D);
    convpad_k<<<D3, 128>>>(W_h, pwh, 300, KH);
    convpad_k<<<BL, 128>>>(wv, pwv, 300, KH);

    // ===== token branch =====
    embed_leaky_k<<<BL, 192>>>(ids, emb, px);
    h_gemm<128,128,32,64,0><<<proj_grid, 256>>>(px, 0, D, pwt, 0, D, b_t, phid, 0, D3, D);
    splitnorm_k<<<Bsz * NH * L, 64>>>(phid, pqn, pkn, pvt, pcol);
    h_gemm<128,128,32,64,1><<<att_grid, 256>>>(pkn, sQK, HD, pqn, sQK, HD, nullptr,
                                               patt16, (long long)LL, L, HD);
    lnsm_k<<<BL, 256>>>(patt16, gam_t, bet_t, pcol);
    h_gemm<128,64,32,32,2><<<av_grid, 256>>>(patt16, (long long)LL, L, pvt, sQK, L, nullptr,
                                             pout, 0, D, L);
    probs_k<<<BL, 160>>>(pout, Wo_t, bo_t, pprobs);
    weights_k<<<Bsz, 512>>>(ids, pcol, pwgt);
    final_k<<<Bsz, 256>>>(pwgt, pprobs, out, 1);

    // ===== hidden / word-vector branch =====
    h_gemm<128,128,32,64,0><<<proj_grid, 256>>>(pwv, 0, KH, pwh, 0, KH, b_h, phid, 0, D3, KH);
    splitnorm_k<<<Bsz * NH * L, 64>>>(phid, pqn, pkn, pvt, pcol);
    h_gemm<128,128,32,64,1><<<att_grid, 256>>>(pkn, sQK, HD, pqn, sQK, HD, nullptr,
                                               patt16, (long long)LL, L, HD);
    lnsm_k<<<BL, 256>>>(patt16, gam_h, bet_h, pcol);
    h_gemm<128,64,32,32,2><<<av_grid, 256>>>(patt16, (long long)LL, L, pvt, sQK, L, nullptr,
                                             pout, 0, D, L);
    probs_k<<<BL, 160>>>(pout, Wo_h, bo_h, pprobs);
    weights_k<<<Bsz, 512>>>(ids, pcol, pwgt);
    final_k<<<Bsz, 256>>>(pwgt, pprobs, out, 0);
}

// round 6
// speedup vs baseline: 4.3983x; 1.0016x over previous
#include <cuda_runtime.h>
#include <cuda_fp16.h>
#include <math.h>

#define Bsz 16
#define L   512
#define NH  12
#define HD  64
#define D   768
#define D3  2304
#define NC  20
#define BL  (Bsz*L)      // 8192
#define BH  (Bsz*NH)     // 192
#define LL  (L*L)        // 262144
#define KH  320          // padded K for hidden branch (300 -> 320)

// ---------------- scratch (allocation-free) ----------------
__device__ __half g_x[(size_t)BL*D];          // token activations fp16
__device__ __half g_wt16[(size_t)D3*D];       // W_t fp16
__device__ __half g_wh16[(size_t)D3*KH];      // W_h fp16 (padded)
__device__ __half g_wv16[(size_t)BL*KH];      // wv fp16 (padded)
__device__ __half g_hid[(size_t)BL*D3];       // post-linear hiddens fp16
__device__ __half g_att16[(size_t)BH*LL];     // LN'd scores fp16
__device__ __half g_qn[(size_t)BH*L*HD];
__device__ __half g_kn[(size_t)BH*L*HD];
__device__ __half g_vt[(size_t)BH*HD*L];      // V transposed [z][d][l]
__device__ float  g_out[(size_t)BL*D];
__device__ float  g_probs[(size_t)BL*NC];
__device__ float  g_col[BL];
__device__ float  g_wgt[BL];

__device__ __forceinline__ float lrelu(float x) { return x >= 0.f ? x : 0.01f * x; }

__device__ __forceinline__ void mma16(float c[4], const unsigned a[4], const unsigned b[2]) {
    asm volatile(
        "mma.sync.aligned.m16n8k16.row.col.f32.f16.f16.f32 "
        "{%0,%1,%2,%3},{%4,%5,%6,%7},{%8,%9},{%0,%1,%2,%3};"
        : "+f"(c[0]), "+f"(c[1]), "+f"(c[2]), "+f"(c[3])
        : "r"(a[0]), "r"(a[1]), "r"(a[2]), "r"(a[3]), "r"(b[0]), "r"(b[1]));
}
__device__ __forceinline__ unsigned lds_u32(const __half* p) { return *(const unsigned*)p; }
__device__ __forceinline__ void cpasync16(void* smem, const void* gmem) {
    unsigned s = (unsigned)__cvta_generic_to_shared(smem);
    asm volatile("cp.async.cg.shared.global [%0], [%1], 16;\n" :: "r"(s), "l"(gmem));
}
__device__ __forceinline__ void cpcommit() { asm volatile("cp.async.commit_group;\n"); }
__device__ __forceinline__ void cpwait1()  { asm volatile("cp.async.wait_group 1;\n"); }

// ---------------- 0. fp32 -> fp16 (optionally K-padded rows) ----------------
__global__ void convpad_k(const float* __restrict__ src, __half* __restrict__ dst,
                          int K, int KP) {
    long long row = blockIdx.x;
    for (int k4 = threadIdx.x * 4; k4 < KP; k4 += blockDim.x * 4) {
        float4 v = (k4 + 4 <= K) ? *(const float4*)(src + row * K + k4)
                                 : make_float4(k4 < K ? src[row * K + k4] : 0.f,
                                               k4 + 1 < K ? src[row * K + k4 + 1] : 0.f,
                                               k4 + 2 < K ? src[row * K + k4 + 2] : 0.f,
                                               k4 + 3 < K ? src[row * K + k4 + 3] : 0.f);
        *(__half2*)(dst + row * KP + k4)     = __floats2half2_rn(v.x, v.y);
        *(__half2*)(dst + row * KP + k4 + 2) = __floats2half2_rn(v.z, v.w);
    }
}

// ---------------- 1. embedding + leaky -> fp16 ----------------
__global__ void embed_leaky_k(const int* __restrict__ ids, const float* __restrict__ emb,
                              __half* __restrict__ x) {
    int bl = blockIdx.x;
    long long id = ids[bl];
    const float* src = emb + id * D;
    __half* dst = x + (long long)bl * D;
    for (int k4 = threadIdx.x * 4; k4 < D; k4 += blockDim.x * 4) {
        float4 v = *(const float4*)(src + k4);
        *(__half2*)(dst + k4)     = __floats2half2_rn(lrelu(v.x), lrelu(v.y));
        *(__half2*)(dst + k4 + 2) = __floats2half2_rn(lrelu(v.z), lrelu(v.w));
    }
}

// ---------------- 2. projection GEMM: hid = lrelu(A @ W^T + bias), cp.async 3-stage ----------------
template<int BM, int BN, int WM, int WN>
__global__ void __launch_bounds__(256)
h_gemm(const __half* __restrict__ A, int lda,
       const __half* __restrict__ B, int ldb,
       const float* __restrict__ bias,
       __half* __restrict__ C, int ldc, int K) {
    constexpr int BK = 32;
    constexpr int PAD = 8;
    constexpr int STG = 3;
    constexpr int IM = WM / 16;
    constexpr int IN = WN / 8;
    constexpr int WCOLS = BN / WN;
    constexpr int AV = BM * BK / (256 * 8);
    constexpr int BV = BN * BK / (256 * 8);

    __shared__ __align__(16) __half As[STG][BM][BK + PAD];
    __shared__ __align__(16) __half Bs[STG][BN][BK + PAD];

    const int tid = threadIdx.x;
    const int wid = tid >> 5, lane = tid & 31;
    const int g = lane >> 2, tg = lane & 3;
    const int wm = (wid / WCOLS) * WM, wn = (wid % WCOLS) * WN;

    const __half* Ab = A + (long long)blockIdx.y * BM * lda;
    const __half* Bb = B + (long long)blockIdx.x * BN * ldb;

    const int ktiles = K / BK;
    float acc[IM][IN][4] = {};

    auto issue = [&](int t, int s) {
        int k0 = t * BK;
#pragma unroll
        for (int c = 0; c < AV; c++) {
            int idx = tid + c * 256;
            int row = idx >> 2, cq = idx & 3;
            cpasync16(&As[s][row][cq * 8], Ab + (long long)row * lda + k0 + cq * 8);
        }
#pragma unroll
        for (int c = 0; c < BV; c++) {
            int idx = tid + c * 256;
            int row = idx >> 2, cq = idx & 3;
            cpasync16(&Bs[s][row][cq * 8], Bb + (long long)row * ldb + k0 + cq * 8);
        }
    };

    issue(0, 0); cpcommit();
    if (ktiles > 1) issue(1, 1);
    cpcommit();
    cpwait1();
    __syncthreads();

    int rs = 0;
    for (int t = 0; t < ktiles; t++) {
#pragma unroll
        for (int kk = 0; kk < BK; kk += 16) {
            unsigned a[IM][4], b[IN][2];
#pragma unroll
            for (int im = 0; im < IM; im++) {
                int r = wm + im * 16 + g;
                a[im][0] = lds_u32(&As[rs][r][kk + tg * 2]);
                a[im][1] = lds_u32(&As[rs][r + 8][kk + tg * 2]);
                a[im][2] = lds_u32(&As[rs][r][kk + tg * 2 + 8]);
                a[im][3] = lds_u32(&As[rs][r + 8][kk + tg * 2 + 8]);
            }
#pragma unroll
            for (int in_ = 0; in_ < IN; in_++) {
                int r = wn + in_ * 8 + g;
                b[in_][0] = lds_u32(&Bs[rs][r][kk + tg * 2]);
                b[in_][1] = lds_u32(&Bs[rs][r][kk + tg * 2 + 8]);
            }
#pragma unroll
            for (int im = 0; im < IM; im++)
#pragma unroll
                for (int in_ = 0; in_ < IN; in_++)
                    mma16(acc[im][in_], a[im], b[in_]);
        }
        if (t + 2 < ktiles) issue(t + 2, (rs + 2) % STG);
        cpcommit();
        cpwait1();
        __syncthreads();
        rs = (rs + 1) % STG;
    }

    const int rbase = blockIdx.y * BM + wm + g;
    const int cbase = blockIdx.x * BN + wn + tg * 2;
#pragma unroll
    for (int im = 0; im < IM; im++) {
        int r = rbase + im * 16;
#pragma unroll
        for (int in_ = 0; in_ < IN; in_++) {
            int cc = cbase + in_ * 8;
            float b0 = bias[cc], b1 = bias[cc + 1];
            *(__half2*)&C[(long long)r * ldc + cc] =
                __floats2half2_rn(lrelu(acc[im][in_][0] + b0), lrelu(acc[im][in_][1] + b1));
            *(__half2*)&C[(long long)(r + 8) * ldc + cc] =
                __floats2half2_rn(lrelu(acc[im][in_][2] + b0), lrelu(acc[im][in_][3] + b1));
        }
    }
}

// ---------------- 3. split QKV + cosine-normalize + V transpose (+ col zero) ----------------
__global__ void splitnorm_k(const __half* __restrict__ hid, __half* __restrict__ qn,
                            __half* __restrict__ kn, __half* __restrict__ vt,
                            float* __restrict__ col) {
    int bhl = blockIdx.x;
    int dd  = threadIdx.x;
    if (dd == 0 && bhl < BL) col[bhl] = 0.f;
    int b   = bhl / (NH * L);
    int rem = bhl % (NH * L);
    int h   = rem / L;
    int l   = rem % L;
    const __half* base = hid + (long long)(b * L + l) * D3 + h * HD;
    float q  = __half2float(base[dd]);
    float k  = __half2float(base[D + dd]);
    __half vv = base[2 * D + dd];
    __shared__ float sq[64], sk[64];
    sq[dd] = q * q; sk[dd] = k * k;
    __syncthreads();
    for (int o = 32; o; o >>= 1) {
        if (dd < o) { sq[dd] += sq[dd + o]; sk[dd] += sk[dd + o]; }
        __syncthreads();
    }
    float qno = fmaxf(sqrtf(sq[0]), 1e-8f);
    float kno = fmaxf(sqrtf(sk[0]), 1e-8f);
    int z = b * NH + h;
    long long o = ((long long)z * L + l) * HD + dd;
    qn[o] = __float2half_rn(q / qno);
    kn[o] = __float2half_rn(k / kno);
    vt[((long long)z * HD + dd) * L + l] = vv;
}

// ---------------- 4. fused scores + LayerNorm(heads) ----------------
// block = (b, 64-row I-tile, 32-col J-tile); computes all 12 heads' 64x32 score
// tiles (raw fp16 in smem), then LN across heads, writes LN'd att fp16.
#define ATTLN_SMEM (2*64*72*2 + 2*32*72*2 + NH*64*40*2)   // 89088
__global__ void __launch_bounds__(256)
attln_k(const __half* __restrict__ kn, const __half* __restrict__ qn,
        __half* __restrict__ att, const float* __restrict__ gamma,
        const float* __restrict__ beta) {
    extern __shared__ __align__(16) char smem_raw[];
    __half (*kbuf)[64][72] = (__half(*)[64][72])smem_raw;
    __half (*qbuf)[32][72] = (__half(*)[32][72])(smem_raw + 2*64*72*2);
    __half (*accS)[64][40] = (__half(*)[64][40])(smem_raw + 2*64*72*2 + 2*32*72*2);

    const int tid = threadIdx.x;
    const int wid = tid >> 5, lane = tid & 31;
    const int g = lane >> 2, tg = lane & 3;
    const int wm = (wid >> 1) * 16, wn = (wid & 1) * 16;
    const int J0 = blockIdx.x * 32, I0 = blockIdx.y * 64, b = blockIdx.z;

    const __half* kb = kn + ((long long)b * NH * L + I0) * HD;
    const __half* qb = qn + ((long long)b * NH * L + J0) * HD;

#define ISSUE(h, s)                                                              \
    {                                                                            \
        long long hoff = (long long)(h) * L * HD;                                \
        _Pragma("unroll")                                                        \
        for (int c = 0; c < 2; c++) {                                            \
            int idx = tid + c * 256;                                             \
            int r = idx >> 3, jc = idx & 7;                                      \
            cpasync16(&kbuf[s][r][jc * 8], kb + hoff + (long long)r * HD + jc * 8); \
        }                                                                        \
        { int r = tid >> 3, jc = tid & 7;                                        \
          cpasync16(&qbuf[s][r][jc * 8], qb + hoff + (long long)r * HD + jc * 8); } \
    }

    ISSUE(0, 0); cpcommit();
    for (int h = 0; h < NH; h++) {
        if (h + 1 < NH) ISSUE(h + 1, (h + 1) & 1);
        cpcommit();
        cpwait1();
        __syncthreads();
        int s = h & 1;
        float acc[2][4] = {};
#pragma unroll
        for (int kk = 0; kk < 64; kk += 16) {
            unsigned a[4];
            a[0] = lds_u32(&kbuf[s][wm + g][kk + tg * 2]);
            a[1] = lds_u32(&kbuf[s][wm + g + 8][kk + tg * 2]);
            a[2] = lds_u32(&kbuf[s][wm + g][kk + tg * 2 + 8]);
            a[3] = lds_u32(&kbuf[s][wm + g + 8][kk + tg * 2 + 8]);
#pragma unroll
            for (int in_ = 0; in_ < 2; in_++) {
                unsigned bb[2];
                bb[0] = lds_u32(&qbuf[s][wn + in_ * 8 + g][kk + tg * 2]);
                bb[1] = lds_u32(&qbuf[s][wn + in_ * 8 + g][kk + tg * 2 + 8]);
                mma16(acc[in_], a, bb);
            }
        }
#pragma unroll
        for (int in_ = 0; in_ < 2; in_++) {
            int c = wn + in_ * 8 + tg * 2;
            *(__half2*)&accS[h][wm + g][c]     = __floats2half2_rn(acc[in_][0], acc[in_][1]);
            *(__half2*)&accS[h][wm + g + 8][c] = __floats2half2_rn(acc[in_][2], acc[in_][3]);
        }
        __syncthreads();
    }
#undef ISSUE

    float gm[NH], be[NH];
#pragma unroll
    for (int h = 0; h < NH; h++) { gm[h] = gamma[h]; be[h] = beta[h]; }
    __half* ob = att + (long long)b * NH * LL + (long long)I0 * L + J0;
#pragma unroll
    for (int rep = 0; rep < 8; rep++) {
        int p = tid + rep * 256;
        int i = p >> 5, j = p & 31;
        float v[NH], mu = 0.f;
#pragma unroll
        for (int h = 0; h < NH; h++) { v[h] = __half2float(accS[h][i][j]); mu += v[h]; }
        mu *= (1.f / NH);
        float var = 0.f;
#pragma unroll
        for (int h = 0; h < NH; h++) { float d0 = v[h] - mu; var += d0 * d0; }
        float rstd = rsqrtf(var * (1.f / NH) + 1e-5f);
#pragma unroll
        for (int h = 0; h < NH; h++)
            ob[(long long)h * LL + (long long)i * L + j] =
                __float2half_rn((v[h] - mu) * rstd * gm[h] + be[h]);
    }
}

// ---------------- 5. fused softmax + colsum + att@V ----------------
// block = (64-row i-tile, z). Loads 64 full LN'd rows, softmaxes them in smem,
// adds colsum partials, then HMMAs against V tiles.
#define SMATTV_SMEM (64*520*2 + 2*64*72*2)   // 84992
__global__ void __launch_bounds__(256)
smattv_k(const __half* __restrict__ att, const __half* __restrict__ vt,
         float* __restrict__ out, float* __restrict__ col) {
    extern __shared__ __align__(16) char smem_raw[];
    __half (*satt)[520] = (__half(*)[520])smem_raw;
    __half (*vbuf)[64][72] = (__half(*)[64][72])(smem_raw + 64*520*2);

    const int tid = threadIdx.x;
    const int wid = tid >> 5, lane = tid & 31;
    const int g = lane >> 2, tg = lane & 3;
    const int wm = (wid >> 1) * 16, wn = (wid & 1) * 32;
    const int I0 = blockIdx.x * 64;
    const int z = blockIdx.y;
    const int b = z / NH, h = z % NH;

    const __half* abase = att + (long long)z * LL + (long long)I0 * L;
    const __half* vbase = vt + (long long)z * HD * L;

#pragma unroll
    for (int c = 0; c < 16; c++) {
        int idx = tid + c * 256;
        int r = idx >> 6, jc = idx & 63;
        cpasync16(&satt[r][jc * 8], abase + (long long)r * L + jc * 8);
    }
    cpcommit();

#define ISSUEV(kt, s)                                                            \
    {                                                                            \
        _Pragma("unroll")                                                        \
        for (int c = 0; c < 2; c++) {                                            \
            int idx = tid + c * 256;                                             \
            int r = idx >> 3, jc = idx & 7;                                      \
            cpasync16(&vbuf[s][r][jc * 8], vbase + (long long)r * L + (kt) * 64 + jc * 8); \
        }                                                                        \
    }
    ISSUEV(0, 0); cpcommit();
    cpwait1();
    __syncthreads();

    // softmax: one warp per row, 8 rows per warp
    for (int k = 0; k < 8; k++) {
        int r = wid * 8 + k;
        float v[16];
        float m = -1e30f;
#pragma unroll
        for (int q = 0; q < 8; q++) {
            float2 f = __half22float2(*(__half2*)&satt[r][lane * 2 + q * 64]);
            v[2 * q] = f.x; v[2 * q + 1] = f.y;
            m = fmaxf(m, fmaxf(f.x, f.y));
        }
#pragma unroll
        for (int o = 16; o; o >>= 1) m = fmaxf(m, __shfl_xor_sync(0xffffffffu, m, o));
        float s = 0.f;
#pragma unroll
        for (int q = 0; q < 16; q++) { v[q] = __expf(v[q] - m); s += v[q]; }
#pragma unroll
        for (int o = 16; o; o >>= 1) s += __shfl_xor_sync(0xffffffffu, s, o);
        float inv = 1.f / s;
#pragma unroll
        for (int q = 0; q < 8; q++)
            *(__half2*)&satt[r][lane * 2 + q * 64] =
                __floats2half2_rn(v[2 * q] * inv, v[2 * q + 1] * inv);
    }
    __syncthreads();

    // colsum partials (2 cols per thread)
    {
        int j = tid * 2;
        float c0 = 0.f, c1 = 0.f;
#pragma unroll 8
        for (int r = 0; r < 64; r++) {
            float2 f = __half22float2(*(__half2*)&satt[r][j]);
            c0 += f.x; c1 += f.y;
        }
        atomicAdd(&col[b * L + j], c0 * (1.f / NH));
        atomicAdd(&col[b * L + j + 1], c1 * (1.f / NH));
    }

    // att @ V
    float acc[4][4] = {};
    int rs = 0;
    for (int kt = 0; kt < 8; kt++) {
        if (kt + 1 < 8) ISSUEV(kt + 1, rs ^ 1);
        cpcommit();
        cpwait1();
        __syncthreads();
#pragma unroll
        for (int kk = 0; kk < 64; kk += 16) {
            unsigned a[4];
            int kc = kt * 64 + kk + tg * 2;
            a[0] = lds_u32(&satt[wm + g][kc]);
            a[1] = lds_u32(&satt[wm + g + 8][kc]);
            a[2] = lds_u32(&satt[wm + g][kc + 8]);
            a[3] = lds_u32(&satt[wm + g + 8][kc + 8]);
#pragma unroll
            for (int in_ = 0; in_ < 4; in_++) {
                unsigned bb[2];
                bb[0] = lds_u32(&vbuf[rs][wn + in_ * 8 + g][kk + tg * 2]);
                bb[1] = lds_u32(&vbuf[rs][wn + in_ * 8 + g][kk + tg * 2 + 8]);
                mma16(acc[in_], a, bb);
            }
        }
        rs ^= 1;
        __syncthreads();
    }
#undef ISSUEV

    float* ob = out + ((long long)b * L + I0) * D + h * HD;
#pragma unroll
    for (int in_ = 0; in_ < 4; in_++) {
        int c = wn + in_ * 8 + tg * 2;
        *(float2*)&ob[(long long)(wm + g) * D + c] = make_float2(acc[in_][0], acc[in_][1]);
        *(float2*)&ob[(long long)(wm + g + 8) * D + c] = make_float2(acc[in_][2], acc[in_][3]);
    }
}

// ---------------- 6. per-token class probs ----------------
__global__ void probs_k(const float* __restrict__ out, const float* __restrict__ Wout,
                        const float* __restrict__ bout, float* __restrict__ probs) {
    int bl = blockIdx.x;
    int warp = threadIdx.x >> 5, lane = threadIdx.x & 31;
    __shared__ float s[NC];
    __shared__ float mx, sum;
    const float* row = out + (long long)bl * D;
#pragma unroll
    for (int cc = 0; cc < 4; cc++) {
        int c = warp * 4 + cc;
        const float* w = Wout + c * D;
        float acc = 0.f;
        for (int k = lane; k < D; k += 32) acc += row[k] * w[k];
#pragma unroll
        for (int o = 16; o; o >>= 1) acc += __shfl_down_sync(0xffffffffu, acc, o);
        if (lane == 0) s[c] = acc + bout[c];
    }
    __syncthreads();
    if (threadIdx.x == 0) {
        float m = -1e30f;
        for (int c = 0; c < NC; c++) m = fmaxf(m, s[c]);
        float ss = 0.f;
        for (int c = 0; c < NC; c++) ss += __expf(s[c] - m);
        mx = m; sum = ss;
    }
    __syncthreads();
    if (threadIdx.x < NC)
        probs[(long long)bl * NC + threadIdx.x] = __expf(s[threadIdx.x] - mx) / sum;
}

// ---------------- 7. per-batch token weights ----------------
__global__ void weights_k(const int* __restrict__ ids, const float* __restrict__ col,
                          float* __restrict__ wgt) {
    int b = blockIdx.x, l = threadIdx.x;
    float w = (ids[b * L + l] != 0 ? 1.f : 0.f) * col[b * L + l];
    __shared__ float red[512];
    red[l] = w;
    __syncthreads();
    for (int o = 256; o; o >>= 1) { if (l < o) red[l] = fmaxf(red[l], red[l + o]); __syncthreads(); }
    float mxv = red[0];
    __syncthreads();
    float e = __expf(w - mxv);
    red[l] = e;
    __syncthreads();
    for (int o = 256; o; o >>= 1) { if (l < o) red[l] += red[l + o]; __syncthreads(); }
    wgt[b * L + l] = e / red[0];
}

// ---------------- 8. final reduce ----------------
__global__ void final_k(const float* __restrict__ wgt, const float* __restrict__ probs,
                        float* __restrict__ dout, int first) {
    int b = blockIdx.x;
    __shared__ float red[256];
    int tid = threadIdx.x;
    for (int c = 0; c < NC; c++) {
        float s = 0.f;
        for (int l = tid; l < L; l += 256)
            s += wgt[b * L + l] * probs[(long long)(b * L + l) * NC + c];
        red[tid] = s;
        __syncthreads();
        for (int o = 128; o; o >>= 1) { if (tid < o) red[tid] += red[tid + o]; __syncthreads(); }
        if (tid == 0) {
            float v = 0.5f * red[0];
            dout[b * NC + c] = first ? v : dout[b * NC + c] + v;
        }
        __syncthreads();
    }
}

// ---------------- launch ----------------
extern "C" void kernel_launch(void* const* d_in, const int* in_sizes, int n_in,
                              void* d_out, int out_size) {
    (void)in_sizes; (void)n_in; (void)out_size;
    const int*   ids   = (const int*)d_in[0];
    const float* wv    = (const float*)d_in[1];
    const float* emb   = (const float*)d_in[2];
    const float* W_t   = (const float*)d_in[3];
    const float* b_t   = (const float*)d_in[4];
    const float* gam_t = (const float*)d_in[5];
    const float* bet_t = (const float*)d_in[6];
    const float* Wo_t  = (const float*)d_in[7];
    const float* bo_t  = (const float*)d_in[8];
    const float* W_h   = (const float*)d_in[9];
    const float* b_h   = (const float*)d_in[10];
    const float* gam_h = (const float*)d_in[11];
    const float* bet_h = (const float*)d_in[12];
    const float* Wo_h  = (const float*)d_in[13];
    const float* bo_h  = (const float*)d_in[14];
    float* out = (float*)d_out;

    __half *px, *pwt, *pwh, *pwv, *phid, *patt16, *pqn, *pkn, *pvt;
    float *pout, *pprobs, *pcol, *pwgt;
    cudaGetSymbolAddress((void**)&px, g_x);
    cudaGetSymbolAddress((void**)&pwt, g_wt16);
    cudaGetSymbolAddress((void**)&pwh, g_wh16);
    cudaGetSymbolAddress((void**)&pwv, g_wv16);
    cudaGetSymbolAddress((void**)&phid, g_hid);
    cudaGetSymbolAddress((void**)&patt16, g_att16);
    cudaGetSymbolAddress((void**)&pqn, g_qn);
    cudaGetSymbolAddress((void**)&pkn, g_kn);
    cudaGetSymbolAddress((void**)&pvt, g_vt);
    cudaGetSymbolAddress((void**)&pout, g_out);
    cudaGetSymbolAddress((void**)&pprobs, g_probs);
    cudaGetSymbolAddress((void**)&pcol, g_col);
    cudaGetSymbolAddress((void**)&pwgt, g_wgt);

    cudaFuncSetAttribute(attln_k, cudaFuncAttributeMaxDynamicSharedMemorySize, ATTLN_SMEM);
    cudaFuncSetAttribute(smattv_k, cudaFuncAttributeMaxDynamicSharedMemorySize, SMATTV_SMEM);

    dim3 proj_grid(D3 / 128, BL / 128);
    dim3 attln_grid(L / 32, L / 64, Bsz);   // 16 x 8 x 16
    dim3 smattv_grid(L / 64, BH);           // 8 x 192

    // weight / input conversions
    convpad_k<<<D3, 192>>>(W_t, pwt, D, D);
    convpad_k<<<D3, 128>>>(W_h, pwh, 300, KH);
    convpad_k<<<BL, 128>>>(wv, pwv, 300, KH);

    // ===== token branch =====
    embed_leaky_k<<<BL, 192>>>(ids, emb, px);
    h_gemm<128,128,32,64><<<proj_grid, 256>>>(px, D, pwt, D, b_t, phid, D3, D);
    splitnorm_k<<<Bsz * NH * L, 64>>>(phid, pqn, pkn, pvt, pcol);
    attln_k<<<attln_grid, 256, ATTLN_SMEM>>>(pkn, pqn, patt16, gam_t, bet_t);
    smattv_k<<<smattv_grid, 256, SMATTV_SMEM>>>(patt16, pvt, pout, pcol);
    probs_k<<<BL, 160>>>(pout, Wo_t, bo_t, pprobs);
    weights_k<<<Bsz, 512>>>(ids, pcol, pwgt);
    final_k<<<Bsz, 256>>>(pwgt, pprobs, out, 1);

    // ===== hidden / word-vector branch =====
    h_gemm<128,128,32,64><<<proj_grid, 256>>>(pwv, KH, pwh, KH, b_h, phid, D3, KH);
    splitnorm_k<<<Bsz * NH * L, 64>>>(phid, pqn, pkn, pvt, pcol);
    attln_k<<<attln_grid, 256, ATTLN_SMEM>>>(pkn, pqn, patt16, gam_h, bet_h);
    smattv_k<<<smattv_grid, 256, SMATTV_SMEM>>>(patt16, pvt, pout, pcol);
    probs_k<<<BL, 160>>>(pout, Wo_h, bo_h, pprobs);
    weights_k<<<Bsz, 512>>>(ids, pcol, pwgt);
    final_k<<<Bsz, 256>>>(pwgt, pprobs, out, 0);
}

// round 7
// speedup vs baseline: 4.7104x; 1.0710x over previous
#include <cuda_runtime.h>
#include <cuda_fp16.h>
#include <math.h>

#define Bsz 16
#define L   512
#define NH  12
#define HD  64
#define D   768
#define D3  2304
#define NC  20
#define BL  (Bsz*L)      // 8192
#define BH  (Bsz*NH)     // 192
#define LL  (L*L)        // 262144
#define KH  320          // padded K for hidden branch (300 -> 320)

// ---------------- scratch (allocation-free) ----------------
// token branch
__device__ __half g_x[(size_t)BL*D];
__device__ __half g_wt16[(size_t)D3*D];
__device__ __half g_hid[(size_t)BL*D3];
__device__ __half g_att16[(size_t)BH*LL];
__device__ __half g_qn[(size_t)BH*L*HD];
__device__ __half g_kn[(size_t)BH*L*HD];
__device__ __half g_vt[(size_t)BH*HD*L];
__device__ float  g_out[(size_t)BL*D];
__device__ float  g_probs[(size_t)BL*NC];
__device__ float  g_col[BL];
__device__ float  g_wgt[BL];
// hidden branch (independent copies so both branches can run concurrently)
__device__ __half g_wh16[(size_t)D3*KH];
__device__ __half g_wv16[(size_t)BL*KH];
__device__ __half g_hid2[(size_t)BL*D3];
__device__ __half g_att16_2[(size_t)BH*LL];
__device__ __half g_qn2[(size_t)BH*L*HD];
__device__ __half g_kn2[(size_t)BH*L*HD];
__device__ __half g_vt2[(size_t)BH*HD*L];
__device__ float  g_out2[(size_t)BL*D];
__device__ float  g_probs2[(size_t)BL*NC];
__device__ float  g_col2[BL];
__device__ float  g_wgt2[BL];

__device__ __forceinline__ float lrelu(float x) { return x >= 0.f ? x : 0.01f * x; }

__device__ __forceinline__ void mma16(float c[4], const unsigned a[4], const unsigned b[2]) {
    asm volatile(
        "mma.sync.aligned.m16n8k16.row.col.f32.f16.f16.f32 "
        "{%0,%1,%2,%3},{%4,%5,%6,%7},{%8,%9},{%0,%1,%2,%3};"
        : "+f"(c[0]), "+f"(c[1]), "+f"(c[2]), "+f"(c[3])
        : "r"(a[0]), "r"(a[1]), "r"(a[2]), "r"(a[3]), "r"(b[0]), "r"(b[1]));
}
__device__ __forceinline__ unsigned lds_u32(const __half* p) { return *(const unsigned*)p; }
__device__ __forceinline__ void cpasync16(void* smem, const void* gmem) {
    unsigned s = (unsigned)__cvta_generic_to_shared(smem);
    asm volatile("cp.async.cg.shared.global [%0], [%1], 16;\n" :: "r"(s), "l"(gmem));
}
__device__ __forceinline__ void cpcommit() { asm volatile("cp.async.commit_group;\n"); }
__device__ __forceinline__ void cpwait1()  { asm volatile("cp.async.wait_group 1;\n"); }

// ---------------- 0. fp32 -> fp16 (optionally K-padded rows) ----------------
__global__ void convpad_k(const float* __restrict__ src, __half* __restrict__ dst,
                          int K, int KP) {
    long long row = blockIdx.x;
    for (int k4 = threadIdx.x * 4; k4 < KP; k4 += blockDim.x * 4) {
        float4 v = (k4 + 4 <= K) ? *(const float4*)(src + row * K + k4)
                                 : make_float4(k4 < K ? src[row * K + k4] : 0.f,
                                               k4 + 1 < K ? src[row * K + k4 + 1] : 0.f,
                                               k4 + 2 < K ? src[row * K + k4 + 2] : 0.f,
                                               k4 + 3 < K ? src[row * K + k4 + 3] : 0.f);
        *(__half2*)(dst + row * KP + k4)     = __floats2half2_rn(v.x, v.y);
        *(__half2*)(dst + row * KP + k4 + 2) = __floats2half2_rn(v.z, v.w);
    }
}

// ---------------- 1. embedding + leaky -> fp16 ----------------
__global__ void embed_leaky_k(const int* __restrict__ ids, const float* __restrict__ emb,
                              __half* __restrict__ x) {
    int bl = blockIdx.x;
    long long id = ids[bl];
    const float* src = emb + id * D;
    __half* dst = x + (long long)bl * D;
    for (int k4 = threadIdx.x * 4; k4 < D; k4 += blockDim.x * 4) {
        float4 v = *(const float4*)(src + k4);
        *(__half2*)(dst + k4)     = __floats2half2_rn(lrelu(v.x), lrelu(v.y));
        *(__half2*)(dst + k4 + 2) = __floats2half2_rn(lrelu(v.z), lrelu(v.w));
    }
}

// ---------------- 2. projection GEMM: hid = lrelu(A @ W^T + bias), cp.async 3-stage ----------------
template<int BM, int BN, int WM, int WN>
__global__ void __launch_bounds__(256)
h_gemm(const __half* __restrict__ A, int lda,
       const __half* __restrict__ B, int ldb,
       const float* __restrict__ bias,
       __half* __restrict__ C, int ldc, int K) {
    constexpr int BK = 32;
    constexpr int PAD = 8;
    constexpr int STG = 3;
    constexpr int IM = WM / 16;
    constexpr int IN = WN / 8;
    constexpr int WCOLS = BN / WN;
    constexpr int AV = BM * BK / (256 * 8);
    constexpr int BV = BN * BK / (256 * 8);

    __shared__ __align__(16) __half As[STG][BM][BK + PAD];
    __shared__ __align__(16) __half Bs[STG][BN][BK + PAD];

    const int tid = threadIdx.x;
    const int wid = tid >> 5, lane = tid & 31;
    const int g = lane >> 2, tg = lane & 3;
    const int wm = (wid / WCOLS) * WM, wn = (wid % WCOLS) * WN;

    const __half* Ab = A + (long long)blockIdx.y * BM * lda;
    const __half* Bb = B + (long long)blockIdx.x * BN * ldb;

    const int ktiles = K / BK;
    float acc[IM][IN][4] = {};

    auto issue = [&](int t, int s) {
        int k0 = t * BK;
#pragma unroll
        for (int c = 0; c < AV; c++) {
            int idx = tid + c * 256;
            int row = idx >> 2, cq = idx & 3;
            cpasync16(&As[s][row][cq * 8], Ab + (long long)row * lda + k0 + cq * 8);
        }
#pragma unroll
        for (int c = 0; c < BV; c++) {
            int idx = tid + c * 256;
            int row = idx >> 2, cq = idx & 3;
            cpasync16(&Bs[s][row][cq * 8], Bb + (long long)row * ldb + k0 + cq * 8);
        }
    };

    issue(0, 0); cpcommit();
    if (ktiles > 1) issue(1, 1);
    cpcommit();
    cpwait1();
    __syncthreads();

    int rs = 0;
    for (int t = 0; t < ktiles; t++) {
#pragma unroll
        for (int kk = 0; kk < BK; kk += 16) {
            unsigned a[IM][4], b[IN][2];
#pragma unroll
            for (int im = 0; im < IM; im++) {
                int r = wm + im * 16 + g;
                a[im][0] = lds_u32(&As[rs][r][kk + tg * 2]);
                a[im][1] = lds_u32(&As[rs][r + 8][kk + tg * 2]);
                a[im][2] = lds_u32(&As[rs][r][kk + tg * 2 + 8]);
                a[im][3] = lds_u32(&As[rs][r + 8][kk + tg * 2 + 8]);
            }
#pragma unroll
            for (int in_ = 0; in_ < IN; in_++) {
                int r = wn + in_ * 8 + g;
                b[in_][0] = lds_u32(&Bs[rs][r][kk + tg * 2]);
                b[in_][1] = lds_u32(&Bs[rs][r][kk + tg * 2 + 8]);
            }
#pragma unroll
            for (int im = 0; im < IM; im++)
#pragma unroll
                for (int in_ = 0; in_ < IN; in_++)
                    mma16(acc[im][in_], a[im], b[in_]);
        }
        if (t + 2 < ktiles) issue(t + 2, (rs + 2) % STG);
        cpcommit();
        cpwait1();
        __syncthreads();
        rs = (rs + 1) % STG;
    }

    const int rbase = blockIdx.y * BM + wm + g;
    const int cbase = blockIdx.x * BN + wn + tg * 2;
#pragma unroll
    for (int im = 0; im < IM; im++) {
        int r = rbase + im * 16;
#pragma unroll
        for (int in_ = 0; in_ < IN; in_++) {
            int cc = cbase + in_ * 8;
            float b0 = bias[cc], b1 = bias[cc + 1];
            *(__half2*)&C[(long long)r * ldc + cc] =
                __floats2half2_rn(lrelu(acc[im][in_][0] + b0), lrelu(acc[im][in_][1] + b1));
            *(__half2*)&C[(long long)(r + 8) * ldc + cc] =
                __floats2half2_rn(lrelu(acc[im][in_][2] + b0), lrelu(acc[im][in_][3] + b1));
        }
    }
}

// ---------------- 3. split QKV + cosine-normalize + V transpose (+ col zero) ----------------
__global__ void splitnorm_k(const __half* __restrict__ hid, __half* __restrict__ qn,
                            __half* __restrict__ kn, __half* __restrict__ vt,
                            float* __restrict__ col) {
    int bhl = blockIdx.x;
    int dd  = threadIdx.x;
    if (dd == 0 && bhl < BL) col[bhl] = 0.f;
    int b   = bhl / (NH * L);
    int rem = bhl % (NH * L);
    int h   = rem / L;
    int l   = rem % L;
    const __half* base = hid + (long long)(b * L + l) * D3 + h * HD;
    float q  = __half2float(base[dd]);
    float k  = __half2float(base[D + dd]);
    __half vv = base[2 * D + dd];
    __shared__ float sq[64], sk[64];
    sq[dd] = q * q; sk[dd] = k * k;
    __syncthreads();
    for (int o = 32; o; o >>= 1) {
        if (dd < o) { sq[dd] += sq[dd + o]; sk[dd] += sk[dd + o]; }
        __syncthreads();
    }
    float qno = fmaxf(sqrtf(sq[0]), 1e-8f);
    float kno = fmaxf(sqrtf(sk[0]), 1e-8f);
    int z = b * NH + h;
    long long o = ((long long)z * L + l) * HD + dd;
    qn[o] = __float2half_rn(q / qno);
    kn[o] = __float2half_rn(k / kno);
    vt[((long long)z * HD + dd) * L + l] = vv;
}

// ---------------- 4. fused scores + LayerNorm(heads) ----------------
#define ATTLN_SMEM (2*64*72*2 + 2*32*72*2 + NH*64*40*2)   // 89088
__global__ void __launch_bounds__(256)
attln_k(const __half* __restrict__ kn, const __half* __restrict__ qn,
        __half* __restrict__ att, const float* __restrict__ gamma,
        const float* __restrict__ beta) {
    extern __shared__ __align__(16) char smem_raw[];
    __half (*kbuf)[64][72] = (__half(*)[64][72])smem_raw;
    __half (*qbuf)[32][72] = (__half(*)[32][72])(smem_raw + 2*64*72*2);
    __half (*accS)[64][40] = (__half(*)[64][40])(smem_raw + 2*64*72*2 + 2*32*72*2);

    const int tid = threadIdx.x;
    const int wid = tid >> 5, lane = tid & 31;
    const int g = lane >> 2, tg = lane & 3;
    const int wm = (wid >> 1) * 16, wn = (wid & 1) * 16;
    const int J0 = blockIdx.x * 32, I0 = blockIdx.y * 64, b = blockIdx.z;

    const __half* kb = kn + ((long long)b * NH * L + I0) * HD;
    const __half* qb = qn + ((long long)b * NH * L + J0) * HD;

#define ISSUE(h, s)                                                              \
    {                                                                            \
        long long hoff = (long long)(h) * L * HD;                                \
        _Pragma("unroll")                                                        \
        for (int c = 0; c < 2; c++) {                                            \
            int idx = tid + c * 256;                                             \
            int r = idx >> 3, jc = idx & 7;                                      \
            cpasync16(&kbuf[s][r][jc * 8], kb + hoff + (long long)r * HD + jc * 8); \
        }                                                                        \
        { int r = tid >> 3, jc = tid & 7;                                        \
          cpasync16(&qbuf[s][r][jc * 8], qb + hoff + (long long)r * HD + jc * 8); } \
    }

    ISSUE(0, 0); cpcommit();
    for (int h = 0; h < NH; h++) {
        if (h + 1 < NH) ISSUE(h + 1, (h + 1) & 1);
        cpcommit();
        cpwait1();
        __syncthreads();
        int s = h & 1;
        float acc[2][4] = {};
#pragma unroll
        for (int kk = 0; kk < 64; kk += 16) {
            unsigned a[4];
            a[0] = lds_u32(&kbuf[s][wm + g][kk + tg * 2]);
            a[1] = lds_u32(&kbuf[s][wm + g + 8][kk + tg * 2]);
            a[2] = lds_u32(&kbuf[s][wm + g][kk + tg * 2 + 8]);
            a[3] = lds_u32(&kbuf[s][wm + g + 8][kk + tg * 2 + 8]);
#pragma unroll
            for (int in_ = 0; in_ < 2; in_++) {
                unsigned bb[2];
                bb[0] = lds_u32(&qbuf[s][wn + in_ * 8 + g][kk + tg * 2]);
                bb[1] = lds_u32(&qbuf[s][wn + in_ * 8 + g][kk + tg * 2 + 8]);
                mma16(acc[in_], a, bb);
            }
        }
#pragma unroll
        for (int in_ = 0; in_ < 2; in_++) {
            int c = wn + in_ * 8 + tg * 2;
            *(__half2*)&accS[h][wm + g][c]     = __floats2half2_rn(acc[in_][0], acc[in_][1]);
            *(__half2*)&accS[h][wm + g + 8][c] = __floats2half2_rn(acc[in_][2], acc[in_][3]);
        }
        __syncthreads();
    }
#undef ISSUE

    float gm[NH], be[NH];
#pragma unroll
    for (int h = 0; h < NH; h++) { gm[h] = gamma[h]; be[h] = beta[h]; }
    __half* ob = att + (long long)b * NH * LL + (long long)I0 * L + J0;
#pragma unroll
    for (int rep = 0; rep < 8; rep++) {
        int p = tid + rep * 256;
        int i = p >> 5, j = p & 31;
        float v[NH], mu = 0.f;
#pragma unroll
        for (int h = 0; h < NH; h++) { v[h] = __half2float(accS[h][i][j]); mu += v[h]; }
        mu *= (1.f / NH);
        float var = 0.f;
#pragma unroll
        for (int h = 0; h < NH; h++) { float d0 = v[h] - mu; var += d0 * d0; }
        float rstd = rsqrtf(var * (1.f / NH) + 1e-5f);
#pragma unroll
        for (int h = 0; h < NH; h++)
            ob[(long long)h * LL + (long long)i * L + j] =
                __float2half_rn((v[h] - mu) * rstd * gm[h] + be[h]);
    }
}

// ---------------- 5. fused softmax + colsum + att@V ----------------
#define SMATTV_SMEM (64*520*2 + 2*64*72*2)   // 84992
__global__ void __launch_bounds__(256)
smattv_k(const __half* __restrict__ att, const __half* __restrict__ vt,
         float* __restrict__ out, float* __restrict__ col) {
    extern __shared__ __align__(16) char smem_raw[];
    __half (*satt)[520] = (__half(*)[520])smem_raw;
    __half (*vbuf)[64][72] = (__half(*)[64][72])(smem_raw + 64*520*2);

    const int tid = threadIdx.x;
    const int wid = tid >> 5, lane = tid & 31;
    const int g = lane >> 2, tg = lane & 3;
    const int wm = (wid >> 1) * 16, wn = (wid & 1) * 32;
    const int I0 = blockIdx.x * 64;
    const int z = blockIdx.y;
    const int b = z / NH, h = z % NH;

    const __half* abase = att + (long long)z * LL + (long long)I0 * L;
    const __half* vbase = vt + (long long)z * HD * L;

#pragma unroll
    for (int c = 0; c < 16; c++) {
        int idx = tid + c * 256;
        int r = idx >> 6, jc = idx & 63;
        cpasync16(&satt[r][jc * 8], abase + (long long)r * L + jc * 8);
    }
    cpcommit();

#define ISSUEV(kt, s)                                                            \
    {                                                                            \
        _Pragma("unroll")                                                        \
        for (int c = 0; c < 2; c++) {                                            \
            int idx = tid + c * 256;                                             \
            int r = idx >> 3, jc = idx & 7;                                      \
            cpasync16(&vbuf[s][r][jc * 8], vbase + (long long)r * L + (kt) * 64 + jc * 8); \
        }                                                                        \
    }
    ISSUEV(0, 0); cpcommit();
    cpwait1();
    __syncthreads();

    for (int k = 0; k < 8; k++) {
        int r = wid * 8 + k;
        float v[16];
        float m = -1e30f;
#pragma unroll
        for (int q = 0; q < 8; q++) {
            float2 f = __half22float2(*(__half2*)&satt[r][lane * 2 + q * 64]);
            v[2 * q] = f.x; v[2 * q + 1] = f.y;
            m = fmaxf(m, fmaxf(f.x, f.y));
        }
#pragma unroll
        for (int o = 16; o; o >>= 1) m = fmaxf(m, __shfl_xor_sync(0xffffffffu, m, o));
        float s = 0.f;
#pragma unroll
        for (int q = 0; q < 16; q++) { v[q] = __expf(v[q] - m); s += v[q]; }
#pragma unroll
        for (int o = 16; o; o >>= 1) s += __shfl_xor_sync(0xffffffffu, s, o);
        float inv = 1.f / s;
#pragma unroll
        for (int q = 0; q < 8; q++)
            *(__half2*)&satt[r][lane * 2 + q * 64] =
                __floats2half2_rn(v[2 * q] * inv, v[2 * q + 1] * inv);
    }
    __syncthreads();

    {
        int j = tid * 2;
        float c0 = 0.f, c1 = 0.f;
#pragma unroll 8
        for (int r = 0; r < 64; r++) {
            float2 f = __half22float2(*(__half2*)&satt[r][j]);
            c0 += f.x; c1 += f.y;
        }
        atomicAdd(&col[b * L + j], c0 * (1.f / NH));
        atomicAdd(&col[b * L + j + 1], c1 * (1.f / NH));
    }

    float acc[4][4] = {};
    int rs = 0;
    for (int kt = 0; kt < 8; kt++) {
        if (kt + 1 < 8) ISSUEV(kt + 1, rs ^ 1);
        cpcommit();
        cpwait1();
        __syncthreads();
#pragma unroll
        for (int kk = 0; kk < 64; kk += 16) {
            unsigned a[4];
            int kc = kt * 64 + kk + tg * 2;
            a[0] = lds_u32(&satt[wm + g][kc]);
            a[1] = lds_u32(&satt[wm + g + 8][kc]);
            a[2] = lds_u32(&satt[wm + g][kc + 8]);
            a[3] = lds_u32(&satt[wm + g + 8][kc + 8]);
#pragma unroll
            for (int in_ = 0; in_ < 4; in_++) {
                unsigned bb[2];
                bb[0] = lds_u32(&vbuf[rs][wn + in_ * 8 + g][kk + tg * 2]);
                bb[1] = lds_u32(&vbuf[rs][wn + in_ * 8 + g][kk + tg * 2 + 8]);
                mma16(acc[in_], a, bb);
            }
        }
        rs ^= 1;
        __syncthreads();
    }
#undef ISSUEV

    float* ob = out + ((long long)b * L + I0) * D + h * HD;
#pragma unroll
    for (int in_ = 0; in_ < 4; in_++) {
        int c = wn + in_ * 8 + tg * 2;
        *(float2*)&ob[(long long)(wm + g) * D + c] = make_float2(acc[in_][0], acc[in_][1]);
        *(float2*)&ob[(long long)(wm + g + 8) * D + c] = make_float2(acc[in_][2], acc[in_][3]);
    }
}

// ---------------- 6. per-token class probs ----------------
__global__ void probs_k(const float* __restrict__ out, const float* __restrict__ Wout,
                        const float* __restrict__ bout, float* __restrict__ probs) {
    int bl = blockIdx.x;
    int warp = threadIdx.x >> 5, lane = threadIdx.x & 31;
    __shared__ float s[NC];
    __shared__ float mx, sum;
    const float* row = out + (long long)bl * D;
#pragma unroll
    for (int cc = 0; cc < 4; cc++) {
        int c = warp * 4 + cc;
        const float* w = Wout + c * D;
        float acc = 0.f;
        for (int k = lane; k < D; k += 32) acc += row[k] * w[k];
#pragma unroll
        for (int o = 16; o; o >>= 1) acc += __shfl_down_sync(0xffffffffu, acc, o);
        if (lane == 0) s[c] = acc + bout[c];
    }
    __syncthreads();
    if (threadIdx.x == 0) {
        float m = -1e30f;
        for (int c = 0; c < NC; c++) m = fmaxf(m, s[c]);
        float ss = 0.f;
        for (int c = 0; c < NC; c++) ss += __expf(s[c] - m);
        mx = m; sum = ss;
    }
    __syncthreads();
    if (threadIdx.x < NC)
        probs[(long long)bl * NC + threadIdx.x] = __expf(s[threadIdx.x] - mx) / sum;
}

// ---------------- 7. per-batch token weights ----------------
__global__ void weights_k(const int* __restrict__ ids, const float* __restrict__ col,
                          float* __restrict__ wgt) {
    int b = blockIdx.x, l = threadIdx.x;
    float w = (ids[b * L + l] != 0 ? 1.f : 0.f) * col[b * L + l];
    __shared__ float red[512];
    red[l] = w;
    __syncthreads();
    for (int o = 256; o; o >>= 1) { if (l < o) red[l] = fmaxf(red[l], red[l + o]); __syncthreads(); }
    float mxv = red[0];
    __syncthreads();
    float e = __expf(w - mxv);
    red[l] = e;
    __syncthreads();
    for (int o = 256; o; o >>= 1) { if (l < o) red[l] += red[l + o]; __syncthreads(); }
    wgt[b * L + l] = e / red[0];
}

// ---------------- 8. final reduce ----------------
__global__ void final_k(const float* __restrict__ wgt, const float* __restrict__ probs,
                        float* __restrict__ dout, int first) {
    int b = blockIdx.x;
    __shared__ float red[256];
    int tid = threadIdx.x;
    for (int c = 0; c < NC; c++) {
        float s = 0.f;
        for (int l = tid; l < L; l += 256)
            s += wgt[b * L + l] * probs[(long long)(b * L + l) * NC + c];
        red[tid] = s;
        __syncthreads();
        for (int o = 128; o; o >>= 1) { if (tid < o) red[tid] += red[tid + o]; __syncthreads(); }
        if (tid == 0) {
            float v = 0.5f * red[0];
            dout[b * NC + c] = first ? v : dout[b * NC + c] + v;
        }
        __syncthreads();
    }
}

// ---------------- launch ----------------
extern "C" void kernel_launch(void* const* d_in, const int* in_sizes, int n_in,
                              void* d_out, int out_size) {
    (void)in_sizes; (void)n_in; (void)out_size;
    const int*   ids   = (const int*)d_in[0];
    const float* wv    = (const float*)d_in[1];
    const float* emb   = (const float*)d_in[2];
    const float* W_t   = (const float*)d_in[3];
    const float* b_t   = (const float*)d_in[4];
    const float* gam_t = (const float*)d_in[5];
    const float* bet_t = (const float*)d_in[6];
    const float* Wo_t  = (const float*)d_in[7];
    const float* bo_t  = (const float*)d_in[8];
    const float* W_h   = (const float*)d_in[9];
    const float* b_h   = (const float*)d_in[10];
    const float* gam_h = (const float*)d_in[11];
    const float* bet_h = (const float*)d_in[12];
    const float* Wo_h  = (const float*)d_in[13];
    const float* bo_h  = (const float*)d_in[14];
    float* out = (float*)d_out;

    __half *px, *pwt, *pwh, *pwv, *phid, *patt16, *pqn, *pkn, *pvt;
    __half *phid2, *patt16_2, *pqn2, *pkn2, *pvt2;
    float *pout, *pprobs, *pcol, *pwgt;
    float *pout2, *pprobs2, *pcol2, *pwgt2;
    cudaGetSymbolAddress((void**)&px, g_x);
    cudaGetSymbolAddress((void**)&pwt, g_wt16);
    cudaGetSymbolAddress((void**)&pwh, g_wh16);
    cudaGetSymbolAddress((void**)&pwv, g_wv16);
    cudaGetSymbolAddress((void**)&phid, g_hid);
    cudaGetSymbolAddress((void**)&patt16, g_att16);
    cudaGetSymbolAddress((void**)&pqn, g_qn);
    cudaGetSymbolAddress((void**)&pkn, g_kn);
    cudaGetSymbolAddress((void**)&pvt, g_vt);
    cudaGetSymbolAddress((void**)&pout, g_out);
    cudaGetSymbolAddress((void**)&pprobs, g_probs);
    cudaGetSymbolAddress((void**)&pcol, g_col);
    cudaGetSymbolAddress((void**)&pwgt, g_wgt);
    cudaGetSymbolAddress((void**)&phid2, g_hid2);
    cudaGetSymbolAddress((void**)&patt16_2, g_att16_2);
    cudaGetSymbolAddress((void**)&pqn2, g_qn2);
    cudaGetSymbolAddress((void**)&pkn2, g_kn2);
    cudaGetSymbolAddress((void**)&pvt2, g_vt2);
    cudaGetSymbolAddress((void**)&pout2, g_out2);
    cudaGetSymbolAddress((void**)&pprobs2, g_probs2);
    cudaGetSymbolAddress((void**)&pcol2, g_col2);
    cudaGetSymbolAddress((void**)&pwgt2, g_wgt2);

    cudaFuncSetAttribute(attln_k, cudaFuncAttributeMaxDynamicSharedMemorySize, ATTLN_SMEM);
    cudaFuncSetAttribute(smattv_k, cudaFuncAttributeMaxDynamicSharedMemorySize, SMATTV_SMEM);

    dim3 proj_grid(D3 / 128, BL / 128);
    dim3 attln_grid(L / 32, L / 64, Bsz);
    dim3 smattv_grid(L / 64, BH);

    // Fork a second stream for the independent hidden branch. Created fresh per
    // call and intentionally NOT destroyed: destroying a stream/event that
    // participated in an ongoing capture invalidates the graph, and
    // kernel_launch only runs a bounded number of times (correctness + capture).
    // No device memory is allocated by stream/event creation.
    cudaStream_t s2;
    cudaStreamCreateWithFlags(&s2, cudaStreamNonBlocking);
    cudaEvent_t evFork, evJoin;
    cudaEventCreateWithFlags(&evFork, cudaEventDisableTiming);
    cudaEventCreateWithFlags(&evJoin, cudaEventDisableTiming);

    cudaEventRecord(evFork, 0);
    cudaStreamWaitEvent(s2, evFork, 0);

    // ===== token branch (main stream) =====
    embed_leaky_k<<<BL, 192>>>(ids, emb, px);
    convpad_k<<<D3, 192>>>(W_t, pwt, D, D);
    h_gemm<128,128,32,64><<<proj_grid, 256>>>(px, D, pwt, D, b_t, phid, D3, D);
    splitnorm_k<<<Bsz * NH * L, 64>>>(phid, pqn, pkn, pvt, pcol);
    attln_k<<<attln_grid, 256, ATTLN_SMEM>>>(pkn, pqn, patt16, gam_t, bet_t);
    smattv_k<<<smattv_grid, 256, SMATTV_SMEM>>>(patt16, pvt, pout, pcol);
    probs_k<<<BL, 160>>>(pout, Wo_t, bo_t, pprobs);
    weights_k<<<Bsz, 512>>>(ids, pcol, pwgt);
    final_k<<<Bsz, 256>>>(pwgt, pprobs, out, 1);

    // ===== hidden / word-vector branch (stream s2) =====
    convpad_k<<<D3, 128, 0, s2>>>(W_h, pwh, 300, KH);
    convpad_k<<<BL, 128, 0, s2>>>(wv, pwv, 300, KH);
    h_gemm<128,128,32,64><<<proj_grid, 256, 0, s2>>>(pwv, KH, pwh, KH, b_h, phid2, D3, KH);
    splitnorm_k<<<Bsz * NH * L, 64, 0, s2>>>(phid2, pqn2, pkn2, pvt2, pcol2);
    attln_k<<<attln_grid, 256, ATTLN_SMEM, s2>>>(pkn2, pqn2, patt16_2, gam_h, bet_h);
    smattv_k<<<smattv_grid, 256, SMATTV_SMEM, s2>>>(patt16_2, pvt2, pout2, pcol2);
    probs_k<<<BL, 160, 0, s2>>>(pout2, Wo_h, bo_h, pprobs2);
    weights_k<<<Bsz, 512, 0, s2>>>(ids, pcol2, pwgt2);

    // join: hidden-branch results folded into d_out on the main stream
    cudaEventRecord(evJoin, s2);
    cudaStreamWaitEvent(0, evJoin, 0);
    final_k<<<Bsz, 256>>>(pwgt2, pprobs2, out, 0);
}

// round 8
// speedup vs baseline: 5.6611x; 1.2018x over previous
#include <cuda_runtime.h>
#include <cuda_fp16.h>
#include <math.h>

#define Bsz 16
#define L   512
#define NH  12
#define HD  64
#define D   768
#define D3  2304
#define NC  20
#define BL  (Bsz*L)      // 8192
#define BH  (Bsz*NH)     // 192
#define LL  (L*L)        // 262144
#define KH  320          // padded K for hidden branch (300 -> 320)

// ---------------- scratch (allocation-free) ----------------
// token branch
__device__ __half g_x[(size_t)BL*D];
__device__ __half g_wt16[(size_t)D3*D];
__device__ __half g_hid[(size_t)BL*D3];
__device__ __half g_att16[(size_t)BH*LL];
__device__ __half g_qn[(size_t)BH*L*HD];
__device__ __half g_kn[(size_t)BH*L*HD];
__device__ __half g_vt[(size_t)BH*HD*L];
__device__ float  g_out[(size_t)BL*D];
__device__ float  g_probs[(size_t)BL*NC];
__device__ float  g_col[BL];
__device__ float  g_wgt[BL];
// hidden branch (independent copies so both branches can run concurrently)
__device__ __half g_wh16[(size_t)D3*KH];
__device__ __half g_wv16[(size_t)BL*KH];
__device__ __half g_hid2[(size_t)BL*D3];
__device__ __half g_att16_2[(size_t)BH*LL];
__device__ __half g_qn2[(size_t)BH*L*HD];
__device__ __half g_kn2[(size_t)BH*L*HD];
__device__ __half g_vt2[(size_t)BH*HD*L];
__device__ float  g_out2[(size_t)BL*D];
__device__ float  g_probs2[(size_t)BL*NC];
__device__ float  g_col2[BL];
__device__ float  g_wgt2[BL];

__device__ __forceinline__ float lrelu(float x) { return x >= 0.f ? x : 0.01f * x; }

__device__ __forceinline__ void mma16(float c[4], const unsigned a[4], const unsigned b[2]) {
    asm volatile(
        "mma.sync.aligned.m16n8k16.row.col.f32.f16.f16.f32 "
        "{%0,%1,%2,%3},{%4,%5,%6,%7},{%8,%9},{%0,%1,%2,%3};"
        : "+f"(c[0]), "+f"(c[1]), "+f"(c[2]), "+f"(c[3])
        : "r"(a[0]), "r"(a[1]), "r"(a[2]), "r"(a[3]), "r"(b[0]), "r"(b[1]));
}
__device__ __forceinline__ unsigned lds_u32(const __half* p) { return *(const unsigned*)p; }
__device__ __forceinline__ void cpasync16(void* smem, const void* gmem) {
    unsigned s = (unsigned)__cvta_generic_to_shared(smem);
    asm volatile("cp.async.cg.shared.global [%0], [%1], 16;\n" :: "r"(s), "l"(gmem));
}
__device__ __forceinline__ void cpcommit() { asm volatile("cp.async.commit_group;\n"); }
__device__ __forceinline__ void cpwait1()  { asm volatile("cp.async.wait_group 1;\n"); }

// ---------------- 0. fp32 -> fp16 (optionally K-padded rows) ----------------
__global__ void convpad_k(const float* __restrict__ src, __half* __restrict__ dst,
                          int K, int KP) {
    long long row = blockIdx.x;
    for (int k4 = threadIdx.x * 4; k4 < KP; k4 += blockDim.x * 4) {
        float4 v = (k4 + 4 <= K) ? *(const float4*)(src + row * K + k4)
                                 : make_float4(k4 < K ? src[row * K + k4] : 0.f,
                                               k4 + 1 < K ? src[row * K + k4 + 1] : 0.f,
                                               k4 + 2 < K ? src[row * K + k4 + 2] : 0.f,
                                               k4 + 3 < K ? src[row * K + k4 + 3] : 0.f);
        *(__half2*)(dst + row * KP + k4)     = __floats2half2_rn(v.x, v.y);
        *(__half2*)(dst + row * KP + k4 + 2) = __floats2half2_rn(v.z, v.w);
    }
}

// ---------------- 1. embedding + leaky -> fp16 ----------------
__global__ void embed_leaky_k(const int* __restrict__ ids, const float* __restrict__ emb,
                              __half* __restrict__ x) {
    int bl = blockIdx.x;
    long long id = ids[bl];
    const float* src = emb + id * D;
    __half* dst = x + (long long)bl * D;
    for (int k4 = threadIdx.x * 4; k4 < D; k4 += blockDim.x * 4) {
        float4 v = *(const float4*)(src + k4);
        *(__half2*)(dst + k4)     = __floats2half2_rn(lrelu(v.x), lrelu(v.y));
        *(__half2*)(dst + k4 + 2) = __floats2half2_rn(lrelu(v.z), lrelu(v.w));
    }
}

// ---------------- 2. projection GEMM: hid = lrelu(A @ W^T + bias), cp.async 3-stage ----------------
template<int BM, int BN, int WM, int WN>
__global__ void __launch_bounds__(256)
h_gemm(const __half* __restrict__ A, int lda,
       const __half* __restrict__ B, int ldb,
       const float* __restrict__ bias,
       __half* __restrict__ C, int ldc, int K) {
    constexpr int BK = 32;
    constexpr int PAD = 8;
    constexpr int STG = 3;
    constexpr int IM = WM / 16;
    constexpr int IN = WN / 8;
    constexpr int WCOLS = BN / WN;
    constexpr int AV = BM * BK / (256 * 8);
    constexpr int BV = BN * BK / (256 * 8);

    __shared__ __align__(16) __half As[STG][BM][BK + PAD];
    __shared__ __align__(16) __half Bs[STG][BN][BK + PAD];

    const int tid = threadIdx.x;
    const int wid = tid >> 5, lane = tid & 31;
    const int g = lane >> 2, tg = lane & 3;
    const int wm = (wid / WCOLS) * WM, wn = (wid % WCOLS) * WN;

    const __half* Ab = A + (long long)blockIdx.y * BM * lda;
    const __half* Bb = B + (long long)blockIdx.x * BN * ldb;

    const int ktiles = K / BK;
    float acc[IM][IN][4] = {};

    auto issue = [&](int t, int s) {
        int k0 = t * BK;
#pragma unroll
        for (int c = 0; c < AV; c++) {
            int idx = tid + c * 256;
            int row = idx >> 2, cq = idx & 3;
            cpasync16(&As[s][row][cq * 8], Ab + (long long)row * lda + k0 + cq * 8);
        }
#pragma unroll
        for (int c = 0; c < BV; c++) {
            int idx = tid + c * 256;
            int row = idx >> 2, cq = idx & 3;
            cpasync16(&Bs[s][row][cq * 8], Bb + (long long)row * ldb + k0 + cq * 8);
        }
    };

    issue(0, 0); cpcommit();
    if (ktiles > 1) issue(1, 1);
    cpcommit();
    cpwait1();
    __syncthreads();

    int rs = 0;
    for (int t = 0; t < ktiles; t++) {
#pragma unroll
        for (int kk = 0; kk < BK; kk += 16) {
            unsigned a[IM][4], b[IN][2];
#pragma unroll
            for (int im = 0; im < IM; im++) {
                int r = wm + im * 16 + g;
                a[im][0] = lds_u32(&As[rs][r][kk + tg * 2]);
                a[im][1] = lds_u32(&As[rs][r + 8][kk + tg * 2]);
                a[im][2] = lds_u32(&As[rs][r][kk + tg * 2 + 8]);
                a[im][3] = lds_u32(&As[rs][r + 8][kk + tg * 2 + 8]);
            }
#pragma unroll
            for (int in_ = 0; in_ < IN; in_++) {
                int r = wn + in_ * 8 + g;
                b[in_][0] = lds_u32(&Bs[rs][r][kk + tg * 2]);
                b[in_][1] = lds_u32(&Bs[rs][r][kk + tg * 2 + 8]);
            }
#pragma unroll
            for (int im = 0; im < IM; im++)
#pragma unroll
                for (int in_ = 0; in_ < IN; in_++)
                    mma16(acc[im][in_], a[im], b[in_]);
        }
        if (t + 2 < ktiles) issue(t + 2, (rs + 2) % STG);
        cpcommit();
        cpwait1();
        __syncthreads();
        rs = (rs + 1) % STG;
    }

    const int rbase = blockIdx.y * BM + wm + g;
    const int cbase = blockIdx.x * BN + wn + tg * 2;
#pragma unroll
    for (int im = 0; im < IM; im++) {
        int r = rbase + im * 16;
#pragma unroll
        for (int in_ = 0; in_ < IN; in_++) {
            int cc = cbase + in_ * 8;
            float b0 = bias[cc], b1 = bias[cc + 1];
            *(__half2*)&C[(long long)r * ldc + cc] =
                __floats2half2_rn(lrelu(acc[im][in_][0] + b0), lrelu(acc[im][in_][1] + b1));
            *(__half2*)&C[(long long)(r + 8) * ldc + cc] =
                __floats2half2_rn(lrelu(acc[im][in_][2] + b0), lrelu(acc[im][in_][3] + b1));
        }
    }
}

// ---------------- 3. splitnorm v2: coalesced, warp-shuffle norms, smem V transpose ----------------
// block = (64-token tile, z); 256 threads.
__global__ void __launch_bounds__(256)
splitnorm2_k(const __half* __restrict__ hid, __half* __restrict__ qn,
             __half* __restrict__ kn, __half* __restrict__ vt,
             float* __restrict__ col) {
    __shared__ __half sv[64][72];
    const int z = blockIdx.y, b = z / NH, h = z % NH;
    const int l0 = blockIdx.x * 64;
    const int tid = threadIdx.x, wid = tid >> 5, lane = tid & 31;

    if (h == 0 && tid < 64) col[b * L + l0 + tid] = 0.f;

    // V tile load: sv[l][d]
#pragma unroll
    for (int c = 0; c < 2; c++) {
        int idx = tid + c * 256;          // 0..511
        int l = idx >> 3, dc = (idx & 7) * 8;
        uint4 v = *(const uint4*)(hid + (long long)(b * L + l0 + l) * D3 + 2 * D + h * HD + dc);
        *(uint4*)&sv[l][dc] = v;
    }

    // Q/K cosine-normalize: warp wid handles tokens l0+wid*8 .. +7
#pragma unroll
    for (int i = 0; i < 8; i++) {
        int l = l0 + wid * 8 + i;
        const __half* rowb = hid + (long long)(b * L + l) * D3 + h * HD;
        float2 fq = __half22float2(*(const __half2*)(rowb + lane * 2));
        float2 fk = __half22float2(*(const __half2*)(rowb + D + lane * 2));
        float sq = fq.x * fq.x + fq.y * fq.y;
        float sk = fk.x * fk.x + fk.y * fk.y;
#pragma unroll
        for (int o = 16; o; o >>= 1) {
            sq += __shfl_xor_sync(0xffffffffu, sq, o);
            sk += __shfl_xor_sync(0xffffffffu, sk, o);
        }
        float rq = 1.f / fmaxf(sqrtf(sq), 1e-8f);
        float rk = 1.f / fmaxf(sqrtf(sk), 1e-8f);
        long long ob = ((long long)z * L + l) * HD + lane * 2;
        *(__half2*)(qn + ob) = __floats2half2_rn(fq.x * rq, fq.y * rq);
        *(__half2*)(kn + ob) = __floats2half2_rn(fk.x * rk, fk.y * rk);
    }
    __syncthreads();

    // V transpose write: vt[z][d][l], 16B coalesced rows
#pragma unroll
    for (int c = 0; c < 2; c++) {
        int idx = tid + c * 256;
        int d = idx >> 3, lc = (idx & 7) * 8;
        __half tmp[8];
#pragma unroll
        for (int i = 0; i < 8; i++) tmp[i] = sv[lc + i][d];
        *(uint4*)(vt + ((long long)z * HD + d) * L + l0 + lc) = *(uint4*)tmp;
    }
}

// ---------------- 4. fused scores + LayerNorm(heads), LN in registers ----------------
__global__ void __launch_bounds__(256)
attln2_k(const __half* __restrict__ kn, const __half* __restrict__ qn,
         __half* __restrict__ att, const float* __restrict__ gamma,
         const float* __restrict__ beta) {
    __shared__ __align__(16) __half kbuf[2][64][72];
    __shared__ __align__(16) __half qbuf[2][32][72];

    const int tid = threadIdx.x;
    const int wid = tid >> 5, lane = tid & 31;
    const int g = lane >> 2, tg = lane & 3;
    const int wm = (wid >> 1) * 16, wn = (wid & 1) * 16;
    const int J0 = blockIdx.x * 32, I0 = blockIdx.y * 64, b = blockIdx.z;

    const __half* kb = kn + ((long long)b * NH * L + I0) * HD;
    const __half* qb = qn + ((long long)b * NH * L + J0) * HD;

    // sc[h][p]: p0 = (row wm+g, in_0), p1 = (row wm+g+8, in_0),
    //           p2 = (row wm+g, in_1), p3 = (row wm+g+8, in_1); each half2 = 2 cols
    __half2 sc[NH][4];

#define ISSUE(h, s)                                                              \
    {                                                                            \
        long long hoff = (long long)(h) * L * HD;                                \
        _Pragma("unroll")                                                        \
        for (int c = 0; c < 2; c++) {                                            \
            int idx = tid + c * 256;                                             \
            int r = idx >> 3, jc = idx & 7;                                      \
            cpasync16(&kbuf[s][r][jc * 8], kb + hoff + (long long)r * HD + jc * 8); \
        }                                                                        \
        { int r = tid >> 3, jc = tid & 7;                                        \
          cpasync16(&qbuf[s][r][jc * 8], qb + hoff + (long long)r * HD + jc * 8); } \
    }

    ISSUE(0, 0); cpcommit();
#pragma unroll
    for (int h = 0; h < NH; h++) {
        if (h + 1 < NH) ISSUE(h + 1, (h + 1) & 1);
        cpcommit();
        cpwait1();
        __syncthreads();
        int s = h & 1;
        float acc[2][4] = {};
#pragma unroll
        for (int kk = 0; kk < 64; kk += 16) {
            unsigned a[4];
            a[0] = lds_u32(&kbuf[s][wm + g][kk + tg * 2]);
            a[1] = lds_u32(&kbuf[s][wm + g + 8][kk + tg * 2]);
            a[2] = lds_u32(&kbuf[s][wm + g][kk + tg * 2 + 8]);
            a[3] = lds_u32(&kbuf[s][wm + g + 8][kk + tg * 2 + 8]);
#pragma unroll
            for (int in_ = 0; in_ < 2; in_++) {
                unsigned bb[2];
                bb[0] = lds_u32(&qbuf[s][wn + in_ * 8 + g][kk + tg * 2]);
                bb[1] = lds_u32(&qbuf[s][wn + in_ * 8 + g][kk + tg * 2 + 8]);
                mma16(acc[in_], a, bb);
            }
        }
        sc[h][0] = __floats2half2_rn(acc[0][0], acc[0][1]);
        sc[h][1] = __floats2half2_rn(acc[0][2], acc[0][3]);
        sc[h][2] = __floats2half2_rn(acc[1][0], acc[1][1]);
        sc[h][3] = __floats2half2_rn(acc[1][2], acc[1][3]);
        __syncthreads();   // all MMA reads of buf s done before it is re-issued
    }
#undef ISSUE

    float gm[NH], be[NH];
#pragma unroll
    for (int h = 0; h < NH; h++) { gm[h] = gamma[h]; be[h] = beta[h]; }

    __half* ob = att + (long long)b * NH * LL + (long long)I0 * L + J0;
#pragma unroll
    for (int p = 0; p < 4; p++) {
        int i = wm + g + ((p & 1) ? 8 : 0);
        int j = wn + ((p >> 1) ? 8 : 0) + tg * 2;
        float vx[NH], vy[NH];
        float mux = 0.f, muy = 0.f;
#pragma unroll
        for (int h = 0; h < NH; h++) {
            float2 f = __half22float2(sc[h][p]);
            vx[h] = f.x; vy[h] = f.y; mux += f.x; muy += f.y;
        }
        mux *= (1.f / NH); muy *= (1.f / NH);
        float varx = 0.f, vary = 0.f;
#pragma unroll
        for (int h = 0; h < NH; h++) {
            float dx = vx[h] - mux, dy = vy[h] - muy;
            varx += dx * dx; vary += dy * dy;
        }
        float rsx = rsqrtf(varx * (1.f / NH) + 1e-5f);
        float rsy = rsqrtf(vary * (1.f / NH) + 1e-5f);
#pragma unroll
        for (int h = 0; h < NH; h++) {
            *(__half2*)&ob[(long long)h * LL + (long long)i * L + j] =
                __floats2half2_rn((vx[h] - mux) * rsx * gm[h] + be[h],
                                  (vy[h] - muy) * rsy * gm[h] + be[h]);
        }
    }
}

// ---------------- 5. fused softmax + colsum + att@V ----------------
#define SMATTV_SMEM (64*520*2 + 2*64*72*2)   // 84992
__global__ void __launch_bounds__(256)
smattv_k(const __half* __restrict__ att, const __half* __restrict__ vt,
         float* __restrict__ out, float* __restrict__ col) {
    extern __shared__ __align__(16) char smem_raw[];
    __half (*satt)[520] = (__half(*)[520])smem_raw;
    __half (*vbuf)[64][72] = (__half(*)[64][72])(smem_raw + 64*520*2);

    const int tid = threadIdx.x;
    const int wid = tid >> 5, lane = tid & 31;
    const int g = lane >> 2, tg = lane & 3;
    const int wm = (wid >> 1) * 16, wn = (wid & 1) * 32;
    const int I0 = blockIdx.x * 64;
    const int z = blockIdx.y;
    const int b = z / NH, h = z % NH;

    const __half* abase = att + (long long)z * LL + (long long)I0 * L;
    const __half* vbase = vt + (long long)z * HD * L;

#pragma unroll
    for (int c = 0; c < 16; c++) {
        int idx = tid + c * 256;
        int r = idx >> 6, jc = idx & 63;
        cpasync16(&satt[r][jc * 8], abase + (long long)r * L + jc * 8);
    }
    cpcommit();

#define ISSUEV(kt, s)                                                            \
    {                                                                            \
        _Pragma("unroll")                                                        \
        for (int c = 0; c < 2; c++) {                                            \
            int idx = tid + c * 256;                                             \
            int r = idx >> 3, jc = idx & 7;                                      \
            cpasync16(&vbuf[s][r][jc * 8], vbase + (long long)r * L + (kt) * 64 + jc * 8); \
        }                                                                        \
    }
    ISSUEV(0, 0); cpcommit();
    cpwait1();
    __syncthreads();

    for (int k = 0; k < 8; k++) {
        int r = wid * 8 + k;
        float v[16];
        float m = -1e30f;
#pragma unroll
        for (int q = 0; q < 8; q++) {
            float2 f = __half22float2(*(__half2*)&satt[r][lane * 2 + q * 64]);
            v[2 * q] = f.x; v[2 * q + 1] = f.y;
            m = fmaxf(m, fmaxf(f.x, f.y));
        }
#pragma unroll
        for (int o = 16; o; o >>= 1) m = fmaxf(m, __shfl_xor_sync(0xffffffffu, m, o));
        float s = 0.f;
#pragma unroll
        for (int q = 0; q < 16; q++) { v[q] = __expf(v[q] - m); s += v[q]; }
#pragma unroll
        for (int o = 16; o; o >>= 1) s += __shfl_xor_sync(0xffffffffu, s, o);
        float inv = 1.f / s;
#pragma unroll
        for (int q = 0; q < 8; q++)
            *(__half2*)&satt[r][lane * 2 + q * 64] =
                __floats2half2_rn(v[2 * q] * inv, v[2 * q + 1] * inv);
    }
    __syncthreads();

    {
        int j = tid * 2;
        float c0 = 0.f, c1 = 0.f;
#pragma unroll 8
        for (int r = 0; r < 64; r++) {
            float2 f = __half22float2(*(__half2*)&satt[r][j]);
            c0 += f.x; c1 += f.y;
        }
        atomicAdd(&col[b * L + j], c0 * (1.f / NH));
        atomicAdd(&col[b * L + j + 1], c1 * (1.f / NH));
    }

    float acc[4][4] = {};
    int rs = 0;
    for (int kt = 0; kt < 8; kt++) {
        if (kt + 1 < 8) ISSUEV(kt + 1, rs ^ 1);
        cpcommit();
        cpwait1();
        __syncthreads();
#pragma unroll
        for (int kk = 0; kk < 64; kk += 16) {
            unsigned a[4];
            int kc = kt * 64 + kk + tg * 2;
            a[0] = lds_u32(&satt[wm + g][kc]);
            a[1] = lds_u32(&satt[wm + g + 8][kc]);
            a[2] = lds_u32(&satt[wm + g][kc + 8]);
            a[3] = lds_u32(&satt[wm + g + 8][kc + 8]);
#pragma unroll
            for (int in_ = 0; in_ < 4; in_++) {
                unsigned bb[2];
                bb[0] = lds_u32(&vbuf[rs][wn + in_ * 8 + g][kk + tg * 2]);
                bb[1] = lds_u32(&vbuf[rs][wn + in_ * 8 + g][kk + tg * 2 + 8]);
                mma16(acc[in_], a, bb);
            }
        }
        rs ^= 1;
        __syncthreads();
    }
#undef ISSUEV

    float* ob = out + ((long long)b * L + I0) * D + h * HD;
#pragma unroll
    for (int in_ = 0; in_ < 4; in_++) {
        int c = wn + in_ * 8 + tg * 2;
        *(float2*)&ob[(long long)(wm + g) * D + c] = make_float2(acc[in_][0], acc[in_][1]);
        *(float2*)&ob[(long long)(wm + g + 8) * D + c] = make_float2(acc[in_][2], acc[in_][3]);
    }
}

// ---------------- 6. per-token class probs ----------------
__global__ void probs_k(const float* __restrict__ out, const float* __restrict__ Wout,
                        const float* __restrict__ bout, float* __restrict__ probs) {
    int bl = blockIdx.x;
    int warp = threadIdx.x >> 5, lane = threadIdx.x & 31;
    __shared__ float s[NC];
    __shared__ float mx, sum;
    const float* row = out + (long long)bl * D;
#pragma unroll
    for (int cc = 0; cc < 4; cc++) {
        int c = warp * 4 + cc;
        const float* w = Wout + c * D;
        float acc = 0.f;
        for (int k = lane; k < D; k += 32) acc += row[k] * w[k];
#pragma unroll
        for (int o = 16; o; o >>= 1) acc += __shfl_down_sync(0xffffffffu, acc, o);
        if (lane == 0) s[c] = acc + bout[c];
    }
    __syncthreads();
    if (threadIdx.x == 0) {
        float m = -1e30f;
        for (int c = 0; c < NC; c++) m = fmaxf(m, s[c]);
        float ss = 0.f;
        for (int c = 0; c < NC; c++) ss += __expf(s[c] - m);
        mx = m; sum = ss;
    }
    __syncthreads();
    if (threadIdx.x < NC)
        probs[(long long)bl * NC + threadIdx.x] = __expf(s[threadIdx.x] - mx) / sum;
}

// ---------------- 7. per-batch token weights ----------------
__global__ void weights_k(const int* __restrict__ ids, const float* __restrict__ col,
                          float* __restrict__ wgt) {
    int b = blockIdx.x, l = threadIdx.x;
    float w = (ids[b * L + l] != 0 ? 1.f : 0.f) * col[b * L + l];
    __shared__ float red[512];
    red[l] = w;
    __syncthreads();
    for (int o = 256; o; o >>= 1) { if (l < o) red[l] = fmaxf(red[l], red[l + o]); __syncthreads(); }
    float mxv = red[0];
    __syncthreads();
    float e = __expf(w - mxv);
    red[l] = e;
    __syncthreads();
    for (int o = 256; o; o >>= 1) { if (l < o) red[l] += red[l + o]; __syncthreads(); }
    wgt[b * L + l] = e / red[0];
}

// ---------------- 8. final reduce ----------------
__global__ void final_k(const float* __restrict__ wgt, const float* __restrict__ probs,
                        float* __restrict__ dout, int first) {
    int b = blockIdx.x;
    __shared__ float red[256];
    int tid = threadIdx.x;
    for (int c = 0; c < NC; c++) {
        float s = 0.f;
        for (int l = tid; l < L; l += 256)
            s += wgt[b * L + l] * probs[(long long)(b * L + l) * NC + c];
        red[tid] = s;
        __syncthreads();
        for (int o = 128; o; o >>= 1) { if (tid < o) red[tid] += red[tid + o]; __syncthreads(); }
        if (tid == 0) {
            float v = 0.5f * red[0];
            dout[b * NC + c] = first ? v : dout[b * NC + c] + v;
        }
        __syncthreads();
    }
}

// ---------------- launch ----------------
extern "C" void kernel_launch(void* const* d_in, const int* in_sizes, int n_in,
                              void* d_out, int out_size) {
    (void)in_sizes; (void)n_in; (void)out_size;
    const int*   ids   = (const int*)d_in[0];
    const float* wv    = (const float*)d_in[1];
    const float* emb   = (const float*)d_in[2];
    const float* W_t   = (const float*)d_in[3];
    const float* b_t   = (const float*)d_in[4];
    const float* gam_t = (const float*)d_in[5];
    const float* bet_t = (const float*)d_in[6];
    const float* Wo_t  = (const float*)d_in[7];
    const float* bo_t  = (const float*)d_in[8];
    const float* W_h   = (const float*)d_in[9];
    const float* b_h   = (const float*)d_in[10];
    const float* gam_h = (const float*)d_in[11];
    const float* bet_h = (const float*)d_in[12];
    const float* Wo_h  = (const float*)d_in[13];
    const float* bo_h  = (const float*)d_in[14];
    float* out = (float*)d_out;

    __half *px, *pwt, *pwh, *pwv, *phid, *patt16, *pqn, *pkn, *pvt;
    __half *phid2, *patt16_2, *pqn2, *pkn2, *pvt2;
    float *pout, *pprobs, *pcol, *pwgt;
    float *pout2, *pprobs2, *pcol2, *pwgt2;
    cudaGetSymbolAddress((void**)&px, g_x);
    cudaGetSymbolAddress((void**)&pwt, g_wt16);
    cudaGetSymbolAddress((void**)&pwh, g_wh16);
    cudaGetSymbolAddress((void**)&pwv, g_wv16);
    cudaGetSymbolAddress((void**)&phid, g_hid);
    cudaGetSymbolAddress((void**)&patt16, g_att16);
    cudaGetSymbolAddress((void**)&pqn, g_qn);
    cudaGetSymbolAddress((void**)&pkn, g_kn);
    cudaGetSymbolAddress((void**)&pvt, g_vt);
    cudaGetSymbolAddress((void**)&pout, g_out);
    cudaGetSymbolAddress((void**)&pprobs, g_probs);
    cudaGetSymbolAddress((void**)&pcol, g_col);
    cudaGetSymbolAddress((void**)&pwgt, g_wgt);
    cudaGetSymbolAddress((void**)&phid2, g_hid2);
    cudaGetSymbolAddress((void**)&patt16_2, g_att16_2);
    cudaGetSymbolAddress((void**)&pqn2, g_qn2);
    cudaGetSymbolAddress((void**)&pkn2, g_kn2);
    cudaGetSymbolAddress((void**)&pvt2, g_vt2);
    cudaGetSymbolAddress((void**)&pout2, g_out2);
    cudaGetSymbolAddress((void**)&pprobs2, g_probs2);
    cudaGetSymbolAddress((void**)&pcol2, g_col2);
    cudaGetSymbolAddress((void**)&pwgt2, g_wgt2);

    cudaFuncSetAttribute(smattv_k, cudaFuncAttributeMaxDynamicSharedMemorySize, SMATTV_SMEM);

    dim3 proj_grid(D3 / 128, BL / 128);
    dim3 split_grid(L / 64, BH);
    dim3 attln_grid(L / 32, L / 64, Bsz);
    dim3 smattv_grid(L / 64, BH);

    // Fork a second stream for the independent hidden branch (graph-capturable;
    // created per call, intentionally not destroyed — see R7 notes).
    cudaStream_t s2;
    cudaStreamCreateWithFlags(&s2, cudaStreamNonBlocking);
    cudaEvent_t evFork, evJoin;
    cudaEventCreateWithFlags(&evFork, cudaEventDisableTiming);
    cudaEventCreateWithFlags(&evJoin, cudaEventDisableTiming);

    cudaEventRecord(evFork, 0);
    cudaStreamWaitEvent(s2, evFork, 0);

    // ===== token branch (main stream) =====
    embed_leaky_k<<<BL, 192>>>(ids, emb, px);
    convpad_k<<<D3, 192>>>(W_t, pwt, D, D);
    h_gemm<128,128,32,64><<<proj_grid, 256>>>(px, D, pwt, D, b_t, phid, D3, D);
    splitnorm2_k<<<split_grid, 256>>>(phid, pqn, pkn, pvt, pcol);
    attln2_k<<<attln_grid, 256>>>(pkn, pqn, patt16, gam_t, bet_t);
    smattv_k<<<smattv_grid, 256, SMATTV_SMEM>>>(patt16, pvt, pout, pcol);
    probs_k<<<BL, 160>>>(pout, Wo_t, bo_t, pprobs);
    weights_k<<<Bsz, 512>>>(ids, pcol, pwgt);
    final_k<<<Bsz, 256>>>(pwgt, pprobs, out, 1);

    // ===== hidden / word-vector branch (stream s2) =====
    convpad_k<<<D3, 128, 0, s2>>>(W_h, pwh, 300, KH);
    convpad_k<<<BL, 128, 0, s2>>>(wv, pwv, 300, KH);
    h_gemm<128,128,32,64><<<proj_grid, 256, 0, s2>>>(pwv, KH, pwh, KH, b_h, phid2, D3, KH);
    splitnorm2_k<<<split_grid, 256, 0, s2>>>(phid2, pqn2, pkn2, pvt2, pcol2);
    attln2_k<<<attln_grid, 256, 0, s2>>>(pkn2, pqn2, patt16_2, gam_h, bet_h);
    smattv_k<<<smattv_grid, 256, SMATTV_SMEM, s2>>>(patt16_2, pvt2, pout2, pcol2);
    probs_k<<<BL, 160, 0, s2>>>(pout2, Wo_h, bo_h, pprobs2);
    weights_k<<<Bsz, 512, 0, s2>>>(ids, pcol2, pwgt2);

    // join: hidden-branch results folded into d_out on the main stream
    cudaEventRecord(evJoin, s2);
    cudaStreamWaitEvent(0, evJoin, 0);
    final_k<<<Bsz, 256>>>(pwgt2, pprobs2, out, 0);
}

// round 9
// speedup vs baseline: 6.1382x; 1.0843x over previous
#include <cuda_runtime.h>
#include <cuda_fp16.h>
#include <math.h>

#define Bsz 16
#define L   512
#define NH  12
#define HD  64
#define D   768
#define D3  2304
#define NC  20
#define BL  (Bsz*L)      // 8192
#define BH  (Bsz*NH)     // 192
#define LL  (L*L)        // 262144
#define KH  320          // padded K for hidden branch (300 -> 320)

// ---------------- scratch (allocation-free) ----------------
// token branch
__device__ __half g_x[(size_t)BL*D];
__device__ __half g_wt16[(size_t)D3*D];
__device__ __half g_att16[(size_t)BH*LL];
__device__ __half g_qn[(size_t)BH*L*HD];
__device__ __half g_kn[(size_t)BH*L*HD];
__device__ __half g_vld[(size_t)BH*L*HD];     // V pre-transpose [z][l][d]
__device__ __half g_vt[(size_t)BH*HD*L];      // V transposed [z][d][l]
__device__ float  g_out[(size_t)BL*D];
__device__ float  g_probs[(size_t)BL*NC];
__device__ float  g_col[BL];
// hidden branch (independent copies so both branches run concurrently)
__device__ __half g_wh16[(size_t)D3*KH];
__device__ __half g_wv16[(size_t)BL*KH];
__device__ __half g_att16_2[(size_t)BH*LL];
__device__ __half g_qn2[(size_t)BH*L*HD];
__device__ __half g_kn2[(size_t)BH*L*HD];
__device__ __half g_vld2[(size_t)BH*L*HD];
__device__ __half g_vt2[(size_t)BH*HD*L];
__device__ float  g_out2[(size_t)BL*D];
__device__ float  g_probs2[(size_t)BL*NC];
__device__ float  g_col2[BL];

__device__ __forceinline__ float lrelu(float x) { return x >= 0.f ? x : 0.01f * x; }

__device__ __forceinline__ void mma16(float c[4], const unsigned a[4], const unsigned b[2]) {
    asm volatile(
        "mma.sync.aligned.m16n8k16.row.col.f32.f16.f16.f32 "
        "{%0,%1,%2,%3},{%4,%5,%6,%7},{%8,%9},{%0,%1,%2,%3};"
        : "+f"(c[0]), "+f"(c[1]), "+f"(c[2]), "+f"(c[3])
        : "r"(a[0]), "r"(a[1]), "r"(a[2]), "r"(a[3]), "r"(b[0]), "r"(b[1]));
}
__device__ __forceinline__ unsigned lds_u32(const __half* p) { return *(const unsigned*)p; }
__device__ __forceinline__ void cpasync16(void* smem, const void* gmem) {
    unsigned s = (unsigned)__cvta_generic_to_shared(smem);
    asm volatile("cp.async.cg.shared.global [%0], [%1], 16;\n" :: "r"(s), "l"(gmem));
}
__device__ __forceinline__ void cpcommit() { asm volatile("cp.async.commit_group;\n"); }
__device__ __forceinline__ void cpwait1()  { asm volatile("cp.async.wait_group 1;\n"); }

// ---------------- 0. fp32 -> fp16 (optionally K-padded rows) ----------------
__global__ void convpad_k(const float* __restrict__ src, __half* __restrict__ dst,
                          int K, int KP) {
    long long row = blockIdx.x;
    for (int k4 = threadIdx.x * 4; k4 < KP; k4 += blockDim.x * 4) {
        float4 v = (k4 + 4 <= K) ? *(const float4*)(src + row * K + k4)
                                 : make_float4(k4 < K ? src[row * K + k4] : 0.f,
                                               k4 + 1 < K ? src[row * K + k4 + 1] : 0.f,
                                               k4 + 2 < K ? src[row * K + k4 + 2] : 0.f,
                                               k4 + 3 < K ? src[row * K + k4 + 3] : 0.f);
        *(__half2*)(dst + row * KP + k4)     = __floats2half2_rn(v.x, v.y);
        *(__half2*)(dst + row * KP + k4 + 2) = __floats2half2_rn(v.z, v.w);
    }
}

// ---------------- 1. embedding + leaky -> fp16 ----------------
__global__ void embed_leaky_k(const int* __restrict__ ids, const float* __restrict__ emb,
                              __half* __restrict__ x) {
    int bl = blockIdx.x;
    long long id = ids[bl];
    const float* src = emb + id * D;
    __half* dst = x + (long long)bl * D;
    for (int k4 = threadIdx.x * 4; k4 < D; k4 += blockDim.x * 4) {
        float4 v = *(const float4*)(src + k4);
        *(__half2*)(dst + k4)     = __floats2half2_rn(lrelu(v.x), lrelu(v.y));
        *(__half2*)(dst + k4 + 2) = __floats2half2_rn(lrelu(v.z), lrelu(v.w));
    }
}

// ---------------- 2. fused proj GEMM + QKV split + cosine-norm ----------------
// C = lrelu(A @ W^T + bias); per-warp 64-col group = one head's Q/K/V slice.
// Q/K slices are L2-normalized in-register and written to qn/kn [z][l][d];
// V written unnormalized to vld [z][l][d].
__global__ void __launch_bounds__(256)
projsplit_k(const __half* __restrict__ A, int lda,
            const __half* __restrict__ W, int ldb,
            const float* __restrict__ bias,
            __half* __restrict__ qn, __half* __restrict__ kn,
            __half* __restrict__ vld, int K) {
    constexpr int BM = 128, BN = 128, WM = 32, WN = 64, BK = 32, PAD = 8, STG = 3;
    constexpr int IM = 2, IN = 8;

    __shared__ __align__(16) __half As[STG][BM][BK + PAD];
    __shared__ __align__(16) __half Bs[STG][BN][BK + PAD];

    const int tid = threadIdx.x;
    const int wid = tid >> 5, lane = tid & 31;
    const int g = lane >> 2, tg = lane & 3;
    const int wm = (wid >> 1) * WM, wn = (wid & 1) * WN;

    const __half* Ab = A + (long long)blockIdx.y * BM * lda;
    const __half* Bb = W + (long long)blockIdx.x * BN * ldb;

    const int ktiles = K / BK;
    float acc[IM][IN][4] = {};

    auto issue = [&](int t, int s) {
        int k0 = t * BK;
#pragma unroll
        for (int c = 0; c < 2; c++) {
            int idx = tid + c * 256;
            int row = idx >> 2, cq = idx & 3;
            cpasync16(&As[s][row][cq * 8], Ab + (long long)row * lda + k0 + cq * 8);
        }
#pragma unroll
        for (int c = 0; c < 2; c++) {
            int idx = tid + c * 256;
            int row = idx >> 2, cq = idx & 3;
            cpasync16(&Bs[s][row][cq * 8], Bb + (long long)row * ldb + k0 + cq * 8);
        }
    };

    issue(0, 0); cpcommit();
    if (ktiles > 1) issue(1, 1);
    cpcommit();
    cpwait1();
    __syncthreads();

    int rs = 0;
    for (int t = 0; t < ktiles; t++) {
#pragma unroll
        for (int kk = 0; kk < BK; kk += 16) {
            unsigned a[IM][4], b[IN][2];
#pragma unroll
            for (int im = 0; im < IM; im++) {
                int r = wm + im * 16 + g;
                a[im][0] = lds_u32(&As[rs][r][kk + tg * 2]);
                a[im][1] = lds_u32(&As[rs][r + 8][kk + tg * 2]);
                a[im][2] = lds_u32(&As[rs][r][kk + tg * 2 + 8]);
                a[im][3] = lds_u32(&As[rs][r + 8][kk + tg * 2 + 8]);
            }
#pragma unroll
            for (int in_ = 0; in_ < IN; in_++) {
                int r = wn + in_ * 8 + g;
                b[in_][0] = lds_u32(&Bs[rs][r][kk + tg * 2]);
                b[in_][1] = lds_u32(&Bs[rs][r][kk + tg * 2 + 8]);
            }
#pragma unroll
            for (int im = 0; im < IM; im++)
#pragma unroll
                for (int in_ = 0; in_ < IN; in_++)
                    mma16(acc[im][in_], a[im], b[in_]);
        }
        if (t + 2 < ktiles) issue(t + 2, (rs + 2) % STG);
        cpcommit();
        cpwait1();
        __syncthreads();
        rs = (rs + 1) % STG;
    }

    // epilogue: bias + lrelu, then per-(token, head-slice) routing
    const int sec  = blockIdx.x / 6;                       // 0=Q, 1=K, 2=V
    const int hloc = (blockIdx.x % 6) * 2 + (wn >> 6);     // head index
    const int m0   = blockIdx.y * BM;
    const int b    = m0 / L;
    const long long z = b * NH + hloc;
    const int l0   = m0 % L;

    __half* dst = (sec == 0) ? qn : (sec == 1) ? kn : vld;

#pragma unroll
    for (int im = 0; im < IM; im++) {
        // bias + lrelu in place
#pragma unroll
        for (int in_ = 0; in_ < IN; in_++) {
            int cc = blockIdx.x * BN + wn + in_ * 8 + tg * 2;
            float b0 = bias[cc], b1 = bias[cc + 1];
            acc[im][in_][0] = lrelu(acc[im][in_][0] + b0);
            acc[im][in_][1] = lrelu(acc[im][in_][1] + b1);
            acc[im][in_][2] = lrelu(acc[im][in_][2] + b0);
            acc[im][in_][3] = lrelu(acc[im][in_][3] + b1);
        }
        float r0 = 1.f, r1 = 1.f;
        if (sec < 2) {
            float ss0 = 0.f, ss1 = 0.f;
#pragma unroll
            for (int in_ = 0; in_ < IN; in_++) {
                ss0 += acc[im][in_][0] * acc[im][in_][0] + acc[im][in_][1] * acc[im][in_][1];
                ss1 += acc[im][in_][2] * acc[im][in_][2] + acc[im][in_][3] * acc[im][in_][3];
            }
            // quad-local reduce (lanes 4g..4g+3 hold the full 64-col group)
            ss0 += __shfl_xor_sync(0xffffffffu, ss0, 1);
            ss0 += __shfl_xor_sync(0xffffffffu, ss0, 2);
            ss1 += __shfl_xor_sync(0xffffffffu, ss1, 1);
            ss1 += __shfl_xor_sync(0xffffffffu, ss1, 2);
            r0 = 1.f / fmaxf(sqrtf(ss0), 1e-8f);
            r1 = 1.f / fmaxf(sqrtf(ss1), 1e-8f);
        }
        int lA = l0 + wm + im * 16 + g;
        int lB = lA + 8;
#pragma unroll
        for (int in_ = 0; in_ < IN; in_++) {
            int dcol = in_ * 8 + tg * 2;
            *(__half2*)&dst[(z * L + lA) * HD + dcol] =
                __floats2half2_rn(acc[im][in_][0] * r0, acc[im][in_][1] * r0);
            *(__half2*)&dst[(z * L + lB) * HD + dcol] =
                __floats2half2_rn(acc[im][in_][2] * r1, acc[im][in_][3] * r1);
        }
    }
}

// ---------------- 3. V transpose [z][l][d] -> [z][d][l] (+ col zero) ----------------
__global__ void __launch_bounds__(256)
vtrans_k(const __half* __restrict__ vld, __half* __restrict__ vt,
         float* __restrict__ col) {
    __shared__ __half sv[64][72];
    const int z = blockIdx.y, b = z / NH, h = z % NH;
    const int l0 = blockIdx.x * 64;
    const int tid = threadIdx.x;
    if (h == 0 && tid < 64) col[b * L + l0 + tid] = 0.f;
#pragma unroll
    for (int c = 0; c < 2; c++) {
        int idx = tid + c * 256;
        int l = idx >> 3, dc = (idx & 7) * 8;
        *(uint4*)&sv[l][dc] = *(const uint4*)(vld + ((long long)z * L + l0 + l) * HD + dc);
    }
    __syncthreads();
#pragma unroll
    for (int c = 0; c < 2; c++) {
        int idx = tid + c * 256;
        int d = idx >> 3, lc = (idx & 7) * 8;
        __half tmp[8];
#pragma unroll
        for (int i = 0; i < 8; i++) tmp[i] = sv[lc + i][d];
        *(uint4*)(vt + ((long long)z * HD + d) * L + l0 + lc) = *(uint4*)tmp;
    }
}

// ---------------- 4. fused scores + LayerNorm(heads), LN in registers ----------------
__global__ void __launch_bounds__(256)
attln2_k(const __half* __restrict__ kn, const __half* __restrict__ qn,
         __half* __restrict__ att, const float* __restrict__ gamma,
         const float* __restrict__ beta) {
    __shared__ __align__(16) __half kbuf[2][64][72];
    __shared__ __align__(16) __half qbuf[2][32][72];

    const int tid = threadIdx.x;
    const int wid = tid >> 5, lane = tid & 31;
    const int g = lane >> 2, tg = lane & 3;
    const int wm = (wid >> 1) * 16, wn = (wid & 1) * 16;
    const int J0 = blockIdx.x * 32, I0 = blockIdx.y * 64, b = blockIdx.z;

    const __half* kb = kn + ((long long)b * NH * L + I0) * HD;
    const __half* qb = qn + ((long long)b * NH * L + J0) * HD;

    __half2 sc[NH][4];

#define ISSUE(h, s)                                                              \
    {                                                                            \
        long long hoff = (long long)(h) * L * HD;                                \
        _Pragma("unroll")                                                        \
        for (int c = 0; c < 2; c++) {                                            \
            int idx = tid + c * 256;                                             \
            int r = idx >> 3, jc = idx & 7;                                      \
            cpasync16(&kbuf[s][r][jc * 8], kb + hoff + (long long)r * HD + jc * 8); \
        }                                                                        \
        { int r = tid >> 3, jc = tid & 7;                                        \
          cpasync16(&qbuf[s][r][jc * 8], qb + hoff + (long long)r * HD + jc * 8); } \
    }

    ISSUE(0, 0); cpcommit();
#pragma unroll
    for (int h = 0; h < NH; h++) {
        if (h + 1 < NH) ISSUE(h + 1, (h + 1) & 1);
        cpcommit();
        cpwait1();
        __syncthreads();
        int s = h & 1;
        float acc[2][4] = {};
#pragma unroll
        for (int kk = 0; kk < 64; kk += 16) {
            unsigned a[4];
            a[0] = lds_u32(&kbuf[s][wm + g][kk + tg * 2]);
            a[1] = lds_u32(&kbuf[s][wm + g + 8][kk + tg * 2]);
            a[2] = lds_u32(&kbuf[s][wm + g][kk + tg * 2 + 8]);
            a[3] = lds_u32(&kbuf[s][wm + g + 8][kk + tg * 2 + 8]);
#pragma unroll
            for (int in_ = 0; in_ < 2; in_++) {
                unsigned bb[2];
                bb[0] = lds_u32(&qbuf[s][wn + in_ * 8 + g][kk + tg * 2]);
                bb[1] = lds_u32(&qbuf[s][wn + in_ * 8 + g][kk + tg * 2 + 8]);
                mma16(acc[in_], a, bb);
            }
        }
        sc[h][0] = __floats2half2_rn(acc[0][0], acc[0][1]);
        sc[h][1] = __floats2half2_rn(acc[0][2], acc[0][3]);
        sc[h][2] = __floats2half2_rn(acc[1][0], acc[1][1]);
        sc[h][3] = __floats2half2_rn(acc[1][2], acc[1][3]);
        __syncthreads();
    }
#undef ISSUE

    float gm[NH], be[NH];
#pragma unroll
    for (int h = 0; h < NH; h++) { gm[h] = gamma[h]; be[h] = beta[h]; }

    __half* ob = att + (long long)b * NH * LL + (long long)I0 * L + J0;
#pragma unroll
    for (int p = 0; p < 4; p++) {
        int i = wm + g + ((p & 1) ? 8 : 0);
        int j = wn + ((p >> 1) ? 8 : 0) + tg * 2;
        float vx[NH], vy[NH];
        float mux = 0.f, muy = 0.f;
#pragma unroll
        for (int h = 0; h < NH; h++) {
            float2 f = __half22float2(sc[h][p]);
            vx[h] = f.x; vy[h] = f.y; mux += f.x; muy += f.y;
        }
        mux *= (1.f / NH); muy *= (1.f / NH);
        float varx = 0.f, vary = 0.f;
#pragma unroll
        for (int h = 0; h < NH; h++) {
            float dx = vx[h] - mux, dy = vy[h] - muy;
            varx += dx * dx; vary += dy * dy;
        }
        float rsx = rsqrtf(varx * (1.f / NH) + 1e-5f);
        float rsy = rsqrtf(vary * (1.f / NH) + 1e-5f);
#pragma unroll
        for (int h = 0; h < NH; h++) {
            *(__half2*)&ob[(long long)h * LL + (long long)i * L + j] =
                __floats2half2_rn((vx[h] - mux) * rsx * gm[h] + be[h],
                                  (vy[h] - muy) * rsy * gm[h] + be[h]);
        }
    }
}

// ---------------- 5. fused softmax + colsum + att@V ----------------
#define SMATTV_SMEM (64*520*2 + 2*64*72*2)   // 84992
__global__ void __launch_bounds__(256)
smattv_k(const __half* __restrict__ att, const __half* __restrict__ vt,
         float* __restrict__ out, float* __restrict__ col) {
    extern __shared__ __align__(16) char smem_raw[];
    __half (*satt)[520] = (__half(*)[520])smem_raw;
    __half (*vbuf)[64][72] = (__half(*)[64][72])(smem_raw + 64*520*2);

    const int tid = threadIdx.x;
    const int wid = tid >> 5, lane = tid & 31;
    const int g = lane >> 2, tg = lane & 3;
    const int wm = (wid >> 1) * 16, wn = (wid & 1) * 32;
    const int I0 = blockIdx.x * 64;
    const int z = blockIdx.y;
    const int b = z / NH, h = z % NH;

    const __half* abase = att + (long long)z * LL + (long long)I0 * L;
    const __half* vbase = vt + (long long)z * HD * L;

#pragma unroll
    for (int c = 0; c < 16; c++) {
        int idx = tid + c * 256;
        int r = idx >> 6, jc = idx & 63;
        cpasync16(&satt[r][jc * 8], abase + (long long)r * L + jc * 8);
    }
    cpcommit();

#define ISSUEV(kt, s)                                                            \
    {                                                                            \
        _Pragma("unroll")                                                        \
        for (int c = 0; c < 2; c++) {                                            \
            int idx = tid + c * 256;                                             \
            int r = idx >> 3, jc = idx & 7;                                      \
            cpasync16(&vbuf[s][r][jc * 8], vbase + (long long)r * L + (kt) * 64 + jc * 8); \
        }                                                                        \
    }
    ISSUEV(0, 0); cpcommit();
    cpwait1();
    __syncthreads();

    for (int k = 0; k < 8; k++) {
        int r = wid * 8 + k;
        float v[16];
        float m = -1e30f;
#pragma unroll
        for (int q = 0; q < 8; q++) {
            float2 f = __half22float2(*(__half2*)&satt[r][lane * 2 + q * 64]);
            v[2 * q] = f.x; v[2 * q + 1] = f.y;
            m = fmaxf(m, fmaxf(f.x, f.y));
        }
#pragma unroll
        for (int o = 16; o; o >>= 1) m = fmaxf(m, __shfl_xor_sync(0xffffffffu, m, o));
        float s = 0.f;
#pragma unroll
        for (int q = 0; q < 16; q++) { v[q] = __expf(v[q] - m); s += v[q]; }
#pragma unroll
        for (int o = 16; o; o >>= 1) s += __shfl_xor_sync(0xffffffffu, s, o);
        float inv = 1.f / s;
#pragma unroll
        for (int q = 0; q < 8; q++)
            *(__half2*)&satt[r][lane * 2 + q * 64] =
                __floats2half2_rn(v[2 * q] * inv, v[2 * q + 1] * inv);
    }
    __syncthreads();

    {
        int j = tid * 2;
        float c0 = 0.f, c1 = 0.f;
#pragma unroll 8
        for (int r = 0; r < 64; r++) {
            float2 f = __half22float2(*(__half2*)&satt[r][j]);
            c0 += f.x; c1 += f.y;
        }
        atomicAdd(&col[b * L + j], c0 * (1.f / NH));
        atomicAdd(&col[b * L + j + 1], c1 * (1.f / NH));
    }

    float acc[4][4] = {};
    int rs = 0;
    for (int kt = 0; kt < 8; kt++) {
        if (kt + 1 < 8) ISSUEV(kt + 1, rs ^ 1);
        cpcommit();
        cpwait1();
        __syncthreads();
#pragma unroll
        for (int kk = 0; kk < 64; kk += 16) {
            unsigned a[4];
            int kc = kt * 64 + kk + tg * 2;
            a[0] = lds_u32(&satt[wm + g][kc]);
            a[1] = lds_u32(&satt[wm + g + 8][kc]);
            a[2] = lds_u32(&satt[wm + g][kc + 8]);
            a[3] = lds_u32(&satt[wm + g + 8][kc + 8]);
#pragma unroll
            for (int in_ = 0; in_ < 4; in_++) {
                unsigned bb[2];
                bb[0] = lds_u32(&vbuf[rs][wn + in_ * 8 + g][kk + tg * 2]);
                bb[1] = lds_u32(&vbuf[rs][wn + in_ * 8 + g][kk + tg * 2 + 8]);
                mma16(acc[in_], a, bb);
            }
        }
        rs ^= 1;
        __syncthreads();
    }
#undef ISSUEV

    float* ob = out + ((long long)b * L + I0) * D + h * HD;
#pragma unroll
    for (int in_ = 0; in_ < 4; in_++) {
        int c = wn + in_ * 8 + tg * 2;
        *(float2*)&ob[(long long)(wm + g) * D + c] = make_float2(acc[in_][0], acc[in_][1]);
        *(float2*)&ob[(long long)(wm + g + 8) * D + c] = make_float2(acc[in_][2], acc[in_][3]);
    }
}

// ---------------- 6. per-token class probs ----------------
__global__ void probs_k(const float* __restrict__ out, const float* __restrict__ Wout,
                        const float* __restrict__ bout, float* __restrict__ probs) {
    int bl = blockIdx.x;
    int warp = threadIdx.x >> 5, lane = threadIdx.x & 31;
    __shared__ float s[NC];
    __shared__ float mx, sum;
    const float* row = out + (long long)bl * D;
#pragma unroll
    for (int cc = 0; cc < 4; cc++) {
        int c = warp * 4 + cc;
        const float* w = Wout + c * D;
        float acc = 0.f;
        for (int k = lane; k < D; k += 32) acc += row[k] * w[k];
#pragma unroll
        for (int o = 16; o; o >>= 1) acc += __shfl_down_sync(0xffffffffu, acc, o);
        if (lane == 0) s[c] = acc + bout[c];
    }
    __syncthreads();
    if (threadIdx.x == 0) {
        float m = -1e30f;
        for (int c = 0; c < NC; c++) m = fmaxf(m, s[c]);
        float ss = 0.f;
        for (int c = 0; c < NC; c++) ss += __expf(s[c] - m);
        mx = m; sum = ss;
    }
    __syncthreads();
    if (threadIdx.x < NC)
        probs[(long long)bl * NC + threadIdx.x] = __expf(s[threadIdx.x] - mx) / sum;
}

// ---------------- 7. fused token weights softmax + final reduce ----------------
__global__ void __launch_bounds__(512)
wfinal_k(const int* __restrict__ ids, const float* __restrict__ col,
         const float* __restrict__ probs, float* __restrict__ dout, int first) {
    int b = blockIdx.x, l = threadIdx.x;
    int wid = l >> 5, lane = l & 31;
    __shared__ float red[512];
    __shared__ float psum[16][NC];

    float w = (ids[b * L + l] != 0 ? 1.f : 0.f) * col[b * L + l];
    red[l] = w;
    __syncthreads();
    for (int o = 256; o; o >>= 1) { if (l < o) red[l] = fmaxf(red[l], red[l + o]); __syncthreads(); }
    float mxv = red[0];
    __syncthreads();
    float e = __expf(w - mxv);
    red[l] = e;
    __syncthreads();
    for (int o = 256; o; o >>= 1) { if (l < o) red[l] += red[l + o]; __syncthreads(); }
    float wg = e / red[0];

    const float* pb = probs + (long long)(b * L + l) * NC;
    float myp[NC];
#pragma unroll
    for (int c = 0; c < NC; c++) myp[c] = wg * pb[c];
#pragma unroll
    for (int c = 0; c < NC; c++) {
        float v = myp[c];
#pragma unroll
        for (int o = 16; o; o >>= 1) v += __shfl_xor_sync(0xffffffffu, v, o);
        if (lane == 0) psum[wid][c] = v;
    }
    __syncthreads();
    if (l < NC) {
        float s = 0.f;
#pragma unroll
        for (int q = 0; q < 16; q++) s += psum[q][l];
        float v = 0.5f * s;
        dout[b * NC + l] = first ? v : dout[b * NC + l] + v;
    }
}

// ---------------- launch ----------------
extern "C" void kernel_launch(void* const* d_in, const int* in_sizes, int n_in,
                              void* d_out, int out_size) {
    (void)in_sizes; (void)n_in; (void)out_size;
    const int*   ids   = (const int*)d_in[0];
    const float* wv    = (const float*)d_in[1];
    const float* emb   = (const float*)d_in[2];
    const float* W_t   = (const float*)d_in[3];
    const float* b_t   = (const float*)d_in[4];
    const float* gam_t = (const float*)d_in[5];
    const float* bet_t = (const float*)d_in[6];
    const float* Wo_t  = (const float*)d_in[7];
    const float* bo_t  = (const float*)d_in[8];
    const float* W_h   = (const float*)d_in[9];
    const float* b_h   = (const float*)d_in[10];
    const float* gam_h = (const float*)d_in[11];
    const float* bet_h = (const float*)d_in[12];
    const float* Wo_h  = (const float*)d_in[13];
    const float* bo_h  = (const float*)d_in[14];
    float* out = (float*)d_out;

    __half *px, *pwt, *pwh, *pwv, *patt16, *pqn, *pkn, *pvld, *pvt;
    __half *patt16_2, *pqn2, *pkn2, *pvld2, *pvt2;
    float *pout, *pprobs, *pcol;
    float *pout2, *pprobs2, *pcol2;
    cudaGetSymbolAddress((void**)&px, g_x);
    cudaGetSymbolAddress((void**)&pwt, g_wt16);
    cudaGetSymbolAddress((void**)&pwh, g_wh16);
    cudaGetSymbolAddress((void**)&pwv, g_wv16);
    cudaGetSymbolAddress((void**)&patt16, g_att16);
    cudaGetSymbolAddress((void**)&pqn, g_qn);
    cudaGetSymbolAddress((void**)&pkn, g_kn);
    cudaGetSymbolAddress((void**)&pvld, g_vld);
    cudaGetSymbolAddress((void**)&pvt, g_vt);
    cudaGetSymbolAddress((void**)&pout, g_out);
    cudaGetSymbolAddress((void**)&pprobs, g_probs);
    cudaGetSymbolAddress((void**)&pcol, g_col);
    cudaGetSymbolAddress((void**)&patt16_2, g_att16_2);
    cudaGetSymbolAddress((void**)&pqn2, g_qn2);
    cudaGetSymbolAddress((void**)&pkn2, g_kn2);
    cudaGetSymbolAddress((void**)&pvld2, g_vld2);
    cudaGetSymbolAddress((void**)&pvt2, g_vt2);
    cudaGetSymbolAddress((void**)&pout2, g_out2);
    cudaGetSymbolAddress((void**)&pprobs2, g_probs2);
    cudaGetSymbolAddress((void**)&pcol2, g_col2);

    cudaFuncSetAttribute(smattv_k, cudaFuncAttributeMaxDynamicSharedMemorySize, SMATTV_SMEM);

    dim3 proj_grid(D3 / 128, BL / 128);
    dim3 vt_grid(L / 64, BH);
    dim3 attln_grid(L / 32, L / 64, Bsz);
    dim3 smattv_grid(L / 64, BH);

    // Fork a second stream for the independent hidden branch (graph-capturable;
    // created per call, intentionally not destroyed — see R7 notes).
    cudaStream_t s2;
    cudaStreamCreateWithFlags(&s2, cudaStreamNonBlocking);
    cudaEvent_t evFork, evJoin;
    cudaEventCreateWithFlags(&evFork, cudaEventDisableTiming);
    cudaEventCreateWithFlags(&evJoin, cudaEventDisableTiming);

    cudaEventRecord(evFork, 0);
    cudaStreamWaitEvent(s2, evFork, 0);

    // ===== token branch (main stream) =====
    embed_leaky_k<<<BL, 192>>>(ids, emb, px);
    convpad_k<<<D3, 192>>>(W_t, pwt, D, D);
    projsplit_k<<<proj_grid, 256>>>(px, D, pwt, D, b_t, pqn, pkn, pvld, D);
    vtrans_k<<<vt_grid, 256>>>(pvld, pvt, pcol);
    attln2_k<<<attln_grid, 256>>>(pkn, pqn, patt16, gam_t, bet_t);
    smattv_k<<<smattv_grid, 256, SMATTV_SMEM>>>(patt16, pvt, pout, pcol);
    probs_k<<<BL, 160>>>(pout, Wo_t, bo_t, pprobs);
    wfinal_k<<<Bsz, 512>>>(ids, pcol, pprobs, out, 1);

    // ===== hidden / word-vector branch (stream s2) =====
    convpad_k<<<D3, 128, 0, s2>>>(W_h, pwh, 300, KH);
    convpad_k<<<BL, 128, 0, s2>>>(wv, pwv, 300, KH);
    projsplit_k<<<proj_grid, 256, 0, s2>>>(pwv, KH, pwh, KH, b_h, pqn2, pkn2, pvld2, KH);
    vtrans_k<<<vt_grid, 256, 0, s2>>>(pvld2, pvt2, pcol2);
    attln2_k<<<attln_grid, 256, 0, s2>>>(pkn2, pqn2, patt16_2, gam_h, bet_h);
    smattv_k<<<smattv_grid, 256, SMATTV_SMEM, s2>>>(patt16_2, pvt2, pout2, pcol2);
    probs_k<<<BL, 160, 0, s2>>>(pout2, Wo_h, bo_h, pprobs2);

    // join: hidden-branch results folded into d_out on the main stream
    cudaEventRecord(evJoin, s2);
    cudaStreamWaitEvent(0, evJoin, 0);
    wfinal_k<<<Bsz, 512>>>(ids, pcol2, pprobs2, out, 0);
}

// round 10
// speedup vs baseline: 6.4053x; 1.0435x over previous
#include <cuda_runtime.h>
#include <cuda_fp16.h>
#include <math.h>

#define Bsz 16
#define L   512
#define NH  12
#define HD  64
#define D   768
#define D3  2304
#define NC  20
#define BL  (Bsz*L)      // 8192
#define BH  (Bsz*NH)     // 192
#define LL  (L*L)        // 262144
#define KH  320          // padded K for hidden branch (300 -> 320)

// ---------------- scratch (allocation-free) ----------------
// token branch
__device__ __half g_x[(size_t)BL*D];
__device__ __half g_wt16[(size_t)D3*D];
__device__ __half g_att16[(size_t)BH*LL];
__device__ __half g_qn[(size_t)BH*L*HD];
__device__ __half g_kn[(size_t)BH*L*HD];
__device__ __half g_vt[(size_t)BH*HD*L];      // V transposed [z][d][l]
__device__ __half g_out[(size_t)BL*D];
__device__ float  g_probs[(size_t)BL*NC];
__device__ float  g_col[BL];
// hidden branch (independent copies so both branches run concurrently)
__device__ __half g_wh16[(size_t)D3*KH];
__device__ __half g_wv16[(size_t)BL*KH];
__device__ __half g_att16_2[(size_t)BH*LL];
__device__ __half g_qn2[(size_t)BH*L*HD];
__device__ __half g_kn2[(size_t)BH*L*HD];
__device__ __half g_vt2[(size_t)BH*HD*L];
__device__ __half g_out2[(size_t)BL*D];
__device__ float  g_probs2[(size_t)BL*NC];
__device__ float  g_col2[BL];

__device__ __forceinline__ float lrelu(float x) { return x >= 0.f ? x : 0.01f * x; }

__device__ __forceinline__ void mma16(float c[4], const unsigned a[4], const unsigned b[2]) {
    asm volatile(
        "mma.sync.aligned.m16n8k16.row.col.f32.f16.f16.f32 "
        "{%0,%1,%2,%3},{%4,%5,%6,%7},{%8,%9},{%0,%1,%2,%3};"
        : "+f"(c[0]), "+f"(c[1]), "+f"(c[2]), "+f"(c[3])
        : "r"(a[0]), "r"(a[1]), "r"(a[2]), "r"(a[3]), "r"(b[0]), "r"(b[1]));
}
__device__ __forceinline__ unsigned lds_u32(const __half* p) { return *(const unsigned*)p; }
__device__ __forceinline__ void cpasync16(void* smem, const void* gmem) {
    unsigned s = (unsigned)__cvta_generic_to_shared(smem);
    asm volatile("cp.async.cg.shared.global [%0], [%1], 16;\n" :: "r"(s), "l"(gmem));
}
__device__ __forceinline__ void cpcommit() { asm volatile("cp.async.commit_group;\n"); }
__device__ __forceinline__ void cpwait1()  { asm volatile("cp.async.wait_group 1;\n"); }

// ---------------- 0. fp32 -> fp16 (optionally K-padded rows) ----------------
__global__ void convpad_k(const float* __restrict__ src, __half* __restrict__ dst,
                          int K, int KP) {
    long long row = blockIdx.x;
    for (int k4 = threadIdx.x * 4; k4 < KP; k4 += blockDim.x * 4) {
        float4 v = (k4 + 4 <= K) ? *(const float4*)(src + row * K + k4)
                                 : make_float4(k4 < K ? src[row * K + k4] : 0.f,
                                               k4 + 1 < K ? src[row * K + k4 + 1] : 0.f,
                                               k4 + 2 < K ? src[row * K + k4 + 2] : 0.f,
                                               k4 + 3 < K ? src[row * K + k4 + 3] : 0.f);
        *(__half2*)(dst + row * KP + k4)     = __floats2half2_rn(v.x, v.y);
        *(__half2*)(dst + row * KP + k4 + 2) = __floats2half2_rn(v.z, v.w);
    }
}

// ---------------- 1. embedding + leaky -> fp16 ----------------
__global__ void embed_leaky_k(const int* __restrict__ ids, const float* __restrict__ emb,
                              __half* __restrict__ x) {
    int bl = blockIdx.x;
    long long id = ids[bl];
    const float* src = emb + id * D;
    __half* dst = x + (long long)bl * D;
    for (int k4 = threadIdx.x * 4; k4 < D; k4 += blockDim.x * 4) {
        float4 v = *(const float4*)(src + k4);
        *(__half2*)(dst + k4)     = __floats2half2_rn(lrelu(v.x), lrelu(v.y));
        *(__half2*)(dst + k4 + 2) = __floats2half2_rn(lrelu(v.z), lrelu(v.w));
    }
}

// ---------------- 2. fused proj GEMM + QKV split + cosine-norm + V transpose ----------------
// C = lrelu(A @ W^T + bias). Q/K slices L2-normalized in-register -> qn/kn [z][l][d].
// V blocks transpose through reused smem -> vt [z][d][l]. Also zeroes col.
__global__ void __launch_bounds__(256)
projsplit_k(const __half* __restrict__ A, int lda,
            const __half* __restrict__ W, int ldb,
            const float* __restrict__ bias,
            __half* __restrict__ qn, __half* __restrict__ kn,
            __half* __restrict__ vt, float* __restrict__ col, int K) {
    constexpr int BM = 128, BN = 128, WM = 32, WN = 64, BK = 32, PAD = 8, STG = 3;
    constexpr int IM = 2, IN = 8;

    __shared__ __align__(16) __half As[STG][BM][BK + PAD];
    __shared__ __align__(16) __half Bs[STG][BN][BK + PAD];

    const int tid = threadIdx.x;
    const int wid = tid >> 5, lane = tid & 31;
    const int g = lane >> 2, tg = lane & 3;
    const int wm = (wid >> 1) * WM, wn = (wid & 1) * WN;

    const __half* Ab = A + (long long)blockIdx.y * BM * lda;
    const __half* Bb = W + (long long)blockIdx.x * BN * ldb;

    const int ktiles = K / BK;
    float acc[IM][IN][4] = {};

    auto issue = [&](int t, int s) {
        int k0 = t * BK;
#pragma unroll
        for (int c = 0; c < 2; c++) {
            int idx = tid + c * 256;
            int row = idx >> 2, cq = idx & 3;
            cpasync16(&As[s][row][cq * 8], Ab + (long long)row * lda + k0 + cq * 8);
        }
#pragma unroll
        for (int c = 0; c < 2; c++) {
            int idx = tid + c * 256;
            int row = idx >> 2, cq = idx & 3;
            cpasync16(&Bs[s][row][cq * 8], Bb + (long long)row * ldb + k0 + cq * 8);
        }
    };

    issue(0, 0); cpcommit();
    if (ktiles > 1) issue(1, 1);
    cpcommit();
    cpwait1();
    __syncthreads();

    int rs = 0;
    for (int t = 0; t < ktiles; t++) {
#pragma unroll
        for (int kk = 0; kk < BK; kk += 16) {
            unsigned a[IM][4], b[IN][2];
#pragma unroll
            for (int im = 0; im < IM; im++) {
                int r = wm + im * 16 + g;
                a[im][0] = lds_u32(&As[rs][r][kk + tg * 2]);
                a[im][1] = lds_u32(&As[rs][r + 8][kk + tg * 2]);
                a[im][2] = lds_u32(&As[rs][r][kk + tg * 2 + 8]);
                a[im][3] = lds_u32(&As[rs][r + 8][kk + tg * 2 + 8]);
            }
#pragma unroll
            for (int in_ = 0; in_ < IN; in_++) {
                int r = wn + in_ * 8 + g;
                b[in_][0] = lds_u32(&Bs[rs][r][kk + tg * 2]);
                b[in_][1] = lds_u32(&Bs[rs][r][kk + tg * 2 + 8]);
            }
#pragma unroll
            for (int im = 0; im < IM; im++)
#pragma unroll
                for (int in_ = 0; in_ < IN; in_++)
                    mma16(acc[im][in_], a[im], b[in_]);
        }
        if (t + 2 < ktiles) issue(t + 2, (rs + 2) % STG);
        cpcommit();
        cpwait1();
        __syncthreads();
        rs = (rs + 1) % STG;
    }

    const int sec  = blockIdx.x / 6;                       // 0=Q, 1=K, 2=V
    const int m0   = blockIdx.y * BM;
    const int b    = m0 / L;
    const int l0   = m0 % L;

    if (blockIdx.x == 12 && tid < 128) col[b * L + l0 + tid] = 0.f;

    // bias + lrelu in place
#pragma unroll
    for (int im = 0; im < IM; im++)
#pragma unroll
        for (int in_ = 0; in_ < IN; in_++) {
            int cc = blockIdx.x * BN + wn + in_ * 8 + tg * 2;
            float b0 = bias[cc], b1 = bias[cc + 1];
            acc[im][in_][0] = lrelu(acc[im][in_][0] + b0);
            acc[im][in_][1] = lrelu(acc[im][in_][1] + b1);
            acc[im][in_][2] = lrelu(acc[im][in_][2] + b0);
            acc[im][in_][3] = lrelu(acc[im][in_][3] + b1);
        }

    if (sec < 2) {
        const int hloc = (blockIdx.x % 6) * 2 + (wn >> 6);
        const long long z = (long long)b * NH + hloc;
        __half* dst = (sec == 0) ? qn : kn;
#pragma unroll
        for (int im = 0; im < IM; im++) {
            float ss0 = 0.f, ss1 = 0.f;
#pragma unroll
            for (int in_ = 0; in_ < IN; in_++) {
                ss0 += acc[im][in_][0] * acc[im][in_][0] + acc[im][in_][1] * acc[im][in_][1];
                ss1 += acc[im][in_][2] * acc[im][in_][2] + acc[im][in_][3] * acc[im][in_][3];
            }
            ss0 += __shfl_xor_sync(0xffffffffu, ss0, 1);
            ss0 += __shfl_xor_sync(0xffffffffu, ss0, 2);
            ss1 += __shfl_xor_sync(0xffffffffu, ss1, 1);
            ss1 += __shfl_xor_sync(0xffffffffu, ss1, 2);
            float r0 = 1.f / fmaxf(sqrtf(ss0), 1e-8f);
            float r1 = 1.f / fmaxf(sqrtf(ss1), 1e-8f);
            int lA = l0 + wm + im * 16 + g;
            int lB = lA + 8;
#pragma unroll
            for (int in_ = 0; in_ < IN; in_++) {
                int dcol = in_ * 8 + tg * 2;
                *(__half2*)&dst[(z * L + lA) * HD + dcol] =
                    __floats2half2_rn(acc[im][in_][0] * r0, acc[im][in_][1] * r0);
                *(__half2*)&dst[(z * L + lB) * HD + dcol] =
                    __floats2half2_rn(acc[im][in_][2] * r1, acc[im][in_][3] * r1);
            }
        }
    } else {
        // V: transpose through reused Bs smem, one head (64 cols) per phase
        __half (*sv)[136] = (__half(*)[136])Bs;   // [d][l] tile, 64x136 halves
#pragma unroll
        for (int p = 0; p < 2; p++) {
            __syncthreads();
            if ((wn >> 6) == p) {
#pragma unroll
                for (int im = 0; im < IM; im++)
#pragma unroll
                    for (int in_ = 0; in_ < IN; in_++) {
                        int d = in_ * 8 + tg * 2;
                        int l = wm + im * 16 + g;
                        sv[d][l]         = __float2half_rn(acc[im][in_][0]);
                        sv[d + 1][l]     = __float2half_rn(acc[im][in_][1]);
                        sv[d][l + 8]     = __float2half_rn(acc[im][in_][2]);
                        sv[d + 1][l + 8] = __float2half_rn(acc[im][in_][3]);
                    }
            }
            __syncthreads();
            long long z = (long long)b * NH + (blockIdx.x % 6) * 2 + p;
#pragma unroll
            for (int c = 0; c < 4; c++) {
                int idx = tid + c * 256;          // 0..1023
                int d = idx >> 4, lc = (idx & 15) * 8;
                *(uint4*)(vt + (z * HD + d) * L + l0 + lc) = *(uint4*)&sv[d][lc];
            }
        }
    }
}

// ---------------- 3. fused scores + LayerNorm(heads), LN in registers ----------------
__global__ void __launch_bounds__(256)
attln2_k(const __half* __restrict__ kn, const __half* __restrict__ qn,
         __half* __restrict__ att, const float* __restrict__ gamma,
         const float* __restrict__ beta) {
    __shared__ __align__(16) __half kbuf[2][64][72];
    __shared__ __align__(16) __half qbuf[2][32][72];

    const int tid = threadIdx.x;
    const int wid = tid >> 5, lane = tid & 31;
    const int g = lane >> 2, tg = lane & 3;
    const int wm = (wid >> 1) * 16, wn = (wid & 1) * 16;
    const int J0 = blockIdx.x * 32, I0 = blockIdx.y * 64, b = blockIdx.z;

    const __half* kb = kn + ((long long)b * NH * L + I0) * HD;
    const __half* qb = qn + ((long long)b * NH * L + J0) * HD;

    __half2 sc[NH][4];

#define ISSUE(h, s)                                                              \
    {                                                                            \
        long long hoff = (long long)(h) * L * HD;                                \
        _Pragma("unroll")                                                        \
        for (int c = 0; c < 2; c++) {                                            \
            int idx = tid + c * 256;                                             \
            int r = idx >> 3, jc = idx & 7;                                      \
            cpasync16(&kbuf[s][r][jc * 8], kb + hoff + (long long)r * HD + jc * 8); \
        }                                                                        \
        { int r = tid >> 3, jc = tid & 7;                                        \
          cpasync16(&qbuf[s][r][jc * 8], qb + hoff + (long long)r * HD + jc * 8); } \
    }

    ISSUE(0, 0); cpcommit();
#pragma unroll
    for (int h = 0; h < NH; h++) {
        if (h + 1 < NH) ISSUE(h + 1, (h + 1) & 1);
        cpcommit();
        cpwait1();
        __syncthreads();
        int s = h & 1;
        float acc[2][4] = {};
#pragma unroll
        for (int kk = 0; kk < 64; kk += 16) {
            unsigned a[4];
            a[0] = lds_u32(&kbuf[s][wm + g][kk + tg * 2]);
            a[1] = lds_u32(&kbuf[s][wm + g + 8][kk + tg * 2]);
            a[2] = lds_u32(&kbuf[s][wm + g][kk + tg * 2 + 8]);
            a[3] = lds_u32(&kbuf[s][wm + g + 8][kk + tg * 2 + 8]);
#pragma unroll
            for (int in_ = 0; in_ < 2; in_++) {
                unsigned bb[2];
                bb[0] = lds_u32(&qbuf[s][wn + in_ * 8 + g][kk + tg * 2]);
                bb[1] = lds_u32(&qbuf[s][wn + in_ * 8 + g][kk + tg * 2 + 8]);
                mma16(acc[in_], a, bb);
            }
        }
        sc[h][0] = __floats2half2_rn(acc[0][0], acc[0][1]);
        sc[h][1] = __floats2half2_rn(acc[0][2], acc[0][3]);
        sc[h][2] = __floats2half2_rn(acc[1][0], acc[1][1]);
        sc[h][3] = __floats2half2_rn(acc[1][2], acc[1][3]);
        __syncthreads();
    }
#undef ISSUE

    float gm[NH], be[NH];
#pragma unroll
    for (int h = 0; h < NH; h++) { gm[h] = gamma[h]; be[h] = beta[h]; }

    __half* ob = att + (long long)b * NH * LL + (long long)I0 * L + J0;
#pragma unroll
    for (int p = 0; p < 4; p++) {
        int i = wm + g + ((p & 1) ? 8 : 0);
        int j = wn + ((p >> 1) ? 8 : 0) + tg * 2;
        float vx[NH], vy[NH];
        float mux = 0.f, muy = 0.f;
#pragma unroll
        for (int h = 0; h < NH; h++) {
            float2 f = __half22float2(sc[h][p]);
            vx[h] = f.x; vy[h] = f.y; mux += f.x; muy += f.y;
        }
        mux *= (1.f / NH); muy *= (1.f / NH);
        float varx = 0.f, vary = 0.f;
#pragma unroll
        for (int h = 0; h < NH; h++) {
            float dx = vx[h] - mux, dy = vy[h] - muy;
            varx += dx * dx; vary += dy * dy;
        }
        float rsx = rsqrtf(varx * (1.f / NH) + 1e-5f);
        float rsy = rsqrtf(vary * (1.f / NH) + 1e-5f);
#pragma unroll
        for (int h = 0; h < NH; h++) {
            *(__half2*)&ob[(long long)h * LL + (long long)i * L + j] =
                __floats2half2_rn((vx[h] - mux) * rsx * gm[h] + be[h],
                                  (vy[h] - muy) * rsy * gm[h] + be[h]);
        }
    }
}

// ---------------- 4. fused softmax + colsum + att@V (fp16 out) ----------------
#define SMATTV_SMEM (64*520*2 + 2*64*72*2)   // 84992
__global__ void __launch_bounds__(256)
smattv_k(const __half* __restrict__ att, const __half* __restrict__ vt,
         __half* __restrict__ out, float* __restrict__ col) {
    extern __shared__ __align__(16) char smem_raw[];
    __half (*satt)[520] = (__half(*)[520])smem_raw;
    __half (*vbuf)[64][72] = (__half(*)[64][72])(smem_raw + 64*520*2);

    const int tid = threadIdx.x;
    const int wid = tid >> 5, lane = tid & 31;
    const int g = lane >> 2, tg = lane & 3;
    const int wm = (wid >> 1) * 16, wn = (wid & 1) * 32;
    const int I0 = blockIdx.x * 64;
    const int z = blockIdx.y;
    const int b = z / NH, h = z % NH;

    const __half* abase = att + (long long)z * LL + (long long)I0 * L;
    const __half* vbase = vt + (long long)z * HD * L;

#pragma unroll
    for (int c = 0; c < 16; c++) {
        int idx = tid + c * 256;
        int r = idx >> 6, jc = idx & 63;
        cpasync16(&satt[r][jc * 8], abase + (long long)r * L + jc * 8);
    }
    cpcommit();

#define ISSUEV(kt, s)                                                            \
    {                                                                            \
        _Pragma("unroll")                                                        \
        for (int c = 0; c < 2; c++) {                                            \
            int idx = tid + c * 256;                                             \
            int r = idx >> 3, jc = idx & 7;                                      \
            cpasync16(&vbuf[s][r][jc * 8], vbase + (long long)r * L + (kt) * 64 + jc * 8); \
        }                                                                        \
    }
    ISSUEV(0, 0); cpcommit();
    cpwait1();
    __syncthreads();

    for (int k = 0; k < 8; k++) {
        int r = wid * 8 + k;
        float v[16];
        float m = -1e30f;
#pragma unroll
        for (int q = 0; q < 8; q++) {
            float2 f = __half22float2(*(__half2*)&satt[r][lane * 2 + q * 64]);
            v[2 * q] = f.x; v[2 * q + 1] = f.y;
            m = fmaxf(m, fmaxf(f.x, f.y));
        }
#pragma unroll
        for (int o = 16; o; o >>= 1) m = fmaxf(m, __shfl_xor_sync(0xffffffffu, m, o));
        float s = 0.f;
#pragma unroll
        for (int q = 0; q < 16; q++) { v[q] = __expf(v[q] - m); s += v[q]; }
#pragma unroll
        for (int o = 16; o; o >>= 1) s += __shfl_xor_sync(0xffffffffu, s, o);
        float inv = 1.f / s;
#pragma unroll
        for (int q = 0; q < 8; q++)
            *(__half2*)&satt[r][lane * 2 + q * 64] =
                __floats2half2_rn(v[2 * q] * inv, v[2 * q + 1] * inv);
    }
    __syncthreads();

    {
        int j = tid * 2;
        float c0 = 0.f, c1 = 0.f;
#pragma unroll 8
        for (int r = 0; r < 64; r++) {
            float2 f = __half22float2(*(__half2*)&satt[r][j]);
            c0 += f.x; c1 += f.y;
        }
        atomicAdd(&col[b * L + j], c0 * (1.f / NH));
        atomicAdd(&col[b * L + j + 1], c1 * (1.f / NH));
    }

    float acc[4][4] = {};
    int rs = 0;
    for (int kt = 0; kt < 8; kt++) {
        if (kt + 1 < 8) ISSUEV(kt + 1, rs ^ 1);
        cpcommit();
        cpwait1();
        __syncthreads();
#pragma unroll
        for (int kk = 0; kk < 64; kk += 16) {
            unsigned a[4];
            int kc = kt * 64 + kk + tg * 2;
            a[0] = lds_u32(&satt[wm + g][kc]);
            a[1] = lds_u32(&satt[wm + g + 8][kc]);
            a[2] = lds_u32(&satt[wm + g][kc + 8]);
            a[3] = lds_u32(&satt[wm + g + 8][kc + 8]);
#pragma unroll
            for (int in_ = 0; in_ < 4; in_++) {
                unsigned bb[2];
                bb[0] = lds_u32(&vbuf[rs][wn + in_ * 8 + g][kk + tg * 2]);
                bb[1] = lds_u32(&vbuf[rs][wn + in_ * 8 + g][kk + tg * 2 + 8]);
                mma16(acc[in_], a, bb);
            }
        }
        rs ^= 1;
        __syncthreads();
    }
#undef ISSUEV

    __half* ob = out + ((long long)b * L + I0) * D + h * HD;
#pragma unroll
    for (int in_ = 0; in_ < 4; in_++) {
        int c = wn + in_ * 8 + tg * 2;
        *(__half2*)&ob[(long long)(wm + g) * D + c] =
            __floats2half2_rn(acc[in_][0], acc[in_][1]);
        *(__half2*)&ob[(long long)(wm + g + 8) * D + c] =
            __floats2half2_rn(acc[in_][2], acc[in_][3]);
    }
}

// ---------------- 5. per-token class probs (fp16 input) ----------------
__global__ void probs_k(const __half* __restrict__ out, const float* __restrict__ Wout,
                        const float* __restrict__ bout, float* __restrict__ probs) {
    int bl = blockIdx.x;
    int warp = threadIdx.x >> 5, lane = threadIdx.x & 31;
    __shared__ float s[NC];
    __shared__ float mx, sum;
    const __half* row = out + (long long)bl * D;
#pragma unroll
    for (int cc = 0; cc < 4; cc++) {
        int c = warp * 4 + cc;
        const float* w = Wout + c * D;
        float acc = 0.f;
        for (int k = lane * 2; k < D; k += 64) {
            float2 f = __half22float2(*(const __half2*)(row + k));
            acc += f.x * w[k] + f.y * w[k + 1];
        }
#pragma unroll
        for (int o = 16; o; o >>= 1) acc += __shfl_down_sync(0xffffffffu, acc, o);
        if (lane == 0) s[c] = acc + bout[c];
    }
    __syncthreads();
    if (threadIdx.x == 0) {
        float m = -1e30f;
        for (int c = 0; c < NC; c++) m = fmaxf(m, s[c]);
        float ss = 0.f;
        for (int c = 0; c < NC; c++) ss += __expf(s[c] - m);
        mx = m; sum = ss;
    }
    __syncthreads();
    if (threadIdx.x < NC)
        probs[(long long)bl * NC + threadIdx.x] = __expf(s[threadIdx.x] - mx) / sum;
}

// ---------------- 6. fused token weights softmax + final reduce ----------------
__global__ void __launch_bounds__(512)
wfinal_k(const int* __restrict__ ids, const float* __restrict__ col,
         const float* __restrict__ probs, float* __restrict__ dout, int first) {
    int b = blockIdx.x, l = threadIdx.x;
    int wid = l >> 5, lane = l & 31;
    __shared__ float red[512];
    __shared__ float psum[16][NC];

    float w = (ids[b * L + l] != 0 ? 1.f : 0.f) * col[b * L + l];
    red[l] = w;
    __syncthreads();
    for (int o = 256; o; o >>= 1) { if (l < o) red[l] = fmaxf(red[l], red[l + o]); __syncthreads(); }
    float mxv = red[0];
    __syncthreads();
    float e = __expf(w - mxv);
    red[l] = e;
    __syncthreads();
    for (int o = 256; o; o >>= 1) { if (l < o) red[l] += red[l + o]; __syncthreads(); }
    float wg = e / red[0];

    const float* pb = probs + (long long)(b * L + l) * NC;
    float myp[NC];
#pragma unroll
    for (int c = 0; c < NC; c++) myp[c] = wg * pb[c];
#pragma unroll
    for (int c = 0; c < NC; c++) {
        float v = myp[c];
#pragma unroll
        for (int o = 16; o; o >>= 1) v += __shfl_xor_sync(0xffffffffu, v, o);
        if (lane == 0) psum[wid][c] = v;
    }
    __syncthreads();
    if (l < NC) {
        float s = 0.f;
#pragma unroll
        for (int q = 0; q < 16; q++) s += psum[q][l];
        float v = 0.5f * s;
        dout[b * NC + l] = first ? v : dout[b * NC + l] + v;
    }
}

// ---------------- launch ----------------
extern "C" void kernel_launch(void* const* d_in, const int* in_sizes, int n_in,
                              void* d_out, int out_size) {
    (void)in_sizes; (void)n_in; (void)out_size;
    const int*   ids   = (const int*)d_in[0];
    const float* wv    = (const float*)d_in[1];
    const float* emb   = (const float*)d_in[2];
    const float* W_t   = (const float*)d_in[3];
    const float* b_t   = (const float*)d_in[4];
    const float* gam_t = (const float*)d_in[5];
    const float* bet_t = (const float*)d_in[6];
    const float* Wo_t  = (const float*)d_in[7];
    const float* bo_t  = (const float*)d_in[8];
    const float* W_h   = (const float*)d_in[9];
    const float* b_h   = (const float*)d_in[10];
    const float* gam_h = (const float*)d_in[11];
    const float* bet_h = (const float*)d_in[12];
    const float* Wo_h  = (const float*)d_in[13];
    const float* bo_h  = (const float*)d_in[14];
    float* out = (float*)d_out;

    __half *px, *pwt, *pwh, *pwv, *patt16, *pqn, *pkn, *pvt, *pout;
    __half *patt16_2, *pqn2, *pkn2, *pvt2, *pout2;
    float *pprobs, *pcol, *pprobs2, *pcol2;
    cudaGetSymbolAddress((void**)&px, g_x);
    cudaGetSymbolAddress((void**)&pwt, g_wt16);
    cudaGetSymbolAddress((void**)&pwh, g_wh16);
    cudaGetSymbolAddress((void**)&pwv, g_wv16);
    cudaGetSymbolAddress((void**)&patt16, g_att16);
    cudaGetSymbolAddress((void**)&pqn, g_qn);
    cudaGetSymbolAddress((void**)&pkn, g_kn);
    cudaGetSymbolAddress((void**)&pvt, g_vt);
    cudaGetSymbolAddress((void**)&pout, g_out);
    cudaGetSymbolAddress((void**)&pprobs, g_probs);
    cudaGetSymbolAddress((void**)&pcol, g_col);
    cudaGetSymbolAddress((void**)&patt16_2, g_att16_2);
    cudaGetSymbolAddress((void**)&pqn2, g_qn2);
    cudaGetSymbolAddress((void**)&pkn2, g_kn2);
    cudaGetSymbolAddress((void**)&pvt2, g_vt2);
    cudaGetSymbolAddress((void**)&pout2, g_out2);
    cudaGetSymbolAddress((void**)&pprobs2, g_probs2);
    cudaGetSymbolAddress((void**)&pcol2, g_col2);

    cudaFuncSetAttribute(smattv_k, cudaFuncAttributeMaxDynamicSharedMemorySize, SMATTV_SMEM);

    dim3 proj_grid(D3 / 128, BL / 128);
    dim3 attln_grid(L / 32, L / 64, Bsz);
    dim3 smattv_grid(L / 64, BH);

    // Fork a second stream for the independent hidden branch (graph-capturable;
    // created per call, intentionally not destroyed — see R7 notes).
    cudaStream_t s2;
    cudaStreamCreateWithFlags(&s2, cudaStreamNonBlocking);
    cudaEvent_t evFork, evJoin;
    cudaEventCreateWithFlags(&evFork, cudaEventDisableTiming);
    cudaEventCreateWithFlags(&evJoin, cudaEventDisableTiming);

    cudaEventRecord(evFork, 0);
    cudaStreamWaitEvent(s2, evFork, 0);

    // ===== token branch (main stream) =====
    embed_leaky_k<<<BL, 192>>>(ids, emb, px);
    convpad_k<<<D3, 192>>>(W_t, pwt, D, D);
    projsplit_k<<<proj_grid, 256>>>(px, D, pwt, D, b_t, pqn, pkn, pvt, pcol, D);
    attln2_k<<<attln_grid, 256>>>(pkn, pqn, patt16, gam_t, bet_t);
    smattv_k<<<smattv_grid, 256, SMATTV_SMEM>>>(patt16, pvt, pout, pcol);
    probs_k<<<BL, 160>>>(pout, Wo_t, bo_t, pprobs);
    wfinal_k<<<Bsz, 512>>>(ids, pcol, pprobs, out, 1);

    // ===== hidden / word-vector branch (stream s2) =====
    convpad_k<<<D3, 128, 0, s2>>>(W_h, pwh, 300, KH);
    convpad_k<<<BL, 128, 0, s2>>>(wv, pwv, 300, KH);
    projsplit_k<<<proj_grid, 256, 0, s2>>>(pwv, KH, pwh, KH, b_h, pqn2, pkn2, pvt2, pcol2, KH);
    attln2_k<<<attln_grid, 256, 0, s2>>>(pkn2, pqn2, patt16_2, gam_h, bet_h);
    smattv_k<<<smattv_grid, 256, SMATTV_SMEM, s2>>>(patt16_2, pvt2, pout2, pcol2);
    probs_k<<<BL, 160, 0, s2>>>(pout2, Wo_h, bo_h, pprobs2);

    // join: hidden-branch results folded into d_out on the main stream
    cudaEventRecord(evJoin, s2);
    cudaStreamWaitEvent(0, evJoin, 0);
    wfinal_k<<<Bsz, 512>>>(ids, pcol2, pprobs2, out, 0);
}

// round 11
// speedup vs baseline: 6.4458x; 1.0063x over previous
#include <cuda_runtime.h>
#include <cuda_fp16.h>
#include <math.h>

#define Bsz 16
#define L   512
#define NH  12
#define HD  64
#define D   768
#define D3  2304
#define NC  20
#define BL  (Bsz*L)      // 8192
#define BH  (Bsz*NH)     // 192
#define LL  (L*L)        // 262144
#define KH  320          // padded K for hidden branch (300 -> 320)

// ---------------- scratch (allocation-free) ----------------
// token branch
__device__ __half g_x[(size_t)BL*D];
__device__ __half g_wt16[(size_t)D3*D];
__device__ __half g_att16[(size_t)BH*LL];
__device__ __half g_qn[(size_t)BH*L*HD];
__device__ __half g_kn[(size_t)BH*L*HD];
__device__ __half g_vt[(size_t)BH*HD*L];      // V transposed [z][d][l]
__device__ __half g_out[(size_t)BL*D];
__device__ float  g_probs[(size_t)BL*NC];
__device__ float  g_col[BL];
// hidden branch (independent copies so both branches run concurrently)
__device__ __half g_wh16[(size_t)D3*KH];
__device__ __half g_wv16[(size_t)BL*KH];
__device__ __half g_att16_2[(size_t)BH*LL];
__device__ __half g_qn2[(size_t)BH*L*HD];
__device__ __half g_kn2[(size_t)BH*L*HD];
__device__ __half g_vt2[(size_t)BH*HD*L];
__device__ __half g_out2[(size_t)BL*D];
__device__ float  g_probs2[(size_t)BL*NC];
__device__ float  g_col2[BL];

__device__ __forceinline__ float lrelu(float x) { return x >= 0.f ? x : 0.01f * x; }

__device__ __forceinline__ void mma16(float c[4], const unsigned a[4], const unsigned b[2]) {
    asm volatile(
        "mma.sync.aligned.m16n8k16.row.col.f32.f16.f16.f32 "
        "{%0,%1,%2,%3},{%4,%5,%6,%7},{%8,%9},{%0,%1,%2,%3};"
        : "+f"(c[0]), "+f"(c[1]), "+f"(c[2]), "+f"(c[3])
        : "r"(a[0]), "r"(a[1]), "r"(a[2]), "r"(a[3]), "r"(b[0]), "r"(b[1]));
}
__device__ __forceinline__ unsigned lds_u32(const __half* p) { return *(const unsigned*)p; }
__device__ __forceinline__ void cpasync16(void* smem, const void* gmem) {
    unsigned s = (unsigned)__cvta_generic_to_shared(smem);
    asm volatile("cp.async.cg.shared.global [%0], [%1], 16;\n" :: "r"(s), "l"(gmem));
}
__device__ __forceinline__ void cpcommit() { asm volatile("cp.async.commit_group;\n"); }
__device__ __forceinline__ void cpwait1()  { asm volatile("cp.async.wait_group 1;\n"); }
__device__ __forceinline__ void cpwait2()  { asm volatile("cp.async.wait_group 2;\n"); }

// ---------------- 0. fp32 -> fp16 (optionally K-padded rows) ----------------
__global__ void convpad_k(const float* __restrict__ src, __half* __restrict__ dst,
                          int K, int KP) {
    long long row = blockIdx.x;
    for (int k4 = threadIdx.x * 4; k4 < KP; k4 += blockDim.x * 4) {
        float4 v = (k4 + 4 <= K) ? *(const float4*)(src + row * K + k4)
                                 : make_float4(k4 < K ? src[row * K + k4] : 0.f,
                                               k4 + 1 < K ? src[row * K + k4 + 1] : 0.f,
                                               k4 + 2 < K ? src[row * K + k4 + 2] : 0.f,
                                               k4 + 3 < K ? src[row * K + k4 + 3] : 0.f);
        *(__half2*)(dst + row * KP + k4)     = __floats2half2_rn(v.x, v.y);
        *(__half2*)(dst + row * KP + k4 + 2) = __floats2half2_rn(v.z, v.w);
    }
}

// ---------------- 1. embedding + leaky -> fp16 ----------------
__global__ void embed_leaky_k(const int* __restrict__ ids, const float* __restrict__ emb,
                              __half* __restrict__ x) {
    int bl = blockIdx.x;
    long long id = ids[bl];
    const float* src = emb + id * D;
    __half* dst = x + (long long)bl * D;
    for (int k4 = threadIdx.x * 4; k4 < D; k4 += blockDim.x * 4) {
        float4 v = *(const float4*)(src + k4);
        *(__half2*)(dst + k4)     = __floats2half2_rn(lrelu(v.x), lrelu(v.y));
        *(__half2*)(dst + k4 + 2) = __floats2half2_rn(lrelu(v.z), lrelu(v.w));
    }
}

// ---------------- 2. fused proj GEMM + QKV split + cosine-norm + V transpose ----------------
__global__ void __launch_bounds__(256)
projsplit_k(const __half* __restrict__ A, int lda,
            const __half* __restrict__ W, int ldb,
            const float* __restrict__ bias,
            __half* __restrict__ qn, __half* __restrict__ kn,
            __half* __restrict__ vt, float* __restrict__ col, int K) {
    constexpr int BM = 128, BN = 128, WM = 32, WN = 64, BK = 32, PAD = 8, STG = 3;
    constexpr int IM = 2, IN = 8;

    __shared__ __align__(16) __half As[STG][BM][BK + PAD];
    __shared__ __align__(16) __half Bs[STG][BN][BK + PAD];

    const int tid = threadIdx.x;
    const int wid = tid >> 5, lane = tid & 31;
    const int g = lane >> 2, tg = lane & 3;
    const int wm = (wid >> 1) * WM, wn = (wid & 1) * WN;

    const __half* Ab = A + (long long)blockIdx.y * BM * lda;
    const __half* Bb = W + (long long)blockIdx.x * BN * ldb;

    const int ktiles = K / BK;
    float acc[IM][IN][4] = {};

    auto issue = [&](int t, int s) {
        int k0 = t * BK;
#pragma unroll
        for (int c = 0; c < 2; c++) {
            int idx = tid + c * 256;
            int row = idx >> 2, cq = idx & 3;
            cpasync16(&As[s][row][cq * 8], Ab + (long long)row * lda + k0 + cq * 8);
        }
#pragma unroll
        for (int c = 0; c < 2; c++) {
            int idx = tid + c * 256;
            int row = idx >> 2, cq = idx & 3;
            cpasync16(&Bs[s][row][cq * 8], Bb + (long long)row * ldb + k0 + cq * 8);
        }
    };

    issue(0, 0); cpcommit();
    if (ktiles > 1) issue(1, 1);
    cpcommit();
    cpwait1();
    __syncthreads();

    int rs = 0;
    for (int t = 0; t < ktiles; t++) {
#pragma unroll
        for (int kk = 0; kk < BK; kk += 16) {
            unsigned a[IM][4], b[IN][2];
#pragma unroll
            for (int im = 0; im < IM; im++) {
                int r = wm + im * 16 + g;
                a[im][0] = lds_u32(&As[rs][r][kk + tg * 2]);
                a[im][1] = lds_u32(&As[rs][r + 8][kk + tg * 2]);
                a[im][2] = lds_u32(&As[rs][r][kk + tg * 2 + 8]);
                a[im][3] = lds_u32(&As[rs][r + 8][kk + tg * 2 + 8]);
            }
#pragma unroll
            for (int in_ = 0; in_ < IN; in_++) {
                int r = wn + in_ * 8 + g;
                b[in_][0] = lds_u32(&Bs[rs][r][kk + tg * 2]);
                b[in_][1] = lds_u32(&Bs[rs][r][kk + tg * 2 + 8]);
            }
#pragma unroll
            for (int im = 0; im < IM; im++)
#pragma unroll
                for (int in_ = 0; in_ < IN; in_++)
                    mma16(acc[im][in_], a[im], b[in_]);
        }
        if (t + 2 < ktiles) issue(t + 2, (rs + 2) % STG);
        cpcommit();
        cpwait1();
        __syncthreads();
        rs = (rs + 1) % STG;
    }

    const int sec  = blockIdx.x / 6;                       // 0=Q, 1=K, 2=V
    const int m0   = blockIdx.y * BM;
    const int b    = m0 / L;
    const int l0   = m0 % L;

    if (blockIdx.x == 12 && tid < 128) col[b * L + l0 + tid] = 0.f;

#pragma unroll
    for (int im = 0; im < IM; im++)
#pragma unroll
        for (int in_ = 0; in_ < IN; in_++) {
            int cc = blockIdx.x * BN + wn + in_ * 8 + tg * 2;
            float b0 = bias[cc], b1 = bias[cc + 1];
            acc[im][in_][0] = lrelu(acc[im][in_][0] + b0);
            acc[im][in_][1] = lrelu(acc[im][in_][1] + b1);
            acc[im][in_][2] = lrelu(acc[im][in_][2] + b0);
            acc[im][in_][3] = lrelu(acc[im][in_][3] + b1);
        }

    if (sec < 2) {
        const int hloc = (blockIdx.x % 6) * 2 + (wn >> 6);
        const long long z = (long long)b * NH + hloc;
        __half* dst = (sec == 0) ? qn : kn;
#pragma unroll
        for (int im = 0; im < IM; im++) {
            float ss0 = 0.f, ss1 = 0.f;
#pragma unroll
            for (int in_ = 0; in_ < IN; in_++) {
                ss0 += acc[im][in_][0] * acc[im][in_][0] + acc[im][in_][1] * acc[im][in_][1];
                ss1 += acc[im][in_][2] * acc[im][in_][2] + acc[im][in_][3] * acc[im][in_][3];
            }
            ss0 += __shfl_xor_sync(0xffffffffu, ss0, 1);
            ss0 += __shfl_xor_sync(0xffffffffu, ss0, 2);
            ss1 += __shfl_xor_sync(0xffffffffu, ss1, 1);
            ss1 += __shfl_xor_sync(0xffffffffu, ss1, 2);
            float r0 = 1.f / fmaxf(sqrtf(ss0), 1e-8f);
            float r1 = 1.f / fmaxf(sqrtf(ss1), 1e-8f);
            int lA = l0 + wm + im * 16 + g;
            int lB = lA + 8;
#pragma unroll
            for (int in_ = 0; in_ < IN; in_++) {
                int dcol = in_ * 8 + tg * 2;
                *(__half2*)&dst[(z * L + lA) * HD + dcol] =
                    __floats2half2_rn(acc[im][in_][0] * r0, acc[im][in_][1] * r0);
                *(__half2*)&dst[(z * L + lB) * HD + dcol] =
                    __floats2half2_rn(acc[im][in_][2] * r1, acc[im][in_][3] * r1);
            }
        }
    } else {
        __half (*sv)[136] = (__half(*)[136])Bs;
#pragma unroll
        for (int p = 0; p < 2; p++) {
            __syncthreads();
            if ((wn >> 6) == p) {
#pragma unroll
                for (int im = 0; im < IM; im++)
#pragma unroll
                    for (int in_ = 0; in_ < IN; in_++) {
                        int d = in_ * 8 + tg * 2;
                        int l = wm + im * 16 + g;
                        sv[d][l]         = __float2half_rn(acc[im][in_][0]);
                        sv[d + 1][l]     = __float2half_rn(acc[im][in_][1]);
                        sv[d][l + 8]     = __float2half_rn(acc[im][in_][2]);
                        sv[d + 1][l + 8] = __float2half_rn(acc[im][in_][3]);
                    }
            }
            __syncthreads();
            long long z = (long long)b * NH + (blockIdx.x % 6) * 2 + p;
#pragma unroll
            for (int c = 0; c < 4; c++) {
                int idx = tid + c * 256;
                int d = idx >> 4, lc = (idx & 15) * 8;
                *(uint4*)(vt + (z * HD + d) * L + l0 + lc) = *(uint4*)&sv[d][lc];
            }
        }
    }
}

// ---------------- 3. fused scores + LN(heads): 2 heads per pipeline stage ----------------
#define ATTLN3_SMEM (4*64*72*2 + 4*32*72*2)   // 55296
__global__ void __launch_bounds__(256, 2)
attln3_k(const __half* __restrict__ kn, const __half* __restrict__ qn,
         __half* __restrict__ att, const float* __restrict__ gamma,
         const float* __restrict__ beta) {
    extern __shared__ __align__(16) char smraw[];
    __half (*kbuf)[64][72] = (__half(*)[64][72])smraw;
    __half (*qbuf)[32][72] = (__half(*)[32][72])(smraw + 4*64*72*2);

    const int tid = threadIdx.x;
    const int wid = tid >> 5, lane = tid & 31;
    const int g = lane >> 2, tg = lane & 3;
    const int wm = (wid >> 1) * 16, wn = (wid & 1) * 16;
    const int J0 = blockIdx.x * 32, I0 = blockIdx.y * 64, b = blockIdx.z;

    const __half* kb = kn + ((long long)b * NH * L + I0) * HD;
    const __half* qb = qn + ((long long)b * NH * L + J0) * HD;

    __half2 sc[NH][4];

#define ISSUE(h)                                                                  \
    {                                                                             \
        int s_ = (h) & 3;                                                         \
        long long hoff = (long long)(h) * L * HD;                                 \
        _Pragma("unroll")                                                         \
        for (int c = 0; c < 2; c++) {                                             \
            int idx = tid + c * 256;                                              \
            int r = idx >> 3, jc = idx & 7;                                       \
            cpasync16(&kbuf[s_][r][jc * 8], kb + hoff + (long long)r * HD + jc * 8); \
        }                                                                         \
        { int r = tid >> 3, jc = tid & 7;                                         \
          cpasync16(&qbuf[s_][r][jc * 8], qb + hoff + (long long)r * HD + jc * 8); } \
        cpcommit();                                                               \
    }

#define COMPUTE(h)                                                                \
    {                                                                             \
        int s_ = (h) & 3;                                                         \
        float acc[2][4] = {};                                                     \
        _Pragma("unroll")                                                         \
        for (int kk = 0; kk < 64; kk += 16) {                                     \
            unsigned a[4];                                                        \
            a[0] = lds_u32(&kbuf[s_][wm + g][kk + tg * 2]);                       \
            a[1] = lds_u32(&kbuf[s_][wm + g + 8][kk + tg * 2]);                   \
            a[2] = lds_u32(&kbuf[s_][wm + g][kk + tg * 2 + 8]);                   \
            a[3] = lds_u32(&kbuf[s_][wm + g + 8][kk + tg * 2 + 8]);               \
            _Pragma("unroll")                                                     \
            for (int in_ = 0; in_ < 2; in_++) {                                   \
                unsigned bb[2];                                                   \
                bb[0] = lds_u32(&qbuf[s_][wn + in_ * 8 + g][kk + tg * 2]);        \
                bb[1] = lds_u32(&qbuf[s_][wn + in_ * 8 + g][kk + tg * 2 + 8]);    \
                mma16(acc[in_], a, bb);                                           \
            }                                                                     \
        }                                                                         \
        sc[h][0] = __floats2half2_rn(acc[0][0], acc[0][1]);                       \
        sc[h][1] = __floats2half2_rn(acc[0][2], acc[0][3]);                       \
        sc[h][2] = __floats2half2_rn(acc[1][0], acc[1][1]);                       \
        sc[h][3] = __floats2half2_rn(acc[1][2], acc[1][3]);                       \
    }

    ISSUE(0); ISSUE(1); ISSUE(2); ISSUE(3);
    cpwait2();            // pair 0 (heads 0,1) resident
    __syncthreads();

#pragma unroll
    for (int p = 0; p < 6; p++) {
        COMPUTE(2 * p);
        COMPUTE(2 * p + 1);
        __syncthreads();                   // all warps done reading pair p's buffers
        if (p + 2 < 6) {
            ISSUE(2 * p + 4);              // reuses pair p's buffer slots
            ISSUE(2 * p + 5);
        } else {
            cpcommit(); cpcommit();        // keep group accounting uniform
        }
        cpwait2();                         // pair p+1 resident
        __syncthreads();
    }
#undef ISSUE
#undef COMPUTE

    float gm[NH], be[NH];
#pragma unroll
    for (int h = 0; h < NH; h++) { gm[h] = gamma[h]; be[h] = beta[h]; }

    __half* ob = att + (long long)b * NH * LL + (long long)I0 * L + J0;
#pragma unroll
    for (int p = 0; p < 4; p++) {
        int i = wm + g + ((p & 1) ? 8 : 0);
        int j = wn + ((p >> 1) ? 8 : 0) + tg * 2;
        float vx[NH], vy[NH];
        float mux = 0.f, muy = 0.f;
#pragma unroll
        for (int h = 0; h < NH; h++) {
            float2 f = __half22float2(sc[h][p]);
            vx[h] = f.x; vy[h] = f.y; mux += f.x; muy += f.y;
        }
        mux *= (1.f / NH); muy *= (1.f / NH);
        float varx = 0.f, vary = 0.f;
#pragma unroll
        for (int h = 0; h < NH; h++) {
            float dx = vx[h] - mux, dy = vy[h] - muy;
            varx += dx * dx; vary += dy * dy;
        }
        float rsx = rsqrtf(varx * (1.f / NH) + 1e-5f);
        float rsy = rsqrtf(vary * (1.f / NH) + 1e-5f);
#pragma unroll
        for (int h = 0; h < NH; h++) {
            *(__half2*)&ob[(long long)h * LL + (long long)i * L + j] =
                __floats2half2_rn((vx[h] - mux) * rsx * gm[h] + be[h],
                                  (vy[h] - muy) * rsy * gm[h] + be[h]);
        }
    }
}

// ---------------- 4. fused softmax + colsum + att@V (fp16 out) ----------------
#define SMATTV_SMEM (64*520*2 + 2*64*72*2)   // 84992
__global__ void __launch_bounds__(256)
smattv_k(const __half* __restrict__ att, const __half* __restrict__ vt,
         __half* __restrict__ out, float* __restrict__ col) {
    extern __shared__ __align__(16) char smem_raw[];
    __half (*satt)[520] = (__half(*)[520])smem_raw;
    __half (*vbuf)[64][72] = (__half(*)[64][72])(smem_raw + 64*520*2);

    const int tid = threadIdx.x;
    const int wid = tid >> 5, lane = tid & 31;
    const int g = lane >> 2, tg = lane & 3;
    const int wm = (wid >> 1) * 16, wn = (wid & 1) * 32;
    const int I0 = blockIdx.x * 64;
    const int z = blockIdx.y;
    const int b = z / NH, h = z % NH;

    const __half* abase = att + (long long)z * LL + (long long)I0 * L;
    const __half* vbase = vt + (long long)z * HD * L;

#pragma unroll
    for (int c = 0; c < 16; c++) {
        int idx = tid + c * 256;
        int r = idx >> 6, jc = idx & 63;
        cpasync16(&satt[r][jc * 8], abase + (long long)r * L + jc * 8);
    }
    cpcommit();

#define ISSUEV(kt, s)                                                            \
    {                                                                            \
        _Pragma("unroll")                                                        \
        for (int c = 0; c < 2; c++) {                                            \
            int idx = tid + c * 256;                                             \
            int r = idx >> 3, jc = idx & 7;                                      \
            cpasync16(&vbuf[s][r][jc * 8], vbase + (long long)r * L + (kt) * 64 + jc * 8); \
        }                                                                        \
    }
    ISSUEV(0, 0); cpcommit();
    cpwait1();
    __syncthreads();

    for (int k = 0; k < 8; k++) {
        int r = wid * 8 + k;
        float v[16];
        float m = -1e30f;
#pragma unroll
        for (int q = 0; q < 8; q++) {
            float2 f = __half22float2(*(__half2*)&satt[r][lane * 2 + q * 64]);
            v[2 * q] = f.x; v[2 * q + 1] = f.y;
            m = fmaxf(m, fmaxf(f.x, f.y));
        }
#pragma unroll
        for (int o = 16; o; o >>= 1) m = fmaxf(m, __shfl_xor_sync(0xffffffffu, m, o));
        float s = 0.f;
#pragma unroll
        for (int q = 0; q < 16; q++) { v[q] = __expf(v[q] - m); s += v[q]; }
#pragma unroll
        for (int o = 16; o; o >>= 1) s += __shfl_xor_sync(0xffffffffu, s, o);
        float inv = 1.f / s;
#pragma unroll
        for (int q = 0; q < 8; q++)
            *(__half2*)&satt[r][lane * 2 + q * 64] =
                __floats2half2_rn(v[2 * q] * inv, v[2 * q + 1] * inv);
    }
    __syncthreads();

    {
        int j = tid * 2;
        float c0 = 0.f, c1 = 0.f;
#pragma unroll 8
        for (int r = 0; r < 64; r++) {
            float2 f = __half22float2(*(__half2*)&satt[r][j]);
            c0 += f.x; c1 += f.y;
        }
        atomicAdd(&col[b * L + j], c0 * (1.f / NH));
        atomicAdd(&col[b * L + j + 1], c1 * (1.f / NH));
    }

    float acc[4][4] = {};
    int rs = 0;
    for (int kt = 0; kt < 8; kt++) {
        if (kt + 1 < 8) ISSUEV(kt + 1, rs ^ 1);
        cpcommit();
        cpwait1();
        __syncthreads();
#pragma unroll
        for (int kk = 0; kk < 64; kk += 16) {
            unsigned a[4];
            int kc = kt * 64 + kk + tg * 2;
            a[0] = lds_u32(&satt[wm + g][kc]);
            a[1] = lds_u32(&satt[wm + g + 8][kc]);
            a[2] = lds_u32(&satt[wm + g][kc + 8]);
            a[3] = lds_u32(&satt[wm + g + 8][kc + 8]);
#pragma unroll
            for (int in_ = 0; in_ < 4; in_++) {
                unsigned bb[2];
                bb[0] = lds_u32(&vbuf[rs][wn + in_ * 8 + g][kk + tg * 2]);
                bb[1] = lds_u32(&vbuf[rs][wn + in_ * 8 + g][kk + tg * 2 + 8]);
                mma16(acc[in_], a, bb);
            }
        }
        rs ^= 1;
        __syncthreads();
    }
#undef ISSUEV

    __half* ob = out + ((long long)b * L + I0) * D + h * HD;
#pragma unroll
    for (int in_ = 0; in_ < 4; in_++) {
        int c = wn + in_ * 8 + tg * 2;
        *(__half2*)&ob[(long long)(wm + g) * D + c] =
            __floats2half2_rn(acc[in_][0], acc[in_][1]);
        *(__half2*)&ob[(long long)(wm + g + 8) * D + c] =
            __floats2half2_rn(acc[in_][2], acc[in_][3]);
    }
}

// ---------------- 5. per-token class probs (fp16 input) ----------------
__global__ void probs_k(const __half* __restrict__ out, const float* __restrict__ Wout,
                        const float* __restrict__ bout, float* __restrict__ probs) {
    int bl = blockIdx.x;
    int warp = threadIdx.x >> 5, lane = threadIdx.x & 31;
    __shared__ float s[NC];
    __shared__ float mx, sum;
    const __half* row = out + (long long)bl * D;
#pragma unroll
    for (int cc = 0; cc < 4; cc++) {
        int c = warp * 4 + cc;
        const float* w = Wout + c * D;
        float acc = 0.f;
        for (int k = lane * 2; k < D; k += 64) {
            float2 f = __half22float2(*(const __half2*)(row + k));
            acc += f.x * w[k] + f.y * w[k + 1];
        }
#pragma unroll
        for (int o = 16; o; o >>= 1) acc += __shfl_down_sync(0xffffffffu, acc, o);
        if (lane == 0) s[c] = acc + bout[c];
    }
    __syncthreads();
    if (threadIdx.x == 0) {
        float m = -1e30f;
        for (int c = 0; c < NC; c++) m = fmaxf(m, s[c]);
        float ss = 0.f;
        for (int c = 0; c < NC; c++) ss += __expf(s[c] - m);
        mx = m; sum = ss;
    }
    __syncthreads();
    if (threadIdx.x < NC)
        probs[(long long)bl * NC + threadIdx.x] = __expf(s[threadIdx.x] - mx) / sum;
}

// ---------------- 6. fused token weights softmax + final reduce ----------------
__global__ void __launch_bounds__(512)
wfinal_k(const int* __restrict__ ids, const float* __restrict__ col,
         const float* __restrict__ probs, float* __restrict__ dout, int first) {
    int b = blockIdx.x, l = threadIdx.x;
    int wid = l >> 5, lane = l & 31;
    __shared__ float red[512];
    __shared__ float psum[16][NC];

    float w = (ids[b * L + l] != 0 ? 1.f : 0.f) * col[b * L + l];
    red[l] = w;
    __syncthreads();
    for (int o = 256; o; o >>= 1) { if (l < o) red[l] = fmaxf(red[l], red[l + o]); __syncthreads(); }
    float mxv = red[0];
    __syncthreads();
    float e = __expf(w - mxv);
    red[l] = e;
    __syncthreads();
    for (int o = 256; o; o >>= 1) { if (l < o) red[l] += red[l + o]; __syncthreads(); }
    float wg = e / red[0];

    const float* pb = probs + (long long)(b * L + l) * NC;
    float myp[NC];
#pragma unroll
    for (int c = 0; c < NC; c++) myp[c] = wg * pb[c];
#pragma unroll
    for (int c = 0; c < NC; c++) {
        float v = myp[c];
#pragma unroll
        for (int o = 16; o; o >>= 1) v += __shfl_xor_sync(0xffffffffu, v, o);
        if (lane == 0) psum[wid][c] = v;
    }
    __syncthreads();
    if (l < NC) {
        float s = 0.f;
#pragma unroll
        for (int q = 0; q < 16; q++) s += psum[q][l];
        float v = 0.5f * s;
        dout[b * NC + l] = first ? v : dout[b * NC + l] + v;
    }
}

// ---------------- launch ----------------
extern "C" void kernel_launch(void* const* d_in, const int* in_sizes, int n_in,
                              void* d_out, int out_size) {
    (void)in_sizes; (void)n_in; (void)out_size;
    const int*   ids   = (const int*)d_in[0];
    const float* wv    = (const float*)d_in[1];
    const float* emb   = (const float*)d_in[2];
    const float* W_t   = (const float*)d_in[3];
    const float* b_t   = (const float*)d_in[4];
    const float* gam_t = (const float*)d_in[5];
    const float* bet_t = (const float*)d_in[6];
    const float* Wo_t  = (const float*)d_in[7];
    const float* bo_t  = (const float*)d_in[8];
    const float* W_h   = (const float*)d_in[9];
    const float* b_h   = (const float*)d_in[10];
    const float* gam_h = (const float*)d_in[11];
    const float* bet_h = (const float*)d_in[12];
    const float* Wo_h  = (const float*)d_in[13];
    const float* bo_h  = (const float*)d_in[14];
    float* out = (float*)d_out;

    __half *px, *pwt, *pwh, *pwv, *patt16, *pqn, *pkn, *pvt, *pout;
    __half *patt16_2, *pqn2, *pkn2, *pvt2, *pout2;
    float *pprobs, *pcol, *pprobs2, *pcol2;
    cudaGetSymbolAddress((void**)&px, g_x);
    cudaGetSymbolAddress((void**)&pwt, g_wt16);
    cudaGetSymbolAddress((void**)&pwh, g_wh16);
    cudaGetSymbolAddress((void**)&pwv, g_wv16);
    cudaGetSymbolAddress((void**)&patt16, g_att16);
    cudaGetSymbolAddress((void**)&pqn, g_qn);
    cudaGetSymbolAddress((void**)&pkn, g_kn);
    cudaGetSymbolAddress((void**)&pvt, g_vt);
    cudaGetSymbolAddress((void**)&pout, g_out);
    cudaGetSymbolAddress((void**)&pprobs, g_probs);
    cudaGetSymbolAddress((void**)&pcol, g_col);
    cudaGetSymbolAddress((void**)&patt16_2, g_att16_2);
    cudaGetSymbolAddress((void**)&pqn2, g_qn2);
    cudaGetSymbolAddress((void**)&pkn2, g_kn2);
    cudaGetSymbolAddress((void**)&pvt2, g_vt2);
    cudaGetSymbolAddress((void**)&pout2, g_out2);
    cudaGetSymbolAddress((void**)&pprobs2, g_probs2);
    cudaGetSymbolAddress((void**)&pcol2, g_col2);

    cudaFuncSetAttribute(smattv_k, cudaFuncAttributeMaxDynamicSharedMemorySize, SMATTV_SMEM);
    cudaFuncSetAttribute(attln3_k, cudaFuncAttributeMaxDynamicSharedMemorySize, ATTLN3_SMEM);

    dim3 proj_grid(D3 / 128, BL / 128);
    dim3 attln_grid(L / 32, L / 64, Bsz);
    dim3 smattv_grid(L / 64, BH);

    // Fork a second stream for the independent hidden branch (graph-capturable;
    // created per call, intentionally not destroyed — see R7 notes).
    cudaStream_t s2;
    cudaStreamCreateWithFlags(&s2, cudaStreamNonBlocking);
    cudaEvent_t evFork, evJoin;
    cudaEventCreateWithFlags(&evFork, cudaEventDisableTiming);
    cudaEventCreateWithFlags(&evJoin, cudaEventDisableTiming);

    cudaEventRecord(evFork, 0);
    cudaStreamWaitEvent(s2, evFork, 0);

    // ===== token branch (main stream) =====
    embed_leaky_k<<<BL, 192>>>(ids, emb, px);
    convpad_k<<<D3, 192>>>(W_t, pwt, D, D);
    projsplit_k<<<proj_grid, 256>>>(px, D, pwt, D, b_t, pqn, pkn, pvt, pcol, D);
    attln3_k<<<attln_grid, 256, ATTLN3_SMEM>>>(pkn, pqn, patt16, gam_t, bet_t);
    smattv_k<<<smattv_grid, 256, SMATTV_SMEM>>>(patt16, pvt, pout, pcol);
    probs_k<<<BL, 160>>>(pout, Wo_t, bo_t, pprobs);
    wfinal_k<<<Bsz, 512>>>(ids, pcol, pprobs, out, 1);

    // ===== hidden / word-vector branch (stream s2) =====
    convpad_k<<<D3, 128, 0, s2>>>(W_h, pwh, 300, KH);
    convpad_k<<<BL, 128, 0, s2>>>(wv, pwv, 300, KH);
    projsplit_k<<<proj_grid, 256, 0, s2>>>(pwv, KH, pwh, KH, b_h, pqn2, pkn2, pvt2, pcol2, KH);
    attln3_k<<<attln_grid, 256, ATTLN3_SMEM, s2>>>(pkn2, pqn2, patt16_2, gam_h, bet_h);
    smattv_k<<<smattv_grid, 256, SMATTV_SMEM, s2>>>(patt16_2, pvt2, pout2, pcol2);
    probs_k<<<BL, 160, 0, s2>>>(pout2, Wo_h, bo_h, pprobs2);

    // join: hidden-branch results folded into d_out on the main stream
    cudaEventRecord(evJoin, s2);
    cudaStreamWaitEvent(0, evJoin, 0);
    wfinal_k<<<Bsz, 512>>>(ids, pcol2, pprobs2, out, 0);
}